// round 8
// baseline (speedup 1.0000x reference)
#include <cuda_runtime.h>
#include <cstdint>
#include <math.h>

#define BB   8
#define TT   2048
#define DD   512
#define BT   (BB*TT)
#define DMID (3*DD)
#define DD2  (DD*DD)
#define WBIG (DD*DMID)
typedef long long ll;

// ---------------- scratch -------------------------------------------------------
__device__ __align__(16) float  g_S[(ll)BB*TT*TT];                  // fp32 scores
__device__ __align__(16) int8_t g_Sq1[(ll)BB*TT*TT], g_Sq2[(ll)BB*TT*TT];
__device__ __align__(16) float  g_Ss[BT];
__device__ __align__(16) float  g_WT[5*DD2 + 2*WBIG];               // transposed weights fp32
__device__ __align__(16) int8_t g_wq1[5*DD2 + 2*WBIG], g_wq2[5*DD2 + 2*WBIG];
__device__ __align__(16) float  g_ws[5*DD + DMID + DD];
__device__ __align__(16) int8_t g_e1q1[BT*DD], g_e1q2[BT*DD];
__device__ __align__(16) int8_t g_e2q1[BT*DD], g_e2q2[BT*DD];
__device__ __align__(16) int8_t g_e3q1[BT*DD], g_e3q2[BT*DD];
__device__ __align__(16) float  g_e1s[BT], g_e2s[BT], g_e3s[BT];
__device__ __align__(16) float  g_lof[BT*DD], g_rof[BT*DD], g_btf[BT*DD];
__device__ __align__(16) int8_t g_loq1[BT*DD], g_loq2[BT*DD];
__device__ __align__(16) int8_t g_roq1[BT*DD], g_roq2[BT*DD];
__device__ __align__(16) int8_t g_btq1[BT*DD], g_btq2[BT*DD];
__device__ __align__(16) float  g_los[BT], g_ros[BT], g_bts[BB*DD];
__device__ __align__(16) float  g_t1f[BT*DD], g_t2[BT*DD], g_ln1[BT*DD], g_ln2[BT*DD];
__device__ __align__(16) int8_t g_t1q1[BT*DD], g_t1q2[BT*DD];
__device__ __align__(16) float  g_t1s[BT];
__device__ __align__(16) int8_t g_l1q1[BT*DD], g_l1q2[BT*DD];
__device__ __align__(16) int8_t g_l2q1[BT*DD], g_l2q2[BT*DD];
__device__ __align__(16) float  g_l1s[BT], g_l2s[BT];
__device__ __align__(16) float  g_midf[BT*DMID];
__device__ __align__(16) int8_t g_mq1[BT*DMID], g_mq2[BT*DMID];
__device__ __align__(16) float  g_ms[BT];

// ---------------- helpers -------------------------------------------------------
__device__ __forceinline__ float gelu_f(float x) {
    return 0.5f * x * (1.0f + erff(x * 0.7071067811865476f));
}
__device__ __forceinline__ uint32_t smem_u32(const void* p) {
    uint32_t a;
    asm("{ .reg .u64 t; cvta.to.shared.u64 t, %1; cvt.u32.u64 %0, t; }" : "=r"(a) : "l"(p));
    return a;
}
__device__ __forceinline__ void cpa16(uint32_t dst, const void* src) {
    asm volatile("cp.async.cg.shared.global [%0], [%1], 16;" :: "r"(dst), "l"(src));
}
__device__ __forceinline__ void ldsm4(uint32_t* r, uint32_t a) {
    asm volatile("ldmatrix.sync.aligned.m8n8.x4.shared.b16 {%0,%1,%2,%3}, [%4];"
                 : "=r"(r[0]), "=r"(r[1]), "=r"(r[2]), "=r"(r[3]) : "r"(a));
}
__device__ __forceinline__ void mmai8(int* d, const uint32_t* a, const uint32_t* b) {
    asm volatile("mma.sync.aligned.m16n8k32.row.col.s32.s8.s8.s32 "
                 "{%0,%1,%2,%3}, {%4,%5,%6,%7}, {%8,%9}, {%0,%1,%2,%3};"
                 : "+r"(d[0]), "+r"(d[1]), "+r"(d[2]), "+r"(d[3])
                 : "r"(a[0]), "r"(a[1]), "r"(a[2]), "r"(a[3]), "r"(b[0]), "r"(b[1]));
}
// quantize one value pair given scale s (x ~= s*(q1 + q2/256))
__device__ __forceinline__ void quant1(float x, float inv, float s, int8_t& o1, int8_t& o2) {
    float q1f = rintf(x * inv);
    float r = x - q1f * s;
    float q2f = fminf(fmaxf(rintf(r * inv * 256.0f), -127.f), 127.f);
    o1 = (int8_t)(int)q1f;
    o2 = (int8_t)(int)q2f;
}

// stage: Aq1 10240 | Aq2 10240 | Bq1 10240 | Bq2 10240 = 40960
#define STG 40960u
#define SMEM_BYTES (3*40960)
#define NTHREADS 256

__device__ __forceinline__ void fill_stage(uint32_t sb,
    const int8_t* A1, const int8_t* A2, const int8_t* B1, const int8_t* B2,
    ll m0, ll n0, int k0, int K, int tid)
{
    #pragma unroll
    for (int j = 0; j < 2; j++) {
        const int id = j*256 + tid;                 // 512 ids: 128 rows x 4 chunks
        const int row = id >> 2, ch = id & 3;
        const uint32_t so = (uint32_t)(row * 80 + ch * 16);
        const ll ao = (m0 + row) * (ll)K + k0 + ch * 16;
        cpa16(sb +          so, A1 + ao);
        cpa16(sb + 10240u + so, A2 + ao);
    }
    #pragma unroll
    for (int j = 0; j < 2; j++) {
        const int id = j*256 + tid;
        const int row = id >> 2, ch = id & 3;
        const uint32_t so = (uint32_t)(row * 80 + ch * 16);
        const ll bo = (n0 + row) * (ll)K + k0 + ch * 16;
        cpa16(sb + 20480u + so, B1 + bo);
        cpa16(sb + 30720u + so, B2 + bo);
    }
}

// ---------------- int8 two-level GEMM: C[128x128 tile] = A @ B^T ----------------
// 8 warps: 2(m) x 4(n), warp tile 64x32. C = sA_i*sB_j*(accH + accL/256), fp32 out.
// EPI: 0 none, 1 +bias, 2 gelu(+bias), 3 gelu(+bias)+res, 4 gelu(+bias)+transposed
template<int EPI>
__global__ void __launch_bounds__(NTHREADS, 1)
gemm_i8(const int8_t* __restrict__ Aq1, const int8_t* __restrict__ Aq2,
        const float* __restrict__ Asc,
        const int8_t* __restrict__ Bq1, const int8_t* __restrict__ Bq2,
        const float* __restrict__ Bsc,
        const float* __restrict__ bias, const float* __restrict__ res,
        float* __restrict__ Cf, int K, int N,
        ll sA, ll sAs, ll sB, ll sBs, ll sC)
{
    extern __shared__ char smc[];
    const uint32_t sbase = smem_u32(smc);
    const int tid = threadIdx.x, lane = tid & 31, wid = tid >> 5;
    const int warp_m = wid & 1, warp_n = wid >> 1;       // 2 x 4, warp tile 64x32
    const ll m0 = (ll)blockIdx.y * 128;
    const ll n0 = (ll)blockIdx.x * 128;
    const ll zb = blockIdx.z;

    const int8_t* A1 = Aq1 + zb * sA;  const int8_t* A2 = Aq2 + zb * sA;
    const int8_t* B1 = Bq1 + zb * sB;  const int8_t* B2 = Bq2 + zb * sB;
    const float*  As = Asc + zb * sAs; const float*  Bs = Bsc + zb * sBs;

    const int NC = K >> 6;
    fill_stage(sbase,       A1, A2, B1, B2, m0, n0,  0, K, tid);
    asm volatile("cp.async.commit_group;" ::: "memory");
    fill_stage(sbase + STG, A1, A2, B1, B2, m0, n0, 64, K, tid);
    asm volatile("cp.async.commit_group;" ::: "memory");

    int accH[4][4][4], accL[4][4][4];
    #pragma unroll
    for (int i = 0; i < 4; i++)
        #pragma unroll
        for (int j = 0; j < 4; j++)
            #pragma unroll
            for (int q = 0; q < 4; q++) { accH[i][j][q] = 0; accL[i][j][q] = 0; }

    const uint32_t a_off = (uint32_t)((warp_m*64 + (lane & 15)) * 80 + ((lane >> 4) << 4));
    const uint32_t b_off = 20480u
        + (uint32_t)((warp_n*32 + ((lane >> 4) << 3) + (lane & 7)) * 80
                     + (((lane >> 3) & 1) << 4));

    for (int c = 0; c < NC; c++) {
        asm volatile("cp.async.wait_group 1;" ::: "memory");
        __syncthreads();
        const uint32_t sb = sbase + (uint32_t)(c % 3) * STG;

        if (c + 2 < NC)
            fill_stage(sbase + (uint32_t)((c + 2) % 3) * STG,
                       A1, A2, B1, B2, m0, n0, (c + 2) * 64, K, tid);
        asm volatile("cp.async.commit_group;" ::: "memory");

        #pragma unroll
        for (int ks = 0; ks < 2; ks++) {
            const uint32_t ab = sb + a_off + (uint32_t)(ks*32);
            const uint32_t bb = sb + b_off + (uint32_t)(ks*32);
            uint32_t a1[4][4], a2[4][4], b1[2][4], b2[2][4];
            #pragma unroll
            for (int mt = 0; mt < 4; mt++) ldsm4(a1[mt], ab + mt*1280u);
            #pragma unroll
            for (int h = 0; h < 2; h++) ldsm4(b1[h], bb + h*1280u);
            // q1*p1 -> accH
            #pragma unroll
            for (int mt = 0; mt < 4; mt++)
                #pragma unroll
                for (int nt = 0; nt < 4; nt++)
                    mmai8(accH[mt][nt], a1[mt], &b1[nt >> 1][(nt & 1) * 2]);
            #pragma unroll
            for (int h = 0; h < 2; h++) ldsm4(b2[h], bb + h*1280u + 10240u);
            // q1*p2 -> accL
            #pragma unroll
            for (int mt = 0; mt < 4; mt++)
                #pragma unroll
                for (int nt = 0; nt < 4; nt++)
                    mmai8(accL[mt][nt], a1[mt], &b2[nt >> 1][(nt & 1) * 2]);
            #pragma unroll
            for (int mt = 0; mt < 4; mt++) ldsm4(a2[mt], ab + mt*1280u + 10240u);
            // q2*p1 -> accL
            #pragma unroll
            for (int mt = 0; mt < 4; mt++)
                #pragma unroll
                for (int nt = 0; nt < 4; nt++)
                    mmai8(accL[mt][nt], a2[mt], &b1[nt >> 1][(nt & 1) * 2]);
        }
    }

    // ---------------- epilogue ----------------------------------------------------
    const int r0 = lane >> 2, c0 = (lane & 3) * 2;
    float sa[4][2];
    #pragma unroll
    for (int mt = 0; mt < 4; mt++)
        #pragma unroll
        for (int hh = 0; hh < 2; hh++)
            sa[mt][hh] = As[m0 + warp_m*64 + mt*16 + r0 + hh*8];

    if (EPI != 4) {
        float* Cb = Cf + zb * sC;
        const float* Rb = res + zb * sC;
        #pragma unroll
        for (int nt = 0; nt < 4; nt++) {
            const int n = warp_n*32 + nt*8 + c0;
            const float sb0 = Bs[n0 + n], sb1 = Bs[n0 + n + 1];
            float2 bv = make_float2(0.f, 0.f);
            if (EPI >= 1) bv = *(const float2*)&bias[n0 + n];
            #pragma unroll
            for (int mt = 0; mt < 4; mt++)
                #pragma unroll
                for (int hh = 0; hh < 2; hh++) {
                    const int m = warp_m*64 + mt*16 + r0 + hh*8;
                    float v0 = sa[mt][hh] * sb0 *
                               ((float)accH[mt][nt][hh*2]   + (float)accL[mt][nt][hh*2]   * 0.00390625f);
                    float v1 = sa[mt][hh] * sb1 *
                               ((float)accH[mt][nt][hh*2+1] + (float)accL[mt][nt][hh*2+1] * 0.00390625f);
                    if (EPI >= 1) { v0 += bv.x; v1 += bv.y; }
                    if (EPI >= 2) { v0 = gelu_f(v0); v1 = gelu_f(v1); }
                    const ll idx = (m0 + m) * (ll)N + n0 + n;
                    if (EPI == 3) {
                        float2 rv = *(const float2*)&Rb[idx];
                        v0 += rv.x; v1 += rv.y;
                    }
                    *(float2*)&Cb[idx] = make_float2(v0, v1);
                }
        }
    } else {
        // gelu(+bias), then transposed store: bodyT[b][d][t] fp32
        __syncthreads();
        float* st = (float*)smc;                       // 128 x 128, stride 132
        #pragma unroll
        for (int nt = 0; nt < 4; nt++) {
            const int n = warp_n*32 + nt*8 + c0;
            const float sb0 = Bs[n0 + n], sb1 = Bs[n0 + n + 1];
            const float2 bv = *(const float2*)&bias[n0 + n];
            #pragma unroll
            for (int mt = 0; mt < 4; mt++)
                #pragma unroll
                for (int hh = 0; hh < 2; hh++) {
                    const int m = warp_m*64 + mt*16 + r0 + hh*8;
                    st[m*132 + n]     = gelu_f(sa[mt][hh]*sb0*
                        ((float)accH[mt][nt][hh*2]   + (float)accL[mt][nt][hh*2]  *0.00390625f) + bv.x);
                    st[m*132 + n + 1] = gelu_f(sa[mt][hh]*sb1*
                        ((float)accH[mt][nt][hh*2+1] + (float)accL[mt][nt][hh*2+1]*0.00390625f) + bv.y);
                }
        }
        __syncthreads();
        const int b  = (int)(m0 >> 11);
        const int t0 = (int)(m0 & 2047);
        for (int e = tid; e < 128 * 32; e += NTHREADS) {
            const int d = e >> 5, tq = (e & 31) * 4;
            float4 v = make_float4(st[(tq+0)*132 + d], st[(tq+1)*132 + d],
                                   st[(tq+2)*132 + d], st[(tq+3)*132 + d]);
            *(float4*)&Cf[((ll)b * DD + n0 + d) * TT + t0 + tq] = v;
        }
    }
}

// ---------------- transpose fp32 (dims multiple of 32) --------------------------
__global__ void __launch_bounds__(256)
transp(const float* __restrict__ src, float* __restrict__ dst, int R, int Cc)
{
    __shared__ float t[32][33];
    int x = blockIdx.x * 32 + threadIdx.x;
    int y = blockIdx.y * 32 + threadIdx.y;
    #pragma unroll
    for (int j = 0; j < 32; j += 8) t[threadIdx.y + j][threadIdx.x] = src[(ll)(y + j) * Cc + x];
    __syncthreads();
    x = blockIdx.y * 32 + threadIdx.x;
    y = blockIdx.x * 32 + threadIdx.y;
    #pragma unroll
    for (int j = 0; j < 32; j += 8) dst[(ll)(y + j) * R + x] = t[threadIdx.x][threadIdx.y + j];
}

// ---------------- rowquant: per-row two-level int8 quantization -----------------
__global__ void __launch_bounds__(256)
rowquant(const float* __restrict__ X, int8_t* __restrict__ q1, int8_t* __restrict__ q2,
         float* __restrict__ sc, int C)
{
    __shared__ float sh[8];
    const ll base = (ll)blockIdx.x * C;
    const int tid = threadIdx.x, lane = tid & 31, warp = tid >> 5;
    float mx = 0.0f;
    for (int i = tid; i < C; i += 256) mx = fmaxf(mx, fabsf(X[base + i]));
    #pragma unroll
    for (int o = 16; o > 0; o >>= 1) mx = fmaxf(mx, __shfl_xor_sync(0xffffffffu, mx, o));
    if (lane == 0) sh[warp] = mx;
    __syncthreads();
    if (tid == 0) {
        float m2 = sh[0];
        for (int w = 1; w < 8; w++) m2 = fmaxf(m2, sh[w]);
        sh[0] = fmaxf(m2, 1e-30f);
    }
    __syncthreads();
    const float s = sh[0] * (1.0f / 127.0f);
    const float inv = 1.0f / s;
    for (int i = tid; i < C; i += 256) {
        int8_t o1, o2;
        quant1(X[base + i], inv, s, o1, o2);
        q1[base + i] = o1;
        q2[base + i] = o2;
    }
    if (tid == 0) sc[blockIdx.x] = s;
}

// ---------------- softmax rows of 2048 (fp32 in) -> int8 two-level out -----------
__global__ void __launch_bounds__(256)
softmaxq(const float* __restrict__ S, int8_t* __restrict__ q1, int8_t* __restrict__ q2,
         float* __restrict__ sc)
{
    __shared__ float sh[8];
    const ll base = (ll)blockIdx.x * TT;
    const int tid = threadIdx.x, lane = tid & 31, warp = tid >> 5;
    float x[8];
    {
        float4 x0 = *(const float4*)(S + base + tid * 8);
        float4 x1 = *(const float4*)(S + base + tid * 8 + 4);
        x[0]=x0.x; x[1]=x0.y; x[2]=x0.z; x[3]=x0.w;
        x[4]=x1.x; x[5]=x1.y; x[6]=x1.z; x[7]=x1.w;
    }
    float m = x[0];
    #pragma unroll
    for (int i = 1; i < 8; i++) m = fmaxf(m, x[i]);
    #pragma unroll
    for (int o = 16; o > 0; o >>= 1) m = fmaxf(m, __shfl_xor_sync(0xffffffffu, m, o));
    if (lane == 0) sh[warp] = m;
    __syncthreads();
    if (tid == 0) { float mm = sh[0]; for (int w = 1; w < 8; w++) mm = fmaxf(mm, sh[w]); sh[0] = mm; }
    __syncthreads();
    const float rmax = sh[0];
    __syncthreads();
    float e[8], ssum = 0.0f;
    #pragma unroll
    for (int i = 0; i < 8; i++) { e[i] = __expf(x[i] - rmax); ssum += e[i]; }
    #pragma unroll
    for (int o = 16; o > 0; o >>= 1) ssum += __shfl_xor_sync(0xffffffffu, ssum, o);
    if (lane == 0) sh[warp] = ssum;
    __syncthreads();
    if (tid == 0) { float t = 0; for (int w = 0; w < 8; w++) t += sh[w]; sh[0] = t; }
    __syncthreads();
    const float invs = 1.0f / sh[0];
    const float s = invs * (1.0f / 127.0f);         // max prob = invs
    const float inv = 1.0f / s;
    int8_t o1[8], o2[8];
    #pragma unroll
    for (int i = 0; i < 8; i++) quant1(e[i] * invs, inv, s, o1[i], o2[i]);
    *(uint2*)&q1[base + tid*8] = *(const uint2*)o1;
    *(uint2*)&q2[base + tid*8] = *(const uint2*)o2;
    if (tid == 0) sc[blockIdx.x] = s;
}

// ---------------- layernorm rows of 512 -> fp32 + int8 two-level ----------------
__global__ void __launch_bounds__(128)
lnq(const float* __restrict__ X, float* __restrict__ Y,
    int8_t* __restrict__ q1, int8_t* __restrict__ q2, float* __restrict__ sc,
    const float* __restrict__ g, const float* __restrict__ b)
{
    __shared__ float shs[4], shq[4];
    const ll base = (ll)blockIdx.x * DD;
    const int tid = threadIdx.x, lane = tid & 31, warp = tid >> 5;
    float4 v = *(const float4*)(X + base + tid * 4);
    float s = v.x + v.y + v.z + v.w;
    float q = v.x*v.x + v.y*v.y + v.z*v.z + v.w*v.w;
    #pragma unroll
    for (int o = 16; o > 0; o >>= 1) {
        s += __shfl_xor_sync(0xffffffffu, s, o);
        q += __shfl_xor_sync(0xffffffffu, q, o);
    }
    if (lane == 0) { shs[warp] = s; shq[warp] = q; }
    __syncthreads();
    if (tid == 0) { shs[0] = shs[0]+shs[1]+shs[2]+shs[3]; shq[0] = shq[0]+shq[1]+shq[2]+shq[3]; }
    __syncthreads();
    const float mu  = shs[0] * (1.0f / DD);
    const float var = shq[0] * (1.0f / DD) - mu * mu;
    const float r = rsqrtf(var + 1e-5f);
    float4 gg = *(const float4*)(g + tid * 4);
    float4 bb = *(const float4*)(b + tid * 4);
    float4 o;
    o.x = (v.x - mu) * r * gg.x + bb.x;
    o.y = (v.y - mu) * r * gg.y + bb.y;
    o.z = (v.z - mu) * r * gg.z + bb.z;
    o.w = (v.w - mu) * r * gg.w + bb.w;
    *(float4*)(Y + base + tid * 4) = o;
    // row max of |o|
    float mx = fmaxf(fmaxf(fabsf(o.x), fabsf(o.y)), fmaxf(fabsf(o.z), fabsf(o.w)));
    #pragma unroll
    for (int of = 16; of > 0; of >>= 1) mx = fmaxf(mx, __shfl_xor_sync(0xffffffffu, mx, of));
    __syncthreads();
    if (lane == 0) shs[warp] = mx;
    __syncthreads();
    if (tid == 0) shs[0] = fmaxf(fmaxf(fmaxf(shs[0], shs[1]), fmaxf(shs[2], shs[3])), 1e-30f);
    __syncthreads();
    const float sq = shs[0] * (1.0f / 127.0f);
    const float inv = 1.0f / sq;
    int8_t a1[4], a2[4];
    quant1(o.x, inv, sq, a1[0], a2[0]);
    quant1(o.y, inv, sq, a1[1], a2[1]);
    quant1(o.z, inv, sq, a1[2], a2[2]);
    quant1(o.w, inv, sq, a1[3], a2[3]);
    *(uint32_t*)&q1[base + tid*4] = *(const uint32_t*)a1;
    *(uint32_t*)&q2[base + tid*4] = *(const uint32_t*)a2;
    if (tid == 0) sc[blockIdx.x] = sq;
}

// ---------------- launch ----------------------------------------------------------
extern "C" void kernel_launch(void* const* d_in, const int* in_sizes, int n_in,
                              void* d_out, int out_size)
{
    const float* left  = (const float*)d_in[0];
    const float* right = (const float*)d_in[1];
    const float* body  = (const float*)d_in[2];
    const float* Wl = (const float*)d_in[3];  const float* bl = (const float*)d_in[4];
    const float* Wr = (const float*)d_in[5];  const float* br = (const float*)d_in[6];
    const float* Wb = (const float*)d_in[7];  const float* bbv = (const float*)d_in[8];
    const float* Wo = (const float*)d_in[9];  const float* bo = (const float*)d_in[10];
    const float* ln_g = (const float*)d_in[11]; const float* ln_b = (const float*)d_in[12];
    const float* W1 = (const float*)d_in[13]; const float* b1 = (const float*)d_in[14];
    const float* lg2 = (const float*)d_in[15]; const float* lb2 = (const float*)d_in[16];
    const float* W2 = (const float*)d_in[17]; const float* b2 = (const float*)d_in[18];
    const float* W3 = (const float*)d_in[19]; const float* b3 = (const float*)d_in[20];
    float* out = (float*)d_out;

    float *S, *Ss, *WT, *ws, *e1s, *e2s, *e3s, *lof, *rof, *btf, *los, *ros, *bts;
    float *t1f, *t1s, *t2, *ln1, *ln2, *l1s, *l2s, *midf, *ms;
    int8_t *Sq1, *Sq2, *wq1, *wq2, *e1q1, *e1q2, *e2q1, *e2q2, *e3q1, *e3q2;
    int8_t *loq1, *loq2, *roq1, *roq2, *btq1, *btq2, *t1q1, *t1q2;
    int8_t *l1q1, *l1q2, *l2q1, *l2q2, *mq1, *mq2;
    cudaGetSymbolAddress((void**)&S,    g_S);
    cudaGetSymbolAddress((void**)&Sq1,  g_Sq1);  cudaGetSymbolAddress((void**)&Sq2, g_Sq2);
    cudaGetSymbolAddress((void**)&Ss,   g_Ss);
    cudaGetSymbolAddress((void**)&WT,   g_WT);
    cudaGetSymbolAddress((void**)&wq1,  g_wq1);  cudaGetSymbolAddress((void**)&wq2, g_wq2);
    cudaGetSymbolAddress((void**)&ws,   g_ws);
    cudaGetSymbolAddress((void**)&e1q1, g_e1q1); cudaGetSymbolAddress((void**)&e1q2, g_e1q2);
    cudaGetSymbolAddress((void**)&e2q1, g_e2q1); cudaGetSymbolAddress((void**)&e2q2, g_e2q2);
    cudaGetSymbolAddress((void**)&e3q1, g_e3q1); cudaGetSymbolAddress((void**)&e3q2, g_e3q2);
    cudaGetSymbolAddress((void**)&e1s,  g_e1s);  cudaGetSymbolAddress((void**)&e2s, g_e2s);
    cudaGetSymbolAddress((void**)&e3s,  g_e3s);
    cudaGetSymbolAddress((void**)&lof,  g_lof);  cudaGetSymbolAddress((void**)&rof, g_rof);
    cudaGetSymbolAddress((void**)&btf,  g_btf);
    cudaGetSymbolAddress((void**)&loq1, g_loq1); cudaGetSymbolAddress((void**)&loq2, g_loq2);
    cudaGetSymbolAddress((void**)&roq1, g_roq1); cudaGetSymbolAddress((void**)&roq2, g_roq2);
    cudaGetSymbolAddress((void**)&btq1, g_btq1); cudaGetSymbolAddress((void**)&btq2, g_btq2);
    cudaGetSymbolAddress((void**)&los,  g_los);  cudaGetSymbolAddress((void**)&ros, g_ros);
    cudaGetSymbolAddress((void**)&bts,  g_bts);
    cudaGetSymbolAddress((void**)&t1f,  g_t1f);  cudaGetSymbolAddress((void**)&t1s, g_t1s);
    cudaGetSymbolAddress((void**)&t1q1, g_t1q1); cudaGetSymbolAddress((void**)&t1q2, g_t1q2);
    cudaGetSymbolAddress((void**)&t2,   g_t2);
    cudaGetSymbolAddress((void**)&ln1,  g_ln1);  cudaGetSymbolAddress((void**)&ln2, g_ln2);
    cudaGetSymbolAddress((void**)&l1q1, g_l1q1); cudaGetSymbolAddress((void**)&l1q2, g_l1q2);
    cudaGetSymbolAddress((void**)&l2q1, g_l2q1); cudaGetSymbolAddress((void**)&l2q2, g_l2q2);
    cudaGetSymbolAddress((void**)&l1s,  g_l1s);  cudaGetSymbolAddress((void**)&l2s, g_l2s);
    cudaGetSymbolAddress((void**)&midf, g_midf); cudaGetSymbolAddress((void**)&ms,  g_ms);
    cudaGetSymbolAddress((void**)&mq1,  g_mq1);  cudaGetSymbolAddress((void**)&mq2, g_mq2);

    cudaFuncSetAttribute(gemm_i8<0>, cudaFuncAttributeMaxDynamicSharedMemorySize, SMEM_BYTES);
    cudaFuncSetAttribute(gemm_i8<1>, cudaFuncAttributeMaxDynamicSharedMemorySize, SMEM_BYTES);
    cudaFuncSetAttribute(gemm_i8<2>, cudaFuncAttributeMaxDynamicSharedMemorySize, SMEM_BYTES);
    cudaFuncSetAttribute(gemm_i8<3>, cudaFuncAttributeMaxDynamicSharedMemorySize, SMEM_BYTES);
    cudaFuncSetAttribute(gemm_i8<4>, cudaFuncAttributeMaxDynamicSharedMemorySize, SMEM_BYTES);

    // weight offsets (elements) and scale offsets (rows)
    const ll oWl = 0, oWr = DD2, oWb = 2*DD2, oWo = 3*DD2, oW1 = 4*DD2;
    const ll oW2 = 5*DD2, oW3 = 5*(ll)DD2 + WBIG;
    const ll sWl = 0, sWr = DD, sWb = 2*DD, sWo = 3*DD, sW1 = 4*DD, sW2 = 5*DD, sW3 = 5*DD + DMID;

    const ll sTD = (ll)TT * DD;
    const ll sTT = (ll)TT * TT;
    dim3 tb(32, 8);

    // 1) weight transpose (fp32) + quantize rows
    transp<<<dim3(16,16), tb>>>(Wl, WT + oWl, DD, DD);
    transp<<<dim3(16,16), tb>>>(Wr, WT + oWr, DD, DD);
    transp<<<dim3(16,16), tb>>>(Wb, WT + oWb, DD, DD);
    transp<<<dim3(16,16), tb>>>(Wo, WT + oWo, DD, DD);
    transp<<<dim3(16,16), tb>>>(W1, WT + oW1, DD, DD);
    transp<<<dim3(48,16), tb>>>(W2, WT + oW2, DD, DMID);   // W2T: 1536 rows x 512
    transp<<<dim3(16,48), tb>>>(W3, WT + oW3, DMID, DD);   // W3T: 512 rows x 1536
    rowquant<<<DD,   256>>>(WT + oWl, wq1 + oWl, wq2 + oWl, ws + sWl, DD);
    rowquant<<<DD,   256>>>(WT + oWr, wq1 + oWr, wq2 + oWr, ws + sWr, DD);
    rowquant<<<DD,   256>>>(WT + oWb, wq1 + oWb, wq2 + oWb, ws + sWb, DD);
    rowquant<<<DD,   256>>>(WT + oWo, wq1 + oWo, wq2 + oWo, ws + sWo, DD);
    rowquant<<<DD,   256>>>(WT + oW1, wq1 + oW1, wq2 + oW1, ws + sW1, DD);
    rowquant<<<DMID, 256>>>(WT + oW2, wq1 + oW2, wq2 + oW2, ws + sW2, DD);
    rowquant<<<DD,   256>>>(WT + oW3, wq1 + oW3, wq2 + oW3, ws + sW3, DMID);

    // 2) quantize embeddings (rows of 512)
    rowquant<<<BT, 256>>>(left,  e1q1, e1q2, e1s, DD);
    rowquant<<<BT, 256>>>(right, e2q1, e2q2, e2s, DD);
    rowquant<<<BT, 256>>>(body,  e3q1, e3q2, e3s, DD);

    // 3) projections (+GELU): lo, ro row-major fp32; body transposed fp32
    gemm_i8<2><<<dim3(4,128,1), NTHREADS, SMEM_BYTES>>>(e1q1, e1q2, e1s, wq1+oWl, wq2+oWl, ws+sWl,
        bl, nullptr, lof, DD, DD, 0,0,0,0,0);
    gemm_i8<2><<<dim3(4,128,1), NTHREADS, SMEM_BYTES>>>(e2q1, e2q2, e2s, wq1+oWr, wq2+oWr, ws+sWr,
        br, nullptr, rof, DD, DD, 0,0,0,0,0);
    gemm_i8<4><<<dim3(4,128,1), NTHREADS, SMEM_BYTES>>>(e3q1, e3q2, e3s, wq1+oWb, wq2+oWb, ws+sWb,
        bbv, nullptr, btf, DD, 0, 0,0,0,0,0);

    // 4) quantize lo, ro (rows 512), bodyT (4096 rows x 2048)
    rowquant<<<BT, 256>>>(lof, loq1, loq2, los, DD);
    rowquant<<<BT, 256>>>(rof, roq1, roq2, ros, DD);
    rowquant<<<BB*DD, 256>>>(btf, btq1, btq2, bts, TT);

    // 5) attention scores: S = ro @ lo^T (fp32), softmax+quant, fuse = P @ bodyT^T
    gemm_i8<0><<<dim3(16,16,BB), NTHREADS, SMEM_BYTES>>>(roq1, roq2, ros, loq1, loq2, los,
        nullptr, nullptr, S, DD, TT, sTD, TT, sTD, TT, sTT);
    softmaxq<<<BT, 256>>>(S, Sq1, Sq2, Ss);
    gemm_i8<0><<<dim3(4,16,BB), NTHREADS, SMEM_BYTES>>>(Sq1, Sq2, Ss, btq1, btq2, bts,
        nullptr, nullptr, t1f, TT, DD, sTT, TT, sTD, DD, sTD);

    // 6) output projection + LN
    rowquant<<<BT, 256>>>(t1f, t1q1, t1q2, t1s, DD);
    gemm_i8<1><<<dim3(4,128,1), NTHREADS, SMEM_BYTES>>>(t1q1, t1q2, t1s, wq1+oWo, wq2+oWo, ws+sWo,
        bo, nullptr, t2, DD, DD, 0,0,0,0,0);
    lnq<<<BT, 128>>>(t2, ln1, l1q1, l1q2, l1s, ln_g, ln_b);

    // 7) inverted residual
    gemm_i8<3><<<dim3(4,128,1), NTHREADS, SMEM_BYTES>>>(l1q1, l1q2, l1s, wq1+oW1, wq2+oW1, ws+sW1,
        b1, ln1, t2, DD, DD, 0,0,0,0,0);
    lnq<<<BT, 128>>>(t2, ln2, l2q1, l2q2, l2s, lg2, lb2);
    gemm_i8<2><<<dim3(12,128,1), NTHREADS, SMEM_BYTES>>>(l2q1, l2q2, l2s, wq1+oW2, wq2+oW2, ws+sW2,
        b2, nullptr, midf, DD, DMID, 0,0,0,0,0);
    rowquant<<<BT, 256>>>(midf, mq1, mq2, ms, DMID);
    gemm_i8<1><<<dim3(4,128,1), NTHREADS, SMEM_BYTES>>>(mq1, mq2, ms, wq1+oW3, wq2+oW3, ws+sW3,
        b3, nullptr, out, DMID, DD, 0,0,0,0,0);
}

// round 9
// speedup vs baseline: 2.3108x; 2.3108x over previous
#include <cuda_runtime.h>
#include <cuda_fp16.h>
#include <cstdint>
#include <math.h>

#define BB   8
#define TT   2048
#define DD   512
#define BT   (BB*TT)
#define DMID (3*DD)
typedef long long ll;

// ---------------- scratch -------------------------------------------------------
__device__ __align__(16) __half g_Sh[(ll)BB*TT*TT];
__device__ __align__(16) __half g_Sl[(ll)BB*TT*TT];
__device__ __align__(16) __half g_e1h[BT*DD], g_e1l[BT*DD];
__device__ __align__(16) __half g_e2h[BT*DD], g_e2l[BT*DD];
__device__ __align__(16) __half g_e3h[BT*DD], g_e3l[BT*DD];
__device__ __align__(16) __half g_loh[BT*DD], g_lol[BT*DD];
__device__ __align__(16) __half g_roh[BT*DD], g_rol[BT*DD];
__device__ __align__(16) __half g_bth[BT*DD], g_btl[BT*DD];
__device__ __align__(16) __half g_t1h[BT*DD], g_t1l[BT*DD];
__device__ __align__(16) float  g_t2 [BT*DD];
__device__ __align__(16) float  g_ln1[BT*DD];
__device__ __align__(16) __half g_l1h[BT*DD], g_l1l[BT*DD];
__device__ __align__(16) __half g_l2h[BT*DD], g_l2l[BT*DD];
__device__ __align__(16) __half g_mh[BT*DMID], g_ml[BT*DMID];
__device__ __align__(16) __half g_WlTh[DD*DD],  g_WlTl[DD*DD];
__device__ __align__(16) __half g_WrTh[DD*DD],  g_WrTl[DD*DD];
__device__ __align__(16) __half g_WbTh[DD*DD],  g_WbTl[DD*DD];
__device__ __align__(16) __half g_WoTh[DD*DD],  g_WoTl[DD*DD];
__device__ __align__(16) __half g_W1Th[DD*DD],  g_W1Tl[DD*DD];
__device__ __align__(16) __half g_W2Th[DMID*DD],g_W2Tl[DMID*DD];
__device__ __align__(16) __half g_W3Th[DD*DMID],g_W3Tl[DD*DMID];

// ---------------- helpers -------------------------------------------------------
__device__ __forceinline__ float gelu_f(float x) {
    return 0.5f * x * (1.0f + erff(x * 0.7071067811865476f));
}
__device__ __forceinline__ uint32_t smem_u32(const void* p) {
    uint32_t a;
    asm("{ .reg .u64 t; cvta.to.shared.u64 t, %1; cvt.u32.u64 %0, t; }" : "=r"(a) : "l"(p));
    return a;
}
__device__ __forceinline__ void cpa16(uint32_t dst, const void* src) {
    asm volatile("cp.async.cg.shared.global [%0], [%1], 16;" :: "r"(dst), "l"(src));
}
__device__ __forceinline__ void ldsm4(uint32_t* r, uint32_t a) {
    asm volatile("ldmatrix.sync.aligned.m8n8.x4.shared.b16 {%0,%1,%2,%3}, [%4];"
                 : "=r"(r[0]), "=r"(r[1]), "=r"(r[2]), "=r"(r[3]) : "r"(a));
}
// fp16 in, fp32 acc (dominant term)
__device__ __forceinline__ void mmaf(float* d, const uint32_t* a, const uint32_t* b) {
    asm volatile("mma.sync.aligned.m16n8k16.row.col.f32.f16.f16.f32 "
                 "{%0,%1,%2,%3}, {%4,%5,%6,%7}, {%8,%9}, {%0,%1,%2,%3};"
                 : "+f"(d[0]), "+f"(d[1]), "+f"(d[2]), "+f"(d[3])
                 : "r"(a[0]), "r"(a[1]), "r"(a[2]), "r"(a[3]), "r"(b[0]), "r"(b[1]));
}
// fp16 in, fp16 acc (cross terms)
__device__ __forceinline__ void mmah(uint32_t* d, const uint32_t* a, const uint32_t* b) {
    asm volatile("mma.sync.aligned.m16n8k16.row.col.f16.f16.f16.f16 "
                 "{%0,%1}, {%2,%3,%4,%5}, {%6,%7}, {%0,%1};"
                 : "+r"(d[0]), "+r"(d[1])
                 : "r"(a[0]), "r"(a[1]), "r"(a[2]), "r"(a[3]), "r"(b[0]), "r"(b[1]));
}
__device__ __forceinline__ void split2(float v0, float v1, __half2& h, __half2& l) {
    h = __floats2half2_rn(v0, v1);
    float2 f = __half22float2(h);
    l = __floats2half2_rn(v0 - f.x, v1 - f.y);
}

// stage: Ah 10240 | Al 10240 | Bh 10240 | Bl 10240 = 40960  (rows of 32 f16, 80B stride)
#define STG 40960u
#define SMEM_BYTES (3*40960)
#define NTHREADS 256

__device__ __forceinline__ void fill_stage(uint32_t sb,
    const __half* A1, const __half* A2, const __half* B1, const __half* B2,
    ll m0, ll n0, int k0, int K, int tid)
{
    #pragma unroll
    for (int j = 0; j < 2; j++) {
        const int id = j*256 + tid;              // 512 ids: 128 rows x 4 chunks of 8 f16
        const int row = id >> 2, ch = id & 3;
        const uint32_t so = (uint32_t)(row * 80 + ch * 16);
        const ll ao = (m0 + row) * (ll)K + k0 + ch * 8;
        cpa16(sb +          so, A1 + ao);
        cpa16(sb + 10240u + so, A2 + ao);
    }
    #pragma unroll
    for (int j = 0; j < 2; j++) {
        const int id = j*256 + tid;
        const int row = id >> 2, ch = id & 3;
        const uint32_t so = (uint32_t)(row * 80 + ch * 16);
        const ll bo = (n0 + row) * (ll)K + k0 + ch * 8;
        cpa16(sb + 20480u + so, B1 + bo);
        cpa16(sb + 30720u + so, B2 + bo);
    }
}

// ---------------- GEMM: C tile 128x128 = A @ B^T, split-fp16 K-major ------------
// 8 warps: 2(m) x 4(n), warp tile 64x32. C = [Ah*Bh]_f32acc + [Al*Bh + Ah*Bl]_f16acc
// EPI: 0 none, 1 +bias, 2 gelu(+bias), 3 gelu(+bias)+res, 4 gelu(+bias)+transposed
// OUT: 0 fp32 C, 1 split-fp16 (Ch, Cl)
template<int EPI, int OUT>
__global__ void __launch_bounds__(NTHREADS, 1)
gemm_mma(const __half* __restrict__ Ahp, const __half* __restrict__ Alp,
         const __half* __restrict__ Bhp, const __half* __restrict__ Blp,
         const float* __restrict__ bias, const float* __restrict__ res,
         float* __restrict__ Cf, __half* __restrict__ Ch, __half* __restrict__ Cl,
         int K, int N, ll sA, ll sB, ll sC)
{
    extern __shared__ char smc[];
    const uint32_t sbase = smem_u32(smc);
    const int tid = threadIdx.x, lane = tid & 31, wid = tid >> 5;
    const int warp_m = wid & 1, warp_n = wid >> 1;     // 2 x 4, warp tile 64x32
    const ll m0 = (ll)blockIdx.y * 128;
    const ll n0 = (ll)blockIdx.x * 128;
    const ll zb = blockIdx.z;

    const __half* A1 = Ahp + zb * sA;  const __half* A2 = Alp + zb * sA;
    const __half* B1 = Bhp + zb * sB;  const __half* B2 = Blp + zb * sB;

    const int NC = K >> 5;
    fill_stage(sbase,       A1, A2, B1, B2, m0, n0,  0, K, tid);
    asm volatile("cp.async.commit_group;" ::: "memory");
    fill_stage(sbase + STG, A1, A2, B1, B2, m0, n0, 32, K, tid);
    asm volatile("cp.async.commit_group;" ::: "memory");

    float    accF[4][4][4];
    uint32_t accH[4][4][2];
    const __half2 hz = __floats2half2_rn(0.f, 0.f);
    #pragma unroll
    for (int i = 0; i < 4; i++)
        #pragma unroll
        for (int j = 0; j < 4; j++) {
            #pragma unroll
            for (int q = 0; q < 4; q++) accF[i][j][q] = 0.0f;
            accH[i][j][0] = *(const uint32_t*)&hz;
            accH[i][j][1] = *(const uint32_t*)&hz;
        }

    const uint32_t a_off = (uint32_t)((warp_m*64 + (lane & 15)) * 80 + ((lane >> 4) << 4));
    const uint32_t b_off = 20480u
        + (uint32_t)((warp_n*32 + ((lane >> 4) << 3) + (lane & 7)) * 80
                     + (((lane >> 3) & 1) << 4));

    for (int c = 0; c < NC; c++) {
        asm volatile("cp.async.wait_group 1;" ::: "memory");
        __syncthreads();
        const uint32_t sb = sbase + (uint32_t)(c % 3) * STG;

        if (c + 2 < NC)
            fill_stage(sbase + (uint32_t)((c + 2) % 3) * STG,
                       A1, A2, B1, B2, m0, n0, (c + 2) * 32, K, tid);
        asm volatile("cp.async.commit_group;" ::: "memory");

        #pragma unroll
        for (int ks = 0; ks < 2; ks++) {
            const uint32_t ab = sb + a_off + (uint32_t)(ks*32);
            const uint32_t bb = sb + b_off + (uint32_t)(ks*32);
            uint32_t a1[4][4], a2[4][4], bq[2][4];
            #pragma unroll
            for (int mt = 0; mt < 4; mt++) {
                ldsm4(a1[mt], ab + mt*1280u);
                ldsm4(a2[mt], ab + mt*1280u + 10240u);
            }
            #pragma unroll
            for (int h = 0; h < 2; h++) ldsm4(bq[h], bb + h*1280u);      // B hi
            // Ah*Bh -> f32 acc
            #pragma unroll
            for (int mt = 0; mt < 4; mt++)
                #pragma unroll
                for (int nt = 0; nt < 4; nt++)
                    mmaf(accF[mt][nt], a1[mt], &bq[nt >> 1][(nt & 1) * 2]);
            // Al*Bh -> f16 acc
            #pragma unroll
            for (int mt = 0; mt < 4; mt++)
                #pragma unroll
                for (int nt = 0; nt < 4; nt++)
                    mmah(accH[mt][nt], a2[mt], &bq[nt >> 1][(nt & 1) * 2]);
            // B lo over B hi
            #pragma unroll
            for (int h = 0; h < 2; h++) ldsm4(bq[h], bb + h*1280u + 10240u);
            // Ah*Bl -> f16 acc
            #pragma unroll
            for (int mt = 0; mt < 4; mt++)
                #pragma unroll
                for (int nt = 0; nt < 4; nt++)
                    mmah(accH[mt][nt], a1[mt], &bq[nt >> 1][(nt & 1) * 2]);
        }
    }

    // ---------------- epilogue ----------------------------------------------------
    const int r0 = lane >> 2, c0 = (lane & 3) * 2;
    if (EPI != 4) {
        float*  Cbf = Cf + zb * sC;
        __half* Cbh = Ch + zb * sC;
        __half* Cbl = Cl + zb * sC;
        const float* Rb = res + zb * sC;
        #pragma unroll
        for (int mt = 0; mt < 4; mt++)
            #pragma unroll
            for (int nt = 0; nt < 4; nt++) {
                const int n = warp_n*32 + nt*8 + c0;
                float2 bv = make_float2(0.f, 0.f);
                if (EPI >= 1) bv = *(const float2*)&bias[n0 + n];
                #pragma unroll
                for (int hh = 0; hh < 2; hh++) {
                    const int m = warp_m*64 + mt*16 + r0 + hh*8;
                    float2 lo2 = __half22float2(*(const __half2*)&accH[mt][nt][hh]);
                    float v0 = accF[mt][nt][hh*2]   + lo2.x;
                    float v1 = accF[mt][nt][hh*2+1] + lo2.y;
                    if (EPI >= 1) { v0 += bv.x; v1 += bv.y; }
                    if (EPI >= 2) { v0 = gelu_f(v0); v1 = gelu_f(v1); }
                    const ll idx = (m0 + m) * (ll)N + n0 + n;
                    if (EPI == 3) {
                        float2 rv = *(const float2*)&Rb[idx];
                        v0 += rv.x; v1 += rv.y;
                    }
                    if (OUT == 0) {
                        *(float2*)&Cbf[idx] = make_float2(v0, v1);
                    } else {
                        __half2 h, l; split2(v0, v1, h, l);
                        *(__half2*)&Cbh[idx] = h;
                        *(__half2*)&Cbl[idx] = l;
                    }
                }
            }
    } else {
        // gelu(+bias), then transposed split store: bodyT[b][d][t]
        __syncthreads();
        float* st = (float*)smc;                     // 128 x 128, stride 132
        #pragma unroll
        for (int mt = 0; mt < 4; mt++)
            #pragma unroll
            for (int nt = 0; nt < 4; nt++) {
                const int n = warp_n*32 + nt*8 + c0;
                const float2 bv = *(const float2*)&bias[n0 + n];
                #pragma unroll
                for (int hh = 0; hh < 2; hh++) {
                    const int m = warp_m*64 + mt*16 + r0 + hh*8;
                    float2 lo2 = __half22float2(*(const __half2*)&accH[mt][nt][hh]);
                    st[m*132 + n]     = gelu_f(accF[mt][nt][hh*2]   + lo2.x + bv.x);
                    st[m*132 + n + 1] = gelu_f(accF[mt][nt][hh*2+1] + lo2.y + bv.y);
                }
            }
        __syncthreads();
        const int b  = (int)(m0 >> 11);
        const int t0 = (int)(m0 & 2047);
        for (int e = tid; e < 128 * 64; e += NTHREADS) {
            const int n  = e >> 6;
            const int tp = (e & 63) * 2;
            const float v0 = st[tp*132 + n], v1 = st[(tp+1)*132 + n];
            __half2 h, l; split2(v0, v1, h, l);
            const ll idx = ((ll)b * DD + n0 + n) * TT + t0 + tp;
            *(__half2*)&Ch[idx] = h;
            *(__half2*)&Cl[idx] = l;
        }
    }
}

// ---------------- fp32 -> split fp16 ---------------------------------------------
__global__ void __launch_bounds__(256)
convsplit(const float* __restrict__ x, __half* __restrict__ xh,
          __half* __restrict__ xl, int n4)
{
    int i = blockIdx.x * 256 + threadIdx.x;
    if (i >= n4) return;
    float4 v = ((const float4*)x)[i];
    __half2 h0, l0, h1, l1;
    split2(v.x, v.y, h0, l0);
    split2(v.z, v.w, h1, l1);
    ((__half2*)xh)[i*2]   = h0;  ((__half2*)xh)[i*2+1] = h1;
    ((__half2*)xl)[i*2]   = l0;  ((__half2*)xl)[i*2+1] = l1;
}

// ---------------- fused weight prep ----------------------------------------------
__global__ void __launch_bounds__(256)
wprep(const float* __restrict__ s0, const float* __restrict__ s1,
      const float* __restrict__ s2, const float* __restrict__ s3,
      const float* __restrict__ s4, const float* __restrict__ s5,
      const float* __restrict__ s6)
{
    __shared__ float t[32][33];
    const int b = blockIdx.x;
    const float* src; __half *dh, *dl;
    int R, Cc, bx, by;
    if (b < 1280) {
        const int w = b >> 8, tt = b & 255;
        bx = tt & 15; by = tt >> 4; R = DD; Cc = DD;
        switch (w) {
            case 0:  src = s0; dh = g_WlTh; dl = g_WlTl; break;
            case 1:  src = s1; dh = g_WrTh; dl = g_WrTl; break;
            case 2:  src = s2; dh = g_WbTh; dl = g_WbTl; break;
            case 3:  src = s3; dh = g_WoTh; dl = g_WoTl; break;
            default: src = s4; dh = g_W1Th; dl = g_W1Tl; break;
        }
    } else if (b < 2048) {
        const int tt = b - 1280;
        bx = tt % 48; by = tt / 48; R = DD; Cc = DMID;
        src = s5; dh = g_W2Th; dl = g_W2Tl;
    } else {
        const int tt = b - 2048;
        bx = tt % 16; by = tt / 16; R = DMID; Cc = DD;
        src = s6; dh = g_W3Th; dl = g_W3Tl;
    }
    int x = bx * 32 + threadIdx.x;
    int y = by * 32 + threadIdx.y;
    #pragma unroll
    for (int j = 0; j < 32; j += 8) t[threadIdx.y + j][threadIdx.x] = src[(ll)(y + j) * Cc + x];
    __syncthreads();
    x = by * 32 + threadIdx.x;
    y = bx * 32 + threadIdx.y;
    #pragma unroll
    for (int j = 0; j < 32; j += 8) {
        float v = t[threadIdx.x][threadIdx.y + j];
        __half h = __float2half_rn(v);
        ll idx = (ll)(y + j) * R + x;
        dh[idx] = h;
        dl[idx] = __float2half_rn(v - __half2float(h));
    }
}

// ---------------- softmax rows of 2048, split-fp16 in/out ------------------------
__global__ void __launch_bounds__(256)
softmax2048s(__half* __restrict__ Sh, __half* __restrict__ Sl)
{
    __shared__ float sh[8];
    const ll base = (ll)blockIdx.x * TT;
    const int tid = threadIdx.x, lane = tid & 31, warp = tid >> 5;

    float x[8];
    {
        uint4 hv = *(const uint4*)(Sh + base + tid * 8);
        uint4 lv = *(const uint4*)(Sl + base + tid * 8);
        const uint32_t hr[4] = {hv.x, hv.y, hv.z, hv.w};
        const uint32_t lr[4] = {lv.x, lv.y, lv.z, lv.w};
        #pragma unroll
        for (int i = 0; i < 4; i++) {
            float2 h2 = __half22float2(*(const __half2*)&hr[i]);
            float2 l2 = __half22float2(*(const __half2*)&lr[i]);
            x[i*2]   = h2.x + l2.x;
            x[i*2+1] = h2.y + l2.y;
        }
    }
    float m = x[0];
    #pragma unroll
    for (int i = 1; i < 8; i++) m = fmaxf(m, x[i]);
    #pragma unroll
    for (int o = 16; o > 0; o >>= 1) m = fmaxf(m, __shfl_xor_sync(0xffffffffu, m, o));
    if (lane == 0) sh[warp] = m;
    __syncthreads();
    if (tid == 0) { float mm = sh[0]; for (int w = 1; w < 8; w++) mm = fmaxf(mm, sh[w]); sh[0] = mm; }
    __syncthreads();
    const float rmax = sh[0];
    __syncthreads();
    float e[8], s = 0.0f;
    #pragma unroll
    for (int i = 0; i < 8; i++) { e[i] = __expf(x[i] - rmax); s += e[i]; }
    #pragma unroll
    for (int o = 16; o > 0; o >>= 1) s += __shfl_xor_sync(0xffffffffu, s, o);
    if (lane == 0) sh[warp] = s;
    __syncthreads();
    if (tid == 0) { float ss = 0; for (int w = 0; w < 8; w++) ss += sh[w]; sh[0] = ss; }
    __syncthreads();
    const float inv = 1.0f / sh[0];
    #pragma unroll
    for (int i = 0; i < 4; i++) {
        __half2 h, l;
        split2(e[i*2] * inv, e[i*2+1] * inv, h, l);
        *(__half2*)&Sh[base + tid*8 + i*2] = h;
        *(__half2*)&Sl[base + tid*8 + i*2] = l;
    }
}

// ---------------- layernorm rows of 512 -> fp32 + fp16 split ---------------------
__global__ void __launch_bounds__(128)
layernorm512s(const float* __restrict__ X, float* __restrict__ Y,
              __half* __restrict__ Yh, __half* __restrict__ Yl,
              const float* __restrict__ g, const float* __restrict__ b)
{
    __shared__ float shs[4], shq[4];
    const ll base = (ll)blockIdx.x * DD;
    const float* x = X + base;
    const int tid = threadIdx.x, lane = tid & 31, warp = tid >> 5;
    float4 v = *(const float4*)(x + tid * 4);
    float s = v.x + v.y + v.z + v.w;
    float q = v.x*v.x + v.y*v.y + v.z*v.z + v.w*v.w;
    #pragma unroll
    for (int o = 16; o > 0; o >>= 1) {
        s += __shfl_xor_sync(0xffffffffu, s, o);
        q += __shfl_xor_sync(0xffffffffu, q, o);
    }
    if (lane == 0) { shs[warp] = s; shq[warp] = q; }
    __syncthreads();
    if (tid == 0) { shs[0] = shs[0]+shs[1]+shs[2]+shs[3]; shq[0] = shq[0]+shq[1]+shq[2]+shq[3]; }
    __syncthreads();
    const float mu  = shs[0] * (1.0f / DD);
    const float var = shq[0] * (1.0f / DD) - mu * mu;
    const float r = rsqrtf(var + 1e-5f);
    float4 gg = *(const float4*)(g + tid * 4);
    float4 bb = *(const float4*)(b + tid * 4);
    float4 o;
    o.x = (v.x - mu) * r * gg.x + bb.x;
    o.y = (v.y - mu) * r * gg.y + bb.y;
    o.z = (v.z - mu) * r * gg.z + bb.z;
    o.w = (v.w - mu) * r * gg.w + bb.w;
    *(float4*)(Y + base + tid * 4) = o;
    __half2 h0, l0, h1, l1;
    split2(o.x, o.y, h0, l0);
    split2(o.z, o.w, h1, l1);
    *(__half2*)&Yh[base + tid*4]     = h0;
    *(__half2*)&Yh[base + tid*4 + 2] = h1;
    *(__half2*)&Yl[base + tid*4]     = l0;
    *(__half2*)&Yl[base + tid*4 + 2] = l1;
}

// ---------------- launch ----------------------------------------------------------
extern "C" void kernel_launch(void* const* d_in, const int* in_sizes, int n_in,
                              void* d_out, int out_size)
{
    const float* left  = (const float*)d_in[0];
    const float* right = (const float*)d_in[1];
    const float* body  = (const float*)d_in[2];
    const float* Wl = (const float*)d_in[3];  const float* bl = (const float*)d_in[4];
    const float* Wr = (const float*)d_in[5];  const float* br = (const float*)d_in[6];
    const float* Wb = (const float*)d_in[7];  const float* bbv = (const float*)d_in[8];
    const float* Wo = (const float*)d_in[9];  const float* bo = (const float*)d_in[10];
    const float* ln_g = (const float*)d_in[11]; const float* ln_b = (const float*)d_in[12];
    const float* W1 = (const float*)d_in[13]; const float* b1 = (const float*)d_in[14];
    const float* lg2 = (const float*)d_in[15]; const float* lb2 = (const float*)d_in[16];
    const float* W2 = (const float*)d_in[17]; const float* b2 = (const float*)d_in[18];
    const float* W3 = (const float*)d_in[19]; const float* b3 = (const float*)d_in[20];
    float* out = (float*)d_out;

    float *t2, *ln1;
    __half *Sh, *Sl, *e1h, *e1l, *e2h, *e2l, *e3h, *e3l;
    __half *loh, *lol, *roh, *rol, *bth, *btl, *t1h, *t1l;
    __half *l1h, *l1l, *l2h, *l2l, *mh, *ml;
    __half *WlTh,*WlTl,*WrTh,*WrTl,*WbTh,*WbTl,*WoTh,*WoTl,*W1Th,*W1Tl,*W2Th,*W2Tl,*W3Th,*W3Tl;
    cudaGetSymbolAddress((void**)&Sh,  g_Sh);  cudaGetSymbolAddress((void**)&Sl,  g_Sl);
    cudaGetSymbolAddress((void**)&e1h, g_e1h); cudaGetSymbolAddress((void**)&e1l, g_e1l);
    cudaGetSymbolAddress((void**)&e2h, g_e2h); cudaGetSymbolAddress((void**)&e2l, g_e2l);
    cudaGetSymbolAddress((void**)&e3h, g_e3h); cudaGetSymbolAddress((void**)&e3l, g_e3l);
    cudaGetSymbolAddress((void**)&loh, g_loh); cudaGetSymbolAddress((void**)&lol, g_lol);
    cudaGetSymbolAddress((void**)&roh, g_roh); cudaGetSymbolAddress((void**)&rol, g_rol);
    cudaGetSymbolAddress((void**)&bth, g_bth); cudaGetSymbolAddress((void**)&btl, g_btl);
    cudaGetSymbolAddress((void**)&t1h, g_t1h); cudaGetSymbolAddress((void**)&t1l, g_t1l);
    cudaGetSymbolAddress((void**)&t2,  g_t2);  cudaGetSymbolAddress((void**)&ln1, g_ln1);
    cudaGetSymbolAddress((void**)&l1h, g_l1h); cudaGetSymbolAddress((void**)&l1l, g_l1l);
    cudaGetSymbolAddress((void**)&l2h, g_l2h); cudaGetSymbolAddress((void**)&l2l, g_l2l);
    cudaGetSymbolAddress((void**)&mh,  g_mh);  cudaGetSymbolAddress((void**)&ml,  g_ml);
    cudaGetSymbolAddress((void**)&WlTh,g_WlTh);cudaGetSymbolAddress((void**)&WlTl,g_WlTl);
    cudaGetSymbolAddress((void**)&WrTh,g_WrTh);cudaGetSymbolAddress((void**)&WrTl,g_WrTl);
    cudaGetSymbolAddress((void**)&WbTh,g_WbTh);cudaGetSymbolAddress((void**)&WbTl,g_WbTl);
    cudaGetSymbolAddress((void**)&WoTh,g_WoTh);cudaGetSymbolAddress((void**)&WoTl,g_WoTl);
    cudaGetSymbolAddress((void**)&W1Th,g_W1Th);cudaGetSymbolAddress((void**)&W1Tl,g_W1Tl);
    cudaGetSymbolAddress((void**)&W2Th,g_W2Th);cudaGetSymbolAddress((void**)&W2Tl,g_W2Tl);
    cudaGetSymbolAddress((void**)&W3Th,g_W3Th);cudaGetSymbolAddress((void**)&W3Tl,g_W3Tl);

    cudaFuncSetAttribute(gemm_mma<0,1>, cudaFuncAttributeMaxDynamicSharedMemorySize, SMEM_BYTES);
    cudaFuncSetAttribute(gemm_mma<1,0>, cudaFuncAttributeMaxDynamicSharedMemorySize, SMEM_BYTES);
    cudaFuncSetAttribute(gemm_mma<2,1>, cudaFuncAttributeMaxDynamicSharedMemorySize, SMEM_BYTES);
    cudaFuncSetAttribute(gemm_mma<3,0>, cudaFuncAttributeMaxDynamicSharedMemorySize, SMEM_BYTES);
    cudaFuncSetAttribute(gemm_mma<4,1>, cudaFuncAttributeMaxDynamicSharedMemorySize, SMEM_BYTES);

    const ll sTD = (ll)TT * DD;
    const ll sTT = (ll)TT * TT;
    const int n4 = BT * DD / 4;

    // launch 0: fused weight prep
    wprep<<<2816, dim3(32, 8)>>>(Wl, Wr, Wb, Wo, W1, W2, W3);

    // launches 1-3: input splits
    convsplit<<<n4/256, 256>>>(left,  e1h, e1l, n4);
    convsplit<<<n4/256, 256>>>(right, e2h, e2l, n4);
    convsplit<<<n4/256, 256>>>(body,  e3h, e3l, n4);

    // launches 4-6: projections (+GELU)
    gemm_mma<2,1><<<dim3(4,128,1), NTHREADS, SMEM_BYTES>>>(e1h, e1l, WlTh, WlTl, bl, nullptr,
        nullptr, loh, lol, DD, DD, 0, 0, 0);
    gemm_mma<2,1><<<dim3(4,128,1), NTHREADS, SMEM_BYTES>>>(e2h, e2l, WrTh, WrTl, br, nullptr,
        nullptr, roh, rol, DD, DD, 0, 0, 0);
    gemm_mma<4,1><<<dim3(4,128,1), NTHREADS, SMEM_BYTES>>>(e3h, e3l, WbTh, WbTl, bbv, nullptr,
        nullptr, bth, btl, DD, DD, 0, 0, 0);

    // attention: S = ro @ lo^T (split out) ; softmax in-place ; fuse = P @ bodyT^T
    gemm_mma<0,1><<<dim3(16,16,BB), NTHREADS, SMEM_BYTES>>>(roh, rol, loh, lol, nullptr, nullptr,
        nullptr, Sh, Sl, DD, TT, sTD, sTD, sTT);
    softmax2048s<<<BT, 256>>>(Sh, Sl);
    gemm_mma<0,1><<<dim3(4,16,BB), NTHREADS, SMEM_BYTES>>>(Sh, Sl, bth, btl, nullptr, nullptr,
        nullptr, t1h, t1l, TT, DD, sTT, sTD, sTD);

    // output projection + LN
    gemm_mma<1,0><<<dim3(4,128,1), NTHREADS, SMEM_BYTES>>>(t1h, t1l, WoTh, WoTl, bo, nullptr,
        t2, nullptr, nullptr, DD, DD, 0, 0, 0);
    layernorm512s<<<BT, 128>>>(t2, ln1, l1h, l1l, ln_g, ln_b);

    // inverted residual
    gemm_mma<3,0><<<dim3(4,128,1), NTHREADS, SMEM_BYTES>>>(l1h, l1l, W1Th, W1Tl, b1, ln1,
        t2, nullptr, nullptr, DD, DD, 0, 0, 0);
    layernorm512s<<<BT, 128>>>(t2, ln1, l2h, l2l, lg2, lb2);
    gemm_mma<2,1><<<dim3(12,128,1), NTHREADS, SMEM_BYTES>>>(l2h, l2l, W2Th, W2Tl, b2, nullptr,
        nullptr, mh, ml, DD, DMID, 0, 0, 0);
    gemm_mma<1,0><<<dim3(4,128,1), NTHREADS, SMEM_BYTES>>>(mh, ml, W3Th, W3Tl, b3, nullptr,
        out, nullptr, nullptr, DMID, DD, 0, 0, 0);
}

// round 10
// speedup vs baseline: 2.5418x; 1.1000x over previous
#include <cuda_runtime.h>
#include <cuda_bf16.h>
#include <cstdint>
#include <math.h>

#define BB   8
#define TT   2048
#define DD   512
#define BT   (BB*TT)
#define DMID (3*DD)
typedef long long ll;

// ---------------- scratch -------------------------------------------------------
__device__ __align__(16) __nv_bfloat16 g_Sh[(ll)BB*TT*TT];
__device__ __align__(16) __nv_bfloat16 g_Sl[(ll)BB*TT*TT];
__device__ __align__(16) __nv_bfloat16 g_loh[BT*DD], g_lol[BT*DD];
__device__ __align__(16) __nv_bfloat16 g_roh[BT*DD], g_rol[BT*DD];
__device__ __align__(16) __nv_bfloat16 g_bth[BT*DD], g_btl[BT*DD];
__device__ __align__(16) __nv_bfloat16 g_t1h[BT*DD], g_t1l[BT*DD];
__device__ __align__(16) float g_t2 [BT*DD];
__device__ __align__(16) float g_ln1[BT*DD];
__device__ __align__(16) __nv_bfloat16 g_l1h[BT*DD], g_l1l[BT*DD];
__device__ __align__(16) __nv_bfloat16 g_l2h[BT*DD], g_l2l[BT*DD];
__device__ __align__(16) __nv_bfloat16 g_mh[BT*DMID], g_ml[BT*DMID];
__device__ __align__(16) __nv_bfloat16 g_WlTh[DD*DD],  g_WlTl[DD*DD];
__device__ __align__(16) __nv_bfloat16 g_WrTh[DD*DD],  g_WrTl[DD*DD];
__device__ __align__(16) __nv_bfloat16 g_WbTh[DD*DD],  g_WbTl[DD*DD];
__device__ __align__(16) __nv_bfloat16 g_WoTh[DD*DD],  g_WoTl[DD*DD];
__device__ __align__(16) __nv_bfloat16 g_W1Th[DD*DD],  g_W1Tl[DD*DD];
__device__ __align__(16) __nv_bfloat16 g_W2Th[DMID*DD],g_W2Tl[DMID*DD];
__device__ __align__(16) __nv_bfloat16 g_W3Th[DD*DMID],g_W3Tl[DD*DMID];

// ---------------- helpers -------------------------------------------------------
__device__ __forceinline__ float gelu_f(float x) {
    return 0.5f * x * (1.0f + erff(x * 0.7071067811865476f));
}
__device__ __forceinline__ uint32_t smem_u32(const void* p) {
    uint32_t a;
    asm("{ .reg .u64 t; cvta.to.shared.u64 t, %1; cvt.u32.u64 %0, t; }" : "=r"(a) : "l"(p));
    return a;
}
__device__ __forceinline__ void cpa16(uint32_t dst, const void* src) {
    asm volatile("cp.async.cg.shared.global [%0], [%1], 16;" :: "r"(dst), "l"(src));
}
__device__ __forceinline__ void ldsm4(uint32_t* r, uint32_t a) {
    asm volatile("ldmatrix.sync.aligned.m8n8.x4.shared.b16 {%0,%1,%2,%3}, [%4];"
                 : "=r"(r[0]), "=r"(r[1]), "=r"(r[2]), "=r"(r[3]) : "r"(a));
}
__device__ __forceinline__ void mma16816(float* d, const uint32_t* a, const uint32_t* b) {
    asm volatile("mma.sync.aligned.m16n8k16.row.col.f32.bf16.bf16.f32 "
                 "{%0,%1,%2,%3}, {%4,%5,%6,%7}, {%8,%9}, {%0,%1,%2,%3};"
                 : "+f"(d[0]), "+f"(d[1]), "+f"(d[2]), "+f"(d[3])
                 : "r"(a[0]), "r"(a[1]), "r"(a[2]), "r"(a[3]), "r"(b[0]), "r"(b[1]));
}
__device__ __forceinline__ void split2(float v0, float v1, __nv_bfloat162& h, __nv_bfloat162& l) {
    h = __floats2bfloat162_rn(v0, v1);
    float2 f = __bfloat1622float2(h);
    l = __floats2bfloat162_rn(v0 - f.x, v1 - f.y);
}

// stage: Ah 10240 | Al 10240 | Bh 20480 | Bl 20480 = 61440
#define STG 61440u
#define SMEM_BYTES (3*61440)
#define NTHREADS 256

// --- B fill (always split bf16 via cp.async): 256 rows x 32 k, 80B row stride ----
__device__ __forceinline__ void fill_B(uint32_t sb,
    const __nv_bfloat16* B1, const __nv_bfloat16* B2, ll n0, int k0, int K, int tid)
{
    #pragma unroll
    for (int j = 0; j < 4; j++) {
        const int id = j*256 + tid;                  // 1024 ids: 256 rows x 4 chunks
        const int row = id >> 2, ch = id & 3;
        const uint32_t so = (uint32_t)(row * 80 + ch * 16);
        const ll bo = (n0 + row) * (ll)K + k0 + ch * 8;
        cpa16(sb + 20480u + so, B1 + bo);
        cpa16(sb + 40960u + so, B2 + bo);
    }
}
// --- A fill, pre-split bf16 source ------------------------------------------------
__device__ __forceinline__ void fill_A_bf(uint32_t sb,
    const __nv_bfloat16* A1, const __nv_bfloat16* A2, ll m0, int k0, int K, int tid)
{
    #pragma unroll
    for (int j = 0; j < 2; j++) {
        const int id = j*256 + tid;                  // 512 ids: 128 rows x 4 chunks
        const int row = id >> 2, ch = id & 3;
        const uint32_t so = (uint32_t)(row * 80 + ch * 16);
        const ll ao = (m0 + row) * (ll)K + k0 + ch * 8;
        cpa16(sb + so, A1 + ao);
        cpa16(sb + 10240u + so, A2 + ao);
    }
}
// --- A fill, fp32 source: LDG to regs, later split+STS ----------------------------
__device__ __forceinline__ void ldg_A_f32(float4* r, const float* Af,
                                          ll m0, int k0, int K, int tid)
{
    #pragma unroll
    for (int j = 0; j < 2; j++) {
        const int id = j*256 + tid;
        const int row = id >> 2, ch = id & 3;
        const float* s = Af + (m0 + row) * (ll)K + k0 + ch * 8;
        r[j*2]   = *(const float4*)s;
        r[j*2+1] = *(const float4*)(s + 4);
    }
}
__device__ __forceinline__ void sts_A_split(char* sp, const float4* r, int tid)
{
    #pragma unroll
    for (int j = 0; j < 2; j++) {
        const int id = j*256 + tid;
        const int row = id >> 2, ch = id & 3;
        const uint32_t so = (uint32_t)(row * 80 + ch * 16);
        __nv_bfloat162 h0,l0,h1,l1,h2,l2,h3,l3;
        split2(r[j*2].x,   r[j*2].y,   h0, l0);
        split2(r[j*2].z,   r[j*2].w,   h1, l1);
        split2(r[j*2+1].x, r[j*2+1].y, h2, l2);
        split2(r[j*2+1].z, r[j*2+1].w, h3, l3);
        *(uint4*)(sp + so) = make_uint4(*(uint32_t*)&h0, *(uint32_t*)&h1,
                                        *(uint32_t*)&h2, *(uint32_t*)&h3);
        *(uint4*)(sp + 10240 + so) = make_uint4(*(uint32_t*)&l0, *(uint32_t*)&l1,
                                                *(uint32_t*)&l2, *(uint32_t*)&l3);
    }
}

// ---------------- GEMM: C tile 128x256 = A @ B^T, split-bf16 3-term --------------
// 8 warps: 2(m) x 4(n), warp tile 64x64
// EPI: 0 none, 1 +bias, 2 gelu(+bias), 3 gelu(+bias)+res, 4 gelu(+bias)+transposed
// OUT: 0 fp32 C, 1 split-bf16 ; ASRC: 0 A pre-split bf16, 1 A fp32 (split in-kernel)
template<int EPI, int OUT, int ASRC>
__global__ void __launch_bounds__(NTHREADS, 1)
gemm_mma(const __nv_bfloat16* __restrict__ Ah, const __nv_bfloat16* __restrict__ Al,
         const float* __restrict__ Af,
         const __nv_bfloat16* __restrict__ Bh, const __nv_bfloat16* __restrict__ Bl,
         const float* __restrict__ bias, const float* __restrict__ res,
         float* __restrict__ Cf, __nv_bfloat16* __restrict__ Ch, __nv_bfloat16* __restrict__ Cl,
         int K, int N, ll sA, ll sB, ll sC)
{
    extern __shared__ char smc[];
    const uint32_t sbase = smem_u32(smc);
    const int tid = threadIdx.x, lane = tid & 31, wid = tid >> 5;
    const int warp_m = wid & 1, warp_n = wid >> 1;
    const ll m0 = (ll)blockIdx.y * 128;
    const ll n0 = (ll)blockIdx.x * 256;
    const ll zb = blockIdx.z;

    const __nv_bfloat16* A1 = Ah + zb * sA;  const __nv_bfloat16* A2 = Al + zb * sA;
    const __nv_bfloat16* B1 = Bh + zb * sB;  const __nv_bfloat16* B2 = Bl + zb * sB;

    const int NC = K >> 5;
    // prologue: stages 0,1
    if (ASRC) {
        float4 r[4];
        ldg_A_f32(r, Af, m0,  0, K, tid); sts_A_split(smc,       r, tid);
        ldg_A_f32(r, Af, m0, 32, K, tid); sts_A_split(smc + STG, r, tid);
    } else {
        fill_A_bf(sbase,       A1, A2, m0,  0, K, tid);
        fill_A_bf(sbase + STG, A1, A2, m0, 32, K, tid);
    }
    fill_B(sbase,       B1, B2, n0,  0, K, tid);
    asm volatile("cp.async.commit_group;" ::: "memory");
    fill_B(sbase + STG, B1, B2, n0, 32, K, tid);
    asm volatile("cp.async.commit_group;" ::: "memory");

    float acc[4][8][4];
    #pragma unroll
    for (int i = 0; i < 4; i++)
        #pragma unroll
        for (int j = 0; j < 8; j++)
            #pragma unroll
            for (int q = 0; q < 4; q++) acc[i][j][q] = 0.0f;

    const uint32_t a_off = (uint32_t)((warp_m*64 + (lane & 15)) * 80 + ((lane >> 4) << 4));
    const uint32_t b_off = 20480u
        + (uint32_t)((warp_n*64 + ((lane >> 4) << 3) + (lane & 7)) * 80
                     + (((lane >> 3) & 1) << 4));

    for (int c = 0; c < NC; c++) {
        asm volatile("cp.async.wait_group 1;" ::: "memory");
        __syncthreads();
        const uint32_t sb = sbase + (uint32_t)(c % 3) * STG;

        float4 r[4];
        const bool pf = (c + 2 < NC);
        if (ASRC) {
            if (pf) ldg_A_f32(r, Af, m0, (c + 2) * 32, K, tid);
        } else {
            if (pf) fill_A_bf(sbase + (uint32_t)((c + 2) % 3) * STG, A1, A2,
                              m0, (c + 2) * 32, K, tid);
        }
        if (pf) fill_B(sbase + (uint32_t)((c + 2) % 3) * STG, B1, B2, n0, (c + 2) * 32, K, tid);
        asm volatile("cp.async.commit_group;" ::: "memory");

        #pragma unroll
        for (int ks = 0; ks < 2; ks++) {
            const uint32_t ab = sb + a_off + (uint32_t)(ks*32);
            const uint32_t bb = sb + b_off + (uint32_t)(ks*32);
            uint32_t afh[4][4], afl[4][4], bq[4][4];
            #pragma unroll
            for (int mt = 0; mt < 4; mt++) {
                ldsm4(afh[mt], ab + mt*1280u);
                ldsm4(afl[mt], ab + mt*1280u + 10240u);
            }
            #pragma unroll
            for (int nt = 0; nt < 4; nt++) ldsm4(bq[nt], bb + nt*1280u);   // B hi
            #pragma unroll
            for (int mt = 0; mt < 4; mt++)
                #pragma unroll
                for (int nt = 0; nt < 8; nt++) {
                    const uint32_t* bp = &bq[nt >> 1][(nt & 1) * 2];
                    mma16816(acc[mt][nt], afh[mt], bp);
                    mma16816(acc[mt][nt], afl[mt], bp);
                }
            #pragma unroll
            for (int nt = 0; nt < 4; nt++) ldsm4(bq[nt], bb + nt*1280u + 20480u); // B lo
            #pragma unroll
            for (int mt = 0; mt < 4; mt++)
                #pragma unroll
                for (int nt = 0; nt < 8; nt++)
                    mma16816(acc[mt][nt], afh[mt], &bq[nt >> 1][(nt & 1) * 2]);
        }
        if (ASRC && pf)
            sts_A_split(smc + ((c + 2) % 3) * STG, r, tid);
    }

    // ---------------- epilogue ----------------------------------------------------
    const int r0 = lane >> 2, c0 = (lane & 3) * 2;
    if (EPI != 4) {
        float*         Cbf = Cf + zb * sC;
        __nv_bfloat16* Cbh = Ch + zb * sC;
        __nv_bfloat16* Cbl = Cl + zb * sC;
        const float*   Rb  = res + zb * sC;
        #pragma unroll
        for (int mt = 0; mt < 4; mt++)
            #pragma unroll
            for (int nt = 0; nt < 8; nt++) {
                const int n = warp_n*64 + nt*8 + c0;
                float2 bv = make_float2(0.f, 0.f);
                if (EPI >= 1) bv = *(const float2*)&bias[n0 + n];
                #pragma unroll
                for (int hh = 0; hh < 2; hh++) {
                    const int m = warp_m*64 + mt*16 + r0 + hh*8;
                    float v0 = acc[mt][nt][hh*2], v1 = acc[mt][nt][hh*2+1];
                    if (EPI >= 1) { v0 += bv.x; v1 += bv.y; }
                    if (EPI >= 2) { v0 = gelu_f(v0); v1 = gelu_f(v1); }
                    const ll idx = (m0 + m) * (ll)N + n0 + n;
                    if (EPI == 3) {
                        float2 rv = *(const float2*)&Rb[idx];
                        v0 += rv.x; v1 += rv.y;
                    }
                    if (OUT == 0) {
                        *(float2*)&Cbf[idx] = make_float2(v0, v1);
                    } else {
                        __nv_bfloat162 h, l; split2(v0, v1, h, l);
                        *(__nv_bfloat162*)&Cbh[idx] = h;
                        *(__nv_bfloat162*)&Cbl[idx] = l;
                    }
                }
            }
    } else {
        // bias+gelu, transposed split store: bodyT[b][n][t]
        __syncthreads();
        float* st = (float*)smc;                     // 128 rows x 256 cols, stride 260
        #pragma unroll
        for (int mt = 0; mt < 4; mt++)
            #pragma unroll
            for (int nt = 0; nt < 8; nt++) {
                const int n = warp_n*64 + nt*8 + c0;
                const float2 bv = *(const float2*)&bias[n0 + n];
                #pragma unroll
                for (int hh = 0; hh < 2; hh++) {
                    const int m = warp_m*64 + mt*16 + r0 + hh*8;
                    st[m*260 + n]     = gelu_f(acc[mt][nt][hh*2]   + bv.x);
                    st[m*260 + n + 1] = gelu_f(acc[mt][nt][hh*2+1] + bv.y);
                }
            }
        __syncthreads();
        const int b  = (int)(m0 >> 11);
        const int t0 = (int)(m0 & 2047);
        for (int e = tid; e < 256 * 64; e += NTHREADS) {
            const int n  = e >> 6;
            const int tp = (e & 63) * 2;
            const float v0 = st[tp*260 + n], v1 = st[(tp+1)*260 + n];
            __nv_bfloat162 h, l; split2(v0, v1, h, l);
            const ll idx = ((ll)b * DD + n0 + n) * TT + t0 + tp;
            *(__nv_bfloat162*)&Ch[idx] = h;
            *(__nv_bfloat162*)&Cl[idx] = l;
        }
    }
}

// ---------------- weight prep (transpose + split) --------------------------------
__device__ __forceinline__ void wtile(const float* src, __nv_bfloat16* dh, __nv_bfloat16* dl,
                                      int R, int Cc, int bx, int by)
{
    __shared__ float t[32][33];
    int x = bx * 32 + threadIdx.x;
    int y = by * 32 + threadIdx.y;
    #pragma unroll
    for (int j = 0; j < 32; j += 8) t[threadIdx.y + j][threadIdx.x] = src[(ll)(y + j) * Cc + x];
    __syncthreads();
    x = by * 32 + threadIdx.x;
    y = bx * 32 + threadIdx.y;
    #pragma unroll
    for (int j = 0; j < 32; j += 8) {
        float v = t[threadIdx.x][threadIdx.y + j];
        __nv_bfloat16 h = __float2bfloat16_rn(v);
        ll idx = (ll)(y + j) * R + x;
        dh[idx] = h;
        dl[idx] = __float2bfloat16_rn(v - __bfloat162float(h));
    }
}
__global__ void __launch_bounds__(256)
wprep1(const float* __restrict__ s0, const float* __restrict__ s1)
{
    const int b = blockIdx.x;
    const int w = b >> 8, tt = b & 255;
    wtile(w ? s1 : s0, w ? g_WrTh : g_WlTh, w ? g_WrTl : g_WlTl,
          DD, DD, tt & 15, tt >> 4);
}
__global__ void __launch_bounds__(256)
wprep2(const float* __restrict__ s2, const float* __restrict__ s3,
       const float* __restrict__ s4, const float* __restrict__ s5,
       const float* __restrict__ s6)
{
    const int b = blockIdx.x;
    if (b < 768) {
        const int w = b >> 8, tt = b & 255;
        const float* src = w == 0 ? s2 : (w == 1 ? s3 : s4);
        __nv_bfloat16* dh = w == 0 ? g_WbTh : (w == 1 ? g_WoTh : g_W1Th);
        __nv_bfloat16* dl = w == 0 ? g_WbTl : (w == 1 ? g_WoTl : g_W1Tl);
        wtile(src, dh, dl, DD, DD, tt & 15, tt >> 4);
    } else if (b < 1536) {
        const int tt = b - 768;
        wtile(s5, g_W2Th, g_W2Tl, DD, DMID, tt % 48, tt / 48);
    } else {
        const int tt = b - 1536;
        wtile(s6, g_W3Th, g_W3Tl, DMID, DD, tt % 16, tt / 16);
    }
}

// ---------------- softmax rows of 2048, split-bf16 in/out ------------------------
__global__ void __launch_bounds__(256)
softmax2048s(__nv_bfloat16* __restrict__ Sh, __nv_bfloat16* __restrict__ Sl)
{
    __shared__ float sh[8];
    const ll base = (ll)blockIdx.x * TT;
    const int tid = threadIdx.x, lane = tid & 31, warp = tid >> 5;
    float x[8];
    {
        uint4 hv = *(const uint4*)(Sh + base + tid * 8);
        uint4 lv = *(const uint4*)(Sl + base + tid * 8);
        const uint32_t hr[4] = {hv.x, hv.y, hv.z, hv.w};
        const uint32_t lr[4] = {lv.x, lv.y, lv.z, lv.w};
        #pragma unroll
        for (int i = 0; i < 4; i++) {
            float2 h2 = __bfloat1622float2(*(const __nv_bfloat162*)&hr[i]);
            float2 l2 = __bfloat1622float2(*(const __nv_bfloat162*)&lr[i]);
            x[i*2]   = h2.x + l2.x;
            x[i*2+1] = h2.y + l2.y;
        }
    }
    float m = x[0];
    #pragma unroll
    for (int i = 1; i < 8; i++) m = fmaxf(m, x[i]);
    #pragma unroll
    for (int o = 16; o > 0; o >>= 1) m = fmaxf(m, __shfl_xor_sync(0xffffffffu, m, o));
    if (lane == 0) sh[warp] = m;
    __syncthreads();
    if (tid == 0) { float mm = sh[0]; for (int w = 1; w < 8; w++) mm = fmaxf(mm, sh[w]); sh[0] = mm; }
    __syncthreads();
    const float rmax = sh[0];
    __syncthreads();
    float e[8], s = 0.0f;
    #pragma unroll
    for (int i = 0; i < 8; i++) { e[i] = __expf(x[i] - rmax); s += e[i]; }
    #pragma unroll
    for (int o = 16; o > 0; o >>= 1) s += __shfl_xor_sync(0xffffffffu, s, o);
    if (lane == 0) sh[warp] = s;
    __syncthreads();
    if (tid == 0) { float ss = 0; for (int w = 0; w < 8; w++) ss += sh[w]; sh[0] = ss; }
    __syncthreads();
    const float inv = 1.0f / sh[0];
    #pragma unroll
    for (int i = 0; i < 4; i++) {
        __nv_bfloat162 h, l;
        split2(e[i*2] * inv, e[i*2+1] * inv, h, l);
        *(__nv_bfloat162*)&Sh[base + tid*8 + i*2] = h;
        *(__nv_bfloat162*)&Sl[base + tid*8 + i*2] = l;
    }
}

// ---------------- layernorm rows of 512 -> fp32 + split -------------------------
__global__ void __launch_bounds__(128)
layernorm512s(const float* __restrict__ X, float* __restrict__ Y,
              __nv_bfloat16* __restrict__ Yh, __nv_bfloat16* __restrict__ Yl,
              const float* __restrict__ g, const float* __restrict__ b)
{
    __shared__ float shs[4], shq[4];
    const ll base = (ll)blockIdx.x * DD;
    const float* x = X + base;
    const int tid = threadIdx.x, lane = tid & 31, warp = tid >> 5;
    float4 v = *(const float4*)(x + tid * 4);
    float s = v.x + v.y + v.z + v.w;
    float q = v.x*v.x + v.y*v.y + v.z*v.z + v.w*v.w;
    #pragma unroll
    for (int o = 16; o > 0; o >>= 1) {
        s += __shfl_xor_sync(0xffffffffu, s, o);
        q += __shfl_xor_sync(0xffffffffu, q, o);
    }
    if (lane == 0) { shs[warp] = s; shq[warp] = q; }
    __syncthreads();
    if (tid == 0) { shs[0] = shs[0]+shs[1]+shs[2]+shs[3]; shq[0] = shq[0]+shq[1]+shq[2]+shq[3]; }
    __syncthreads();
    const float mu  = shs[0] * (1.0f / DD);
    const float var = shq[0] * (1.0f / DD) - mu * mu;
    const float r = rsqrtf(var + 1e-5f);
    float4 gg = *(const float4*)(g + tid * 4);
    float4 bb = *(const float4*)(b + tid * 4);
    float4 o;
    o.x = (v.x - mu) * r * gg.x + bb.x;
    o.y = (v.y - mu) * r * gg.y + bb.y;
    o.z = (v.z - mu) * r * gg.z + bb.z;
    o.w = (v.w - mu) * r * gg.w + bb.w;
    *(float4*)(Y + base + tid * 4) = o;
    __nv_bfloat162 h0, l0, h1, l1;
    split2(o.x, o.y, h0, l0);
    split2(o.z, o.w, h1, l1);
    *(__nv_bfloat162*)&Yh[base + tid*4]     = h0;
    *(__nv_bfloat162*)&Yh[base + tid*4 + 2] = h1;
    *(__nv_bfloat162*)&Yl[base + tid*4]     = l0;
    *(__nv_bfloat162*)&Yl[base + tid*4 + 2] = l1;
}

// ---------------- launch ----------------------------------------------------------
extern "C" void kernel_launch(void* const* d_in, const int* in_sizes, int n_in,
                              void* d_out, int out_size)
{
    const float* left  = (const float*)d_in[0];
    const float* right = (const float*)d_in[1];
    const float* body  = (const float*)d_in[2];
    const float* Wl = (const float*)d_in[3];  const float* bl = (const float*)d_in[4];
    const float* Wr = (const float*)d_in[5];  const float* br = (const float*)d_in[6];
    const float* Wb = (const float*)d_in[7];  const float* bbv = (const float*)d_in[8];
    const float* Wo = (const float*)d_in[9];  const float* bo = (const float*)d_in[10];
    const float* ln_g = (const float*)d_in[11]; const float* ln_b = (const float*)d_in[12];
    const float* W1 = (const float*)d_in[13]; const float* b1 = (const float*)d_in[14];
    const float* lg2 = (const float*)d_in[15]; const float* lb2 = (const float*)d_in[16];
    const float* W2 = (const float*)d_in[17]; const float* b2 = (const float*)d_in[18];
    const float* W3 = (const float*)d_in[19]; const float* b3 = (const float*)d_in[20];
    float* out = (float*)d_out;

    float *t2, *ln1;
    __nv_bfloat16 *Sh, *Sl, *loh, *lol, *roh, *rol, *bth, *btl;
    __nv_bfloat16 *t1h, *t1l, *l1h, *l1l, *l2h, *l2l, *mh, *ml;
    __nv_bfloat16 *WlTh,*WlTl,*WrTh,*WrTl,*WbTh,*WbTl,*WoTh,*WoTl,*W1Th,*W1Tl,*W2Th,*W2Tl,*W3Th,*W3Tl;
    cudaGetSymbolAddress((void**)&Sh,  g_Sh);  cudaGetSymbolAddress((void**)&Sl,  g_Sl);
    cudaGetSymbolAddress((void**)&loh, g_loh); cudaGetSymbolAddress((void**)&lol, g_lol);
    cudaGetSymbolAddress((void**)&roh, g_roh); cudaGetSymbolAddress((void**)&rol, g_rol);
    cudaGetSymbolAddress((void**)&bth, g_bth); cudaGetSymbolAddress((void**)&btl, g_btl);
    cudaGetSymbolAddress((void**)&t1h, g_t1h); cudaGetSymbolAddress((void**)&t1l, g_t1l);
    cudaGetSymbolAddress((void**)&t2,  g_t2);  cudaGetSymbolAddress((void**)&ln1, g_ln1);
    cudaGetSymbolAddress((void**)&l1h, g_l1h); cudaGetSymbolAddress((void**)&l1l, g_l1l);
    cudaGetSymbolAddress((void**)&l2h, g_l2h); cudaGetSymbolAddress((void**)&l2l, g_l2l);
    cudaGetSymbolAddress((void**)&mh,  g_mh);  cudaGetSymbolAddress((void**)&ml,  g_ml);
    cudaGetSymbolAddress((void**)&WlTh,g_WlTh);cudaGetSymbolAddress((void**)&WlTl,g_WlTl);
    cudaGetSymbolAddress((void**)&WrTh,g_WrTh);cudaGetSymbolAddress((void**)&WrTl,g_WrTl);
    cudaGetSymbolAddress((void**)&WbTh,g_WbTh);cudaGetSymbolAddress((void**)&WbTl,g_WbTl);
    cudaGetSymbolAddress((void**)&WoTh,g_WoTh);cudaGetSymbolAddress((void**)&WoTl,g_WoTl);
    cudaGetSymbolAddress((void**)&W1Th,g_W1Th);cudaGetSymbolAddress((void**)&W1Tl,g_W1Tl);
    cudaGetSymbolAddress((void**)&W2Th,g_W2Th);cudaGetSymbolAddress((void**)&W2Tl,g_W2Tl);
    cudaGetSymbolAddress((void**)&W3Th,g_W3Th);cudaGetSymbolAddress((void**)&W3Tl,g_W3Tl);

    cudaFuncSetAttribute(gemm_mma<2,1,1>, cudaFuncAttributeMaxDynamicSharedMemorySize, SMEM_BYTES);
    cudaFuncSetAttribute(gemm_mma<4,1,1>, cudaFuncAttributeMaxDynamicSharedMemorySize, SMEM_BYTES);
    cudaFuncSetAttribute(gemm_mma<0,1,0>, cudaFuncAttributeMaxDynamicSharedMemorySize, SMEM_BYTES);
    cudaFuncSetAttribute(gemm_mma<1,0,0>, cudaFuncAttributeMaxDynamicSharedMemorySize, SMEM_BYTES);
    cudaFuncSetAttribute(gemm_mma<3,0,0>, cudaFuncAttributeMaxDynamicSharedMemorySize, SMEM_BYTES);
    cudaFuncSetAttribute(gemm_mma<2,1,0>, cudaFuncAttributeMaxDynamicSharedMemorySize, SMEM_BYTES);

    const ll sTD = (ll)TT * DD;
    const ll sTT = (ll)TT * TT;
    dim3 tb(32, 8);

    // idx 0: Wl, Wr prep only
    wprep1<<<512, tb>>>(Wl, Wr);
    // idx 1-2: left/right projections (A = fp32 embeds, split in-kernel)
    gemm_mma<2,1,1><<<dim3(2,128,1), NTHREADS, SMEM_BYTES>>>(nullptr, nullptr, left,
        WlTh, WlTl, bl, nullptr, nullptr, loh, lol, DD, DD, 0, 0, 0);
    gemm_mma<2,1,1><<<dim3(2,128,1), NTHREADS, SMEM_BYTES>>>(nullptr, nullptr, right,
        WrTh, WrTl, br, nullptr, nullptr, roh, rol, DD, DD, 0, 0, 0);
    // idx 3: attention scores  <-- ncu profiles this launch
    gemm_mma<0,1,0><<<dim3(8,16,BB), NTHREADS, SMEM_BYTES>>>(roh, rol, nullptr,
        loh, lol, nullptr, nullptr, nullptr, Sh, Sl, DD, TT, sTD, sTD, sTT);
    // idx 4-5: remaining weight prep + body projection (transposed out)
    wprep2<<<2304, tb>>>(Wb, Wo, W1, W2, W3);
    gemm_mma<4,1,1><<<dim3(2,128,1), NTHREADS, SMEM_BYTES>>>(nullptr, nullptr, body,
        WbTh, WbTl, bbv, nullptr, nullptr, bth, btl, DD, DD, 0, 0, 0);
    // softmax + fuse
    softmax2048s<<<BT, 256>>>(Sh, Sl);
    gemm_mma<0,1,0><<<dim3(2,16,BB), NTHREADS, SMEM_BYTES>>>(Sh, Sl, nullptr,
        bth, btl, nullptr, nullptr, nullptr, t1h, t1l, TT, DD, sTT, sTD, sTD);
    // output projection + LN
    gemm_mma<1,0,0><<<dim3(2,128,1), NTHREADS, SMEM_BYTES>>>(t1h, t1l, nullptr,
        WoTh, WoTl, bo, nullptr, t2, nullptr, nullptr, DD, DD, 0, 0, 0);
    layernorm512s<<<BT, 128>>>(t2, ln1, l1h, l1l, ln_g, ln_b);
    // inverted residual
    gemm_mma<3,0,0><<<dim3(2,128,1), NTHREADS, SMEM_BYTES>>>(l1h, l1l, nullptr,
        W1Th, W1Tl, b1, ln1, t2, nullptr, nullptr, DD, DD, 0, 0, 0);
    layernorm512s<<<BT, 128>>>(t2, ln1, l2h, l2l, lg2, lb2);
    gemm_mma<2,1,0><<<dim3(6,128,1), NTHREADS, SMEM_BYTES>>>(l2h, l2l, nullptr,
        W2Th, W2Tl, b2, nullptr, nullptr, mh, ml, DD, DMID, 0, 0, 0);
    gemm_mma<1,0,0><<<dim3(2,128,1), NTHREADS, SMEM_BYTES>>>(mh, ml, nullptr,
        W3Th, W3Tl, b3, nullptr, out, nullptr, nullptr, DMID, DD, 0, 0, 0);
}

// round 11
// speedup vs baseline: 2.8643x; 1.1269x over previous
#include <cuda_runtime.h>
#include <cuda_bf16.h>
#include <cstdint>
#include <math.h>

#define BB   8
#define TT   2048
#define DD   512
#define BT   (BB*TT)
#define DMID (3*DD)
typedef long long ll;

// ---------------- scratch -------------------------------------------------------
__device__ __align__(16) __nv_bfloat16 g_Sh[(ll)BB*TT*TT];
__device__ __align__(16) __nv_bfloat16 g_Sl[(ll)BB*TT*TT];
__device__ __align__(16) __nv_bfloat16 g_loh[BT*DD], g_lol[BT*DD];
__device__ __align__(16) __nv_bfloat16 g_roh[BT*DD], g_rol[BT*DD];
__device__ __align__(16) __nv_bfloat16 g_bth[BT*DD], g_btl[BT*DD];
__device__ __align__(16) __nv_bfloat16 g_t1h[BT*DD], g_t1l[BT*DD];
__device__ __align__(16) float g_t2 [BT*DD];
__device__ __align__(16) float g_ln1[BT*DD];
__device__ __align__(16) __nv_bfloat16 g_l1h[BT*DD], g_l1l[BT*DD];
__device__ __align__(16) __nv_bfloat16 g_l2h[BT*DD], g_l2l[BT*DD];
__device__ __align__(16) __nv_bfloat16 g_mh[BT*DMID], g_ml[BT*DMID];
__device__ __align__(16) __nv_bfloat16 g_WlTh[DD*DD],  g_WlTl[DD*DD];
__device__ __align__(16) __nv_bfloat16 g_WrTh[DD*DD],  g_WrTl[DD*DD];
__device__ __align__(16) __nv_bfloat16 g_WbTh[DD*DD],  g_WbTl[DD*DD];
__device__ __align__(16) __nv_bfloat16 g_WoTh[DD*DD],  g_WoTl[DD*DD];
__device__ __align__(16) __nv_bfloat16 g_W1Th[DD*DD],  g_W1Tl[DD*DD];
__device__ __align__(16) __nv_bfloat16 g_W2Th[DMID*DD],g_W2Tl[DMID*DD];
__device__ __align__(16) __nv_bfloat16 g_W3Th[DD*DMID],g_W3Tl[DD*DMID];

// ---------------- helpers -------------------------------------------------------
__device__ __forceinline__ float gelu_f(float x) {
    return 0.5f * x * (1.0f + erff(x * 0.7071067811865476f));
}
__device__ __forceinline__ uint32_t smem_u32(const void* p) {
    uint32_t a;
    asm("{ .reg .u64 t; cvta.to.shared.u64 t, %1; cvt.u32.u64 %0, t; }" : "=r"(a) : "l"(p));
    return a;
}
__device__ __forceinline__ void cpa16(uint32_t dst, const void* src) {
    asm volatile("cp.async.cg.shared.global [%0], [%1], 16;" :: "r"(dst), "l"(src));
}
__device__ __forceinline__ void ldsm4(uint32_t* r, uint32_t a) {
    asm volatile("ldmatrix.sync.aligned.m8n8.x4.shared.b16 {%0,%1,%2,%3}, [%4];"
                 : "=r"(r[0]), "=r"(r[1]), "=r"(r[2]), "=r"(r[3]) : "r"(a));
}
__device__ __forceinline__ void mma16816(float* d, const uint32_t* a, const uint32_t* b) {
    asm volatile("mma.sync.aligned.m16n8k16.row.col.f32.bf16.bf16.f32 "
                 "{%0,%1,%2,%3}, {%4,%5,%6,%7}, {%8,%9}, {%0,%1,%2,%3};"
                 : "+f"(d[0]), "+f"(d[1]), "+f"(d[2]), "+f"(d[3])
                 : "r"(a[0]), "r"(a[1]), "r"(a[2]), "r"(a[3]), "r"(b[0]), "r"(b[1]));
}
__device__ __forceinline__ void split2(float v0, float v1, __nv_bfloat162& h, __nv_bfloat162& l) {
    h = __floats2bfloat162_rn(v0, v1);
    float2 f = __bfloat1622float2(h);
    l = __floats2bfloat162_rn(v0 - f.x, v1 - f.y);
}
// swizzled smem offset: 64B rows, chunk (16B) XORed with (row>>1)&3
__device__ __forceinline__ uint32_t swz_off(int row, int ch) {
    return (uint32_t)(row * 64 + ((ch ^ ((row >> 1) & 3)) << 4));
}

// stage: Ah 8192 | Al 8192 | Bh 8192 | Bl 8192 = 32768 (swizzled 64B rows)
#define STG 32768u
#define SMEM_BYTES (3*32768)
#define NTHREADS 256

// --- B fill: 128 rows x 32 k (split bf16) ----------------------------------------
__device__ __forceinline__ void fill_B(uint32_t sb,
    const __nv_bfloat16* B1, const __nv_bfloat16* B2, ll n0, int k0, int K, int tid)
{
    #pragma unroll
    for (int j = 0; j < 2; j++) {
        const int id = j*256 + tid;                 // 512 ids: 128 rows x 4 chunks
        const int row = id >> 2, ch = id & 3;
        const uint32_t so = swz_off(row, ch);
        const ll bo = (n0 + row) * (ll)K + k0 + ch * 8;
        cpa16(sb + 16384u + so, B1 + bo);
        cpa16(sb + 24576u + so, B2 + bo);
    }
}
// --- A fill, pre-split bf16 -------------------------------------------------------
__device__ __forceinline__ void fill_A_bf(uint32_t sb,
    const __nv_bfloat16* A1, const __nv_bfloat16* A2, ll m0, int k0, int K, int tid)
{
    #pragma unroll
    for (int j = 0; j < 2; j++) {
        const int id = j*256 + tid;
        const int row = id >> 2, ch = id & 3;
        const uint32_t so = swz_off(row, ch);
        const ll ao = (m0 + row) * (ll)K + k0 + ch * 8;
        cpa16(sb + so, A1 + ao);
        cpa16(sb + 8192u + so, A2 + ao);
    }
}
// --- A fill, fp32 source ----------------------------------------------------------
__device__ __forceinline__ void ldg_A_f32(float4* r, const float* Af,
                                          ll m0, int k0, int K, int tid)
{
    #pragma unroll
    for (int j = 0; j < 2; j++) {
        const int id = j*256 + tid;
        const int row = id >> 2, ch = id & 3;
        const float* s = Af + (m0 + row) * (ll)K + k0 + ch * 8;
        r[j*2]   = *(const float4*)s;
        r[j*2+1] = *(const float4*)(s + 4);
    }
}
__device__ __forceinline__ void sts_A_split(char* sp, const float4* r, int tid)
{
    #pragma unroll
    for (int j = 0; j < 2; j++) {
        const int id = j*256 + tid;
        const int row = id >> 2, ch = id & 3;
        const uint32_t so = swz_off(row, ch);
        __nv_bfloat162 h0,l0,h1,l1,h2,l2,h3,l3;
        split2(r[j*2].x,   r[j*2].y,   h0, l0);
        split2(r[j*2].z,   r[j*2].w,   h1, l1);
        split2(r[j*2+1].x, r[j*2+1].y, h2, l2);
        split2(r[j*2+1].z, r[j*2+1].w, h3, l3);
        *(uint4*)(sp + so) = make_uint4(*(uint32_t*)&h0, *(uint32_t*)&h1,
                                        *(uint32_t*)&h2, *(uint32_t*)&h3);
        *(uint4*)(sp + 8192 + so) = make_uint4(*(uint32_t*)&l0, *(uint32_t*)&l1,
                                               *(uint32_t*)&l2, *(uint32_t*)&l3);
    }
}

// ---------------- GEMM: C tile 128x128 = A @ B^T, split-bf16 3-term --------------
// 8 warps 2(m) x 4(n), warp tile 64x32; 2 CTAs/SM (128-reg cap)
// EPI: 0 none, 1 +bias, 2 gelu(+bias), 3 gelu(+bias)+res, 4 gelu(+bias)+transposed
// OUT: 0 fp32, 1 split-bf16 ; ASRC: 0 A pre-split bf16, 1 A fp32 (split in-kernel)
template<int EPI, int OUT, int ASRC>
__global__ void __launch_bounds__(NTHREADS, 2)
gemm_mma(const __nv_bfloat16* __restrict__ Ah, const __nv_bfloat16* __restrict__ Al,
         const float* __restrict__ Af,
         const __nv_bfloat16* __restrict__ Bh, const __nv_bfloat16* __restrict__ Bl,
         const float* __restrict__ bias, const float* __restrict__ res,
         float* __restrict__ Cf, __nv_bfloat16* __restrict__ Ch, __nv_bfloat16* __restrict__ Cl,
         int K, int N, ll sA, ll sB, ll sC)
{
    extern __shared__ char smc[];
    const uint32_t sbase = smem_u32(smc);
    const int tid = threadIdx.x, lane = tid & 31, wid = tid >> 5;
    const int warp_m = wid & 1, warp_n = wid >> 1;   // 2 x 4, warp tile 64x32
    const ll m0 = (ll)blockIdx.y * 128;
    const ll n0 = (ll)blockIdx.x * 128;
    const ll zb = blockIdx.z;

    const __nv_bfloat16* A1 = Ah + zb * sA;  const __nv_bfloat16* A2 = Al + zb * sA;
    const __nv_bfloat16* B1 = Bh + zb * sB;  const __nv_bfloat16* B2 = Bl + zb * sB;

    const int NC = K >> 5;
    if (ASRC) {
        float4 r[4];
        ldg_A_f32(r, Af, m0,  0, K, tid); sts_A_split(smc,       r, tid);
        ldg_A_f32(r, Af, m0, 32, K, tid); sts_A_split(smc + STG, r, tid);
    } else {
        fill_A_bf(sbase,       A1, A2, m0,  0, K, tid);
        fill_A_bf(sbase + STG, A1, A2, m0, 32, K, tid);
    }
    fill_B(sbase,       B1, B2, n0,  0, K, tid);
    asm volatile("cp.async.commit_group;" ::: "memory");
    fill_B(sbase + STG, B1, B2, n0, 32, K, tid);
    asm volatile("cp.async.commit_group;" ::: "memory");

    float acc[4][4][4];
    #pragma unroll
    for (int i = 0; i < 4; i++)
        #pragma unroll
        for (int j = 0; j < 4; j++)
            #pragma unroll
            for (int q = 0; q < 4; q++) acc[i][j][q] = 0.0f;

    // ldsm addressing (swizzled)
    const int row_a = warp_m*64 + (lane & 15);
    const uint32_t a_row = (uint32_t)(row_a * 64);
    const int swa = ((lane & 15) >> 1) & 3;
    const int cha = lane >> 4;                       // 0/1
    const int row_b = warp_n*32 + ((lane >> 4) << 3) + (lane & 7);
    const uint32_t b_row = (uint32_t)(row_b * 64);
    const int swb = (row_b >> 1) & 3;
    const int chb = (lane >> 3) & 1;

    for (int c = 0; c < NC; c++) {
        asm volatile("cp.async.wait_group 1;" ::: "memory");
        __syncthreads();
        const uint32_t sb = sbase + (uint32_t)(c % 3) * STG;

        float4 r[4];
        const bool pf = (c + 2 < NC);
        if (ASRC) {
            if (pf) ldg_A_f32(r, Af, m0, (c + 2) * 32, K, tid);
        } else {
            if (pf) fill_A_bf(sbase + (uint32_t)((c + 2) % 3) * STG, A1, A2,
                              m0, (c + 2) * 32, K, tid);
        }
        if (pf) fill_B(sbase + (uint32_t)((c + 2) % 3) * STG, B1, B2, n0, (c + 2) * 32, K, tid);
        asm volatile("cp.async.commit_group;" ::: "memory");

        #pragma unroll
        for (int ks = 0; ks < 2; ks++) {
            const uint32_t ca = (uint32_t)(((ks*2 + cha) ^ swa) << 4);
            const uint32_t cb = (uint32_t)(((ks*2 + chb) ^ swb) << 4);
            uint32_t afh[4][4], afl[4][4], bq[2][4];
            #pragma unroll
            for (int mt = 0; mt < 4; mt++) {
                ldsm4(afh[mt], sb + a_row + mt*1024u + ca);
                ldsm4(afl[mt], sb + 8192u + a_row + mt*1024u + ca);
            }
            #pragma unroll
            for (int h = 0; h < 2; h++)
                ldsm4(bq[h], sb + 16384u + b_row + h*1024u + cb);      // B hi
            // term 1: Ah*Bh
            #pragma unroll
            for (int mt = 0; mt < 4; mt++)
                #pragma unroll
                for (int nt = 0; nt < 4; nt++)
                    mma16816(acc[mt][nt], afh[mt], &bq[nt >> 1][(nt & 1) * 2]);
            // term 2: Al*Bh
            #pragma unroll
            for (int mt = 0; mt < 4; mt++)
                #pragma unroll
                for (int nt = 0; nt < 4; nt++)
                    mma16816(acc[mt][nt], afl[mt], &bq[nt >> 1][(nt & 1) * 2]);
            // B lo over B hi
            #pragma unroll
            for (int h = 0; h < 2; h++)
                ldsm4(bq[h], sb + 24576u + b_row + h*1024u + cb);
            // term 3: Ah*Bl
            #pragma unroll
            for (int mt = 0; mt < 4; mt++)
                #pragma unroll
                for (int nt = 0; nt < 4; nt++)
                    mma16816(acc[mt][nt], afh[mt], &bq[nt >> 1][(nt & 1) * 2]);
        }
        if (ASRC && pf)
            sts_A_split(smc + ((c + 2) % 3) * STG, r, tid);
    }

    // ---------------- epilogue ----------------------------------------------------
    const int r0 = lane >> 2, c0 = (lane & 3) * 2;
    if (EPI != 4) {
        float*         Cbf = Cf + zb * sC;
        __nv_bfloat16* Cbh = Ch + zb * sC;
        __nv_bfloat16* Cbl = Cl + zb * sC;
        const float*   Rb  = res + zb * sC;
        #pragma unroll
        for (int mt = 0; mt < 4; mt++)
            #pragma unroll
            for (int nt = 0; nt < 4; nt++) {
                const int n = warp_n*32 + nt*8 + c0;
                float2 bv = make_float2(0.f, 0.f);
                if (EPI >= 1) bv = *(const float2*)&bias[n0 + n];
                #pragma unroll
                for (int hh = 0; hh < 2; hh++) {
                    const int m = warp_m*64 + mt*16 + r0 + hh*8;
                    float v0 = acc[mt][nt][hh*2], v1 = acc[mt][nt][hh*2+1];
                    if (EPI >= 1) { v0 += bv.x; v1 += bv.y; }
                    if (EPI >= 2) { v0 = gelu_f(v0); v1 = gelu_f(v1); }
                    const ll idx = (m0 + m) * (ll)N + n0 + n;
                    if (EPI == 3) {
                        float2 rv = *(const float2*)&Rb[idx];
                        v0 += rv.x; v1 += rv.y;
                    }
                    if (OUT == 0) {
                        *(float2*)&Cbf[idx] = make_float2(v0, v1);
                    } else {
                        __nv_bfloat162 h, l; split2(v0, v1, h, l);
                        *(__nv_bfloat162*)&Cbh[idx] = h;
                        *(__nv_bfloat162*)&Cbl[idx] = l;
                    }
                }
            }
    } else {
        // bias+gelu, transposed split store: bodyT[b][n][t]
        __syncthreads();
        float* st = (float*)smc;                    // 128 rows x 128 cols, stride 132
        #pragma unroll
        for (int mt = 0; mt < 4; mt++)
            #pragma unroll
            for (int nt = 0; nt < 4; nt++) {
                const int n = warp_n*32 + nt*8 + c0;
                const float2 bv = *(const float2*)&bias[n0 + n];
                #pragma unroll
                for (int hh = 0; hh < 2; hh++) {
                    const int m = warp_m*64 + mt*16 + r0 + hh*8;
                    st[m*132 + n]     = gelu_f(acc[mt][nt][hh*2]   + bv.x);
                    st[m*132 + n + 1] = gelu_f(acc[mt][nt][hh*2+1] + bv.y);
                }
            }
        __syncthreads();
        const int b  = (int)(m0 >> 11);
        const int t0 = (int)(m0 & 2047);
        for (int e = tid; e < 128 * 64; e += NTHREADS) {
            const int n  = e >> 6;
            const int tp = (e & 63) * 2;
            const float v0 = st[tp*132 + n], v1 = st[(tp+1)*132 + n];
            __nv_bfloat162 h, l; split2(v0, v1, h, l);
            const ll idx = ((ll)b * DD + n0 + n) * TT + t0 + tp;
            *(__nv_bfloat162*)&Ch[idx] = h;
            *(__nv_bfloat162*)&Cl[idx] = l;
        }
    }
}

// ---------------- weight prep (transpose + split) --------------------------------
__device__ __forceinline__ void wtile(const float* src, __nv_bfloat16* dh, __nv_bfloat16* dl,
                                      int R, int Cc, int bx, int by)
{
    __shared__ float t[32][33];
    int x = bx * 32 + threadIdx.x;
    int y = by * 32 + threadIdx.y;
    #pragma unroll
    for (int j = 0; j < 32; j += 8) t[threadIdx.y + j][threadIdx.x] = src[(ll)(y + j) * Cc + x];
    __syncthreads();
    x = by * 32 + threadIdx.x;
    y = bx * 32 + threadIdx.y;
    #pragma unroll
    for (int j = 0; j < 32; j += 8) {
        float v = t[threadIdx.x][threadIdx.y + j];
        __nv_bfloat16 h = __float2bfloat16_rn(v);
        ll idx = (ll)(y + j) * R + x;
        dh[idx] = h;
        dl[idx] = __float2bfloat16_rn(v - __bfloat162float(h));
    }
}
__global__ void __launch_bounds__(256)
wprep1(const float* __restrict__ s0, const float* __restrict__ s1)
{
    const int b = blockIdx.x;
    const int w = b >> 8, tt = b & 255;
    wtile(w ? s1 : s0, w ? g_WrTh : g_WlTh, w ? g_WrTl : g_WlTl,
          DD, DD, tt & 15, tt >> 4);
}
__global__ void __launch_bounds__(256)
wprep2(const float* __restrict__ s2, const float* __restrict__ s3,
       const float* __restrict__ s4, const float* __restrict__ s5,
       const float* __restrict__ s6)
{
    const int b = blockIdx.x;
    if (b < 768) {
        const int w = b >> 8, tt = b & 255;
        const float* src = w == 0 ? s2 : (w == 1 ? s3 : s4);
        __nv_bfloat16* dh = w == 0 ? g_WbTh : (w == 1 ? g_WoTh : g_W1Th);
        __nv_bfloat16* dl = w == 0 ? g_WbTl : (w == 1 ? g_WoTl : g_W1Tl);
        wtile(src, dh, dl, DD, DD, tt & 15, tt >> 4);
    } else if (b < 1536) {
        const int tt = b - 768;
        wtile(s5, g_W2Th, g_W2Tl, DD, DMID, tt % 48, tt / 48);
    } else {
        const int tt = b - 1536;
        wtile(s6, g_W3Th, g_W3Tl, DMID, DD, tt % 16, tt / 16);
    }
}

// ---------------- softmax rows of 2048, split-bf16 in/out ------------------------
__global__ void __launch_bounds__(256)
softmax2048s(__nv_bfloat16* __restrict__ Sh, __nv_bfloat16* __restrict__ Sl)
{
    __shared__ float sh[8];
    const ll base = (ll)blockIdx.x * TT;
    const int tid = threadIdx.x, lane = tid & 31, warp = tid >> 5;
    float x[8];
    {
        uint4 hv = *(const uint4*)(Sh + base + tid * 8);
        uint4 lv = *(const uint4*)(Sl + base + tid * 8);
        const uint32_t hr[4] = {hv.x, hv.y, hv.z, hv.w};
        const uint32_t lr[4] = {lv.x, lv.y, lv.z, lv.w};
        #pragma unroll
        for (int i = 0; i < 4; i++) {
            float2 h2 = __bfloat1622float2(*(const __nv_bfloat162*)&hr[i]);
            float2 l2 = __bfloat1622float2(*(const __nv_bfloat162*)&lr[i]);
            x[i*2]   = h2.x + l2.x;
            x[i*2+1] = h2.y + l2.y;
        }
    }
    float m = x[0];
    #pragma unroll
    for (int i = 1; i < 8; i++) m = fmaxf(m, x[i]);
    #pragma unroll
    for (int o = 16; o > 0; o >>= 1) m = fmaxf(m, __shfl_xor_sync(0xffffffffu, m, o));
    if (lane == 0) sh[warp] = m;
    __syncthreads();
    if (tid == 0) { float mm = sh[0]; for (int w = 1; w < 8; w++) mm = fmaxf(mm, sh[w]); sh[0] = mm; }
    __syncthreads();
    const float rmax = sh[0];
    __syncthreads();
    float e[8], s = 0.0f;
    #pragma unroll
    for (int i = 0; i < 8; i++) { e[i] = __expf(x[i] - rmax); s += e[i]; }
    #pragma unroll
    for (int o = 16; o > 0; o >>= 1) s += __shfl_xor_sync(0xffffffffu, s, o);
    if (lane == 0) sh[warp] = s;
    __syncthreads();
    if (tid == 0) { float ss = 0; for (int w = 0; w < 8; w++) ss += sh[w]; sh[0] = ss; }
    __syncthreads();
    const float inv = 1.0f / sh[0];
    #pragma unroll
    for (int i = 0; i < 4; i++) {
        __nv_bfloat162 h, l;
        split2(e[i*2] * inv, e[i*2+1] * inv, h, l);
        *(__nv_bfloat162*)&Sh[base + tid*8 + i*2] = h;
        *(__nv_bfloat162*)&Sl[base + tid*8 + i*2] = l;
    }
}

// ---------------- layernorm rows of 512 -> fp32 + split -------------------------
__global__ void __launch_bounds__(128)
layernorm512s(const float* __restrict__ X, float* __restrict__ Y,
              __nv_bfloat16* __restrict__ Yh, __nv_bfloat16* __restrict__ Yl,
              const float* __restrict__ g, const float* __restrict__ b)
{
    __shared__ float shs[4], shq[4];
    const ll base = (ll)blockIdx.x * DD;
    const float* x = X + base;
    const int tid = threadIdx.x, lane = tid & 31, warp = tid >> 5;
    float4 v = *(const float4*)(x + tid * 4);
    float s = v.x + v.y + v.z + v.w;
    float q = v.x*v.x + v.y*v.y + v.z*v.z + v.w*v.w;
    #pragma unroll
    for (int o = 16; o > 0; o >>= 1) {
        s += __shfl_xor_sync(0xffffffffu, s, o);
        q += __shfl_xor_sync(0xffffffffu, q, o);
    }
    if (lane == 0) { shs[warp] = s; shq[warp] = q; }
    __syncthreads();
    if (tid == 0) { shs[0] = shs[0]+shs[1]+shs[2]+shs[3]; shq[0] = shq[0]+shq[1]+shq[2]+shq[3]; }
    __syncthreads();
    const float mu  = shs[0] * (1.0f / DD);
    const float var = shq[0] * (1.0f / DD) - mu * mu;
    const float r = rsqrtf(var + 1e-5f);
    float4 gg = *(const float4*)(g + tid * 4);
    float4 bb = *(const float4*)(b + tid * 4);
    float4 o;
    o.x = (v.x - mu) * r * gg.x + bb.x;
    o.y = (v.y - mu) * r * gg.y + bb.y;
    o.z = (v.z - mu) * r * gg.z + bb.z;
    o.w = (v.w - mu) * r * gg.w + bb.w;
    *(float4*)(Y + base + tid * 4) = o;
    __nv_bfloat162 h0, l0, h1, l1;
    split2(o.x, o.y, h0, l0);
    split2(o.z, o.w, h1, l1);
    *(__nv_bfloat162*)&Yh[base + tid*4]     = h0;
    *(__nv_bfloat162*)&Yh[base + tid*4 + 2] = h1;
    *(__nv_bfloat162*)&Yl[base + tid*4]     = l0;
    *(__nv_bfloat162*)&Yl[base + tid*4 + 2] = l1;
}

// ---------------- launch ----------------------------------------------------------
extern "C" void kernel_launch(void* const* d_in, const int* in_sizes, int n_in,
                              void* d_out, int out_size)
{
    const float* left  = (const float*)d_in[0];
    const float* right = (const float*)d_in[1];
    const float* body  = (const float*)d_in[2];
    const float* Wl = (const float*)d_in[3];  const float* bl = (const float*)d_in[4];
    const float* Wr = (const float*)d_in[5];  const float* br = (const float*)d_in[6];
    const float* Wb = (const float*)d_in[7];  const float* bbv = (const float*)d_in[8];
    const float* Wo = (const float*)d_in[9];  const float* bo = (const float*)d_in[10];
    const float* ln_g = (const float*)d_in[11]; const float* ln_b = (const float*)d_in[12];
    const float* W1 = (const float*)d_in[13]; const float* b1 = (const float*)d_in[14];
    const float* lg2 = (const float*)d_in[15]; const float* lb2 = (const float*)d_in[16];
    const float* W2 = (const float*)d_in[17]; const float* b2 = (const float*)d_in[18];
    const float* W3 = (const float*)d_in[19]; const float* b3 = (const float*)d_in[20];
    float* out = (float*)d_out;

    float *t2, *ln1;
    __nv_bfloat16 *Sh, *Sl, *loh, *lol, *roh, *rol, *bth, *btl;
    __nv_bfloat16 *t1h, *t1l, *l1h, *l1l, *l2h, *l2l, *mh, *ml;
    __nv_bfloat16 *WlTh,*WlTl,*WrTh,*WrTl,*WbTh,*WbTl,*WoTh,*WoTl,*W1Th,*W1Tl,*W2Th,*W2Tl,*W3Th,*W3Tl;
    cudaGetSymbolAddress((void**)&Sh,  g_Sh);  cudaGetSymbolAddress((void**)&Sl,  g_Sl);
    cudaGetSymbolAddress((void**)&loh, g_loh); cudaGetSymbolAddress((void**)&lol, g_lol);
    cudaGetSymbolAddress((void**)&roh, g_roh); cudaGetSymbolAddress((void**)&rol, g_rol);
    cudaGetSymbolAddress((void**)&bth, g_bth); cudaGetSymbolAddress((void**)&btl, g_btl);
    cudaGetSymbolAddress((void**)&t1h, g_t1h); cudaGetSymbolAddress((void**)&t1l, g_t1l);
    cudaGetSymbolAddress((void**)&t2,  g_t2);  cudaGetSymbolAddress((void**)&ln1, g_ln1);
    cudaGetSymbolAddress((void**)&l1h, g_l1h); cudaGetSymbolAddress((void**)&l1l, g_l1l);
    cudaGetSymbolAddress((void**)&l2h, g_l2h); cudaGetSymbolAddress((void**)&l2l, g_l2l);
    cudaGetSymbolAddress((void**)&mh,  g_mh);  cudaGetSymbolAddress((void**)&ml,  g_ml);
    cudaGetSymbolAddress((void**)&WlTh,g_WlTh);cudaGetSymbolAddress((void**)&WlTl,g_WlTl);
    cudaGetSymbolAddress((void**)&WrTh,g_WrTh);cudaGetSymbolAddress((void**)&WrTl,g_WrTl);
    cudaGetSymbolAddress((void**)&WbTh,g_WbTh);cudaGetSymbolAddress((void**)&WbTl,g_WbTl);
    cudaGetSymbolAddress((void**)&WoTh,g_WoTh);cudaGetSymbolAddress((void**)&WoTl,g_WoTl);
    cudaGetSymbolAddress((void**)&W1Th,g_W1Th);cudaGetSymbolAddress((void**)&W1Tl,g_W1Tl);
    cudaGetSymbolAddress((void**)&W2Th,g_W2Th);cudaGetSymbolAddress((void**)&W2Tl,g_W2Tl);
    cudaGetSymbolAddress((void**)&W3Th,g_W3Th);cudaGetSymbolAddress((void**)&W3Tl,g_W3Tl);

    cudaFuncSetAttribute(gemm_mma<2,1,1>, cudaFuncAttributeMaxDynamicSharedMemorySize, SMEM_BYTES);
    cudaFuncSetAttribute(gemm_mma<4,1,1>, cudaFuncAttributeMaxDynamicSharedMemorySize, SMEM_BYTES);
    cudaFuncSetAttribute(gemm_mma<0,1,0>, cudaFuncAttributeMaxDynamicSharedMemorySize, SMEM_BYTES);
    cudaFuncSetAttribute(gemm_mma<1,0,0>, cudaFuncAttributeMaxDynamicSharedMemorySize, SMEM_BYTES);
    cudaFuncSetAttribute(gemm_mma<3,0,0>, cudaFuncAttributeMaxDynamicSharedMemorySize, SMEM_BYTES);
    cudaFuncSetAttribute(gemm_mma<2,1,0>, cudaFuncAttributeMaxDynamicSharedMemorySize, SMEM_BYTES);

    const ll sTD = (ll)TT * DD;
    const ll sTT = (ll)TT * TT;
    dim3 tb(32, 8);

    // idx 0: Wl, Wr prep only
    wprep1<<<512, tb>>>(Wl, Wr);
    // idx 1-2: left/right projections (A = fp32 embeds, split in-kernel)
    gemm_mma<2,1,1><<<dim3(4,128,1), NTHREADS, SMEM_BYTES>>>(nullptr, nullptr, left,
        WlTh, WlTl, bl, nullptr, nullptr, loh, lol, DD, DD, 0, 0, 0);
    gemm_mma<2,1,1><<<dim3(4,128,1), NTHREADS, SMEM_BYTES>>>(nullptr, nullptr, right,
        WrTh, WrTl, br, nullptr, nullptr, roh, rol, DD, DD, 0, 0, 0);
    // idx 3: attention scores  <-- ncu profiles this launch
    gemm_mma<0,1,0><<<dim3(16,16,BB), NTHREADS, SMEM_BYTES>>>(roh, rol, nullptr,
        loh, lol, nullptr, nullptr, nullptr, Sh, Sl, DD, TT, sTD, sTD, sTT);
    // idx 4-5: remaining weight prep + body projection (transposed out)
    wprep2<<<2304, tb>>>(Wb, Wo, W1, W2, W3);
    gemm_mma<4,1,1><<<dim3(4,128,1), NTHREADS, SMEM_BYTES>>>(nullptr, nullptr, body,
        WbTh, WbTl, bbv, nullptr, nullptr, bth, btl, DD, DD, 0, 0, 0);
    // softmax + fuse
    softmax2048s<<<BT, 256>>>(Sh, Sl);
    gemm_mma<0,1,0><<<dim3(4,16,BB), NTHREADS, SMEM_BYTES>>>(Sh, Sl, nullptr,
        bth, btl, nullptr, nullptr, nullptr, t1h, t1l, TT, DD, sTT, sTD, sTD);
    // output projection + LN
    gemm_mma<1,0,0><<<dim3(4,128,1), NTHREADS, SMEM_BYTES>>>(t1h, t1l, nullptr,
        WoTh, WoTl, bo, nullptr, t2, nullptr, nullptr, DD, DD, 0, 0, 0);
    layernorm512s<<<BT, 128>>>(t2, ln1, l1h, l1l, ln_g, ln_b);
    // inverted residual
    gemm_mma<3,0,0><<<dim3(4,128,1), NTHREADS, SMEM_BYTES>>>(l1h, l1l, nullptr,
        W1Th, W1Tl, b1, ln1, t2, nullptr, nullptr, DD, DD, 0, 0, 0);
    layernorm512s<<<BT, 128>>>(t2, ln1, l2h, l2l, lg2, lb2);
    gemm_mma<2,1,0><<<dim3(12,128,1), NTHREADS, SMEM_BYTES>>>(l2h, l2l, nullptr,
        W2Th, W2Tl, b2, nullptr, nullptr, mh, ml, DD, DMID, 0, 0, 0);
    gemm_mma<1,0,0><<<dim3(4,128,1), NTHREADS, SMEM_BYTES>>>(mh, ml, nullptr,
        W3Th, W3Tl, b3, nullptr, out, nullptr, nullptr, DMID, DD, 0, 0, 0);
}

// round 12
// speedup vs baseline: 3.3778x; 1.1793x over previous
#include <cuda_runtime.h>
#include <cuda_fp16.h>
#include <cstdint>
#include <math.h>

#define BB   8
#define TT   2048
#define DD   512
#define BT   (BB*TT)
#define DMID (3*DD)
typedef long long ll;

// ---------------- scratch -------------------------------------------------------
__device__ __align__(16) __half g_Sh[(ll)BB*TT*TT];
__device__ __align__(16) __half g_Sl[(ll)BB*TT*TT];
__device__ __align__(16) __half g_loh[BT*DD], g_lol[BT*DD];
__device__ __align__(16) __half g_roh[BT*DD], g_rol[BT*DD];
__device__ __align__(16) __half g_bth[BT*DD], g_btl[BT*DD];
__device__ __align__(16) __half g_t1h[BT*DD], g_t1l[BT*DD];
__device__ __align__(16) float g_t2 [BT*DD];
__device__ __align__(16) float g_ln1[BT*DD];
__device__ __align__(16) __half g_l1h[BT*DD], g_l1l[BT*DD];
__device__ __align__(16) __half g_l2h[BT*DD], g_l2l[BT*DD];
__device__ __align__(16) __half g_mh[BT*DMID], g_ml[BT*DMID];
__device__ __align__(16) __half g_WlTh[DD*DD],  g_WlTl[DD*DD];
__device__ __align__(16) __half g_WrTh[DD*DD],  g_WrTl[DD*DD];
__device__ __align__(16) __half g_WbTh[DD*DD],  g_WbTl[DD*DD];
__device__ __align__(16) __half g_WoTh[DD*DD],  g_WoTl[DD*DD];
__device__ __align__(16) __half g_W1Th[DD*DD],  g_W1Tl[DD*DD];
__device__ __align__(16) __half g_W2Th[DMID*DD],g_W2Tl[DMID*DD];
__device__ __align__(16) __half g_W3Th[DD*DMID],g_W3Tl[DD*DMID];

// ---------------- helpers -------------------------------------------------------
__device__ __forceinline__ float gelu_f(float x) {
    return 0.5f * x * (1.0f + erff(x * 0.7071067811865476f));
}
__device__ __forceinline__ uint32_t smem_u32(const void* p) {
    uint32_t a;
    asm("{ .reg .u64 t; cvta.to.shared.u64 t, %1; cvt.u32.u64 %0, t; }" : "=r"(a) : "l"(p));
    return a;
}
__device__ __forceinline__ void cpa16(uint32_t dst, const void* src) {
    asm volatile("cp.async.cg.shared.global [%0], [%1], 16;" :: "r"(dst), "l"(src));
}
__device__ __forceinline__ void ldsm4(uint32_t* r, uint32_t a) {
    asm volatile("ldmatrix.sync.aligned.m8n8.x4.shared.b16 {%0,%1,%2,%3}, [%4];"
                 : "=r"(r[0]), "=r"(r[1]), "=r"(r[2]), "=r"(r[3]) : "r"(a));
}
__device__ __forceinline__ void mma16816(float* d, const uint32_t* a, const uint32_t* b) {
    asm volatile("mma.sync.aligned.m16n8k16.row.col.f32.f16.f16.f32 "
                 "{%0,%1,%2,%3}, {%4,%5,%6,%7}, {%8,%9}, {%0,%1,%2,%3};"
                 : "+f"(d[0]), "+f"(d[1]), "+f"(d[2]), "+f"(d[3])
                 : "r"(a[0]), "r"(a[1]), "r"(a[2]), "r"(a[3]), "r"(b[0]), "r"(b[1]));
}
__device__ __forceinline__ void split2(float v0, float v1, __half2& h, __half2& l) {
    h = __floats2half2_rn(v0, v1);
    float2 f = __half22float2(h);
    l = __floats2half2_rn(v0 - f.x, v1 - f.y);
}
// swizzled smem offset: 64B rows, chunk (16B) XORed with (row>>1)&3
__device__ __forceinline__ uint32_t swz_off(int row, int ch) {
    return (uint32_t)(row * 64 + ((ch ^ ((row >> 1) & 3)) << 4));
}

// stage: Ah 8192 | Al 8192 | Bh 8192 | Bl 8192 = 32768 (swizzled 64B rows)
#define STG 32768u
#define SMEM_BYTES (3*32768)
#define NTHREADS 256

// --- B fill: 128 rows x 32 k (TERMS==3 loads lo too) ------------------------------
template<int TERMS>
__device__ __forceinline__ void fill_B(uint32_t sb,
    const __half* B1, const __half* B2, ll n0, int k0, int K, int tid)
{
    #pragma unroll
    for (int j = 0; j < 2; j++) {
        const int id = j*256 + tid;
        const int row = id >> 2, ch = id & 3;
        const uint32_t so = swz_off(row, ch);
        const ll bo = (n0 + row) * (ll)K + k0 + ch * 8;
        cpa16(sb + 16384u + so, B1 + bo);
        if (TERMS == 3) cpa16(sb + 24576u + so, B2 + bo);
    }
}
// --- A fill, pre-split fp16 --------------------------------------------------------
__device__ __forceinline__ void fill_A_hf(uint32_t sb,
    const __half* A1, const __half* A2, ll m0, int k0, int K, int tid)
{
    #pragma unroll
    for (int j = 0; j < 2; j++) {
        const int id = j*256 + tid;
        const int row = id >> 2, ch = id & 3;
        const uint32_t so = swz_off(row, ch);
        const ll ao = (m0 + row) * (ll)K + k0 + ch * 8;
        cpa16(sb + so, A1 + ao);
        cpa16(sb + 8192u + so, A2 + ao);
    }
}
// --- A fill, fp32 source -----------------------------------------------------------
__device__ __forceinline__ void ldg_A_f32(float4* r, const float* Af,
                                          ll m0, int k0, int K, int tid)
{
    #pragma unroll
    for (int j = 0; j < 2; j++) {
        const int id = j*256 + tid;
        const int row = id >> 2, ch = id & 3;
        const float* s = Af + (m0 + row) * (ll)K + k0 + ch * 8;
        r[j*2]   = *(const float4*)s;
        r[j*2+1] = *(const float4*)(s + 4);
    }
}
__device__ __forceinline__ void sts_A_split(char* sp, const float4* r, int tid)
{
    #pragma unroll
    for (int j = 0; j < 2; j++) {
        const int id = j*256 + tid;
        const int row = id >> 2, ch = id & 3;
        const uint32_t so = swz_off(row, ch);
        __half2 h0,l0,h1,l1,h2,l2,h3,l3;
        split2(r[j*2].x,   r[j*2].y,   h0, l0);
        split2(r[j*2].z,   r[j*2].w,   h1, l1);
        split2(r[j*2+1].x, r[j*2+1].y, h2, l2);
        split2(r[j*2+1].z, r[j*2+1].w, h3, l3);
        *(uint4*)(sp + so) = make_uint4(*(uint32_t*)&h0, *(uint32_t*)&h1,
                                        *(uint32_t*)&h2, *(uint32_t*)&h3);
        *(uint4*)(sp + 8192 + so) = make_uint4(*(uint32_t*)&l0, *(uint32_t*)&l1,
                                               *(uint32_t*)&l2, *(uint32_t*)&l3);
    }
}

// ---------------- GEMM: C tile 128x128 = A @ B^T, split-fp16 ---------------------
// 8 warps 2(m) x 4(n), warp tile 64x32; 2 CTAs/SM
// TERMS: 3 = AhBh+AlBh+AhBl ; 2 = AhBh+AlBh (skip B-lo entirely)
// EPI: 0 none, 1 +bias, 2 gelu(+bias), 3 gelu(+bias)+res, 4 gelu(+bias)+transposed
// OUT: 0 fp32, 1 split-fp16 ; ASRC: 0 A pre-split fp16, 1 A fp32 (split in-kernel)
template<int EPI, int OUT, int ASRC, int TERMS>
__global__ void __launch_bounds__(NTHREADS, 2)
gemm_mma(const __half* __restrict__ Ah, const __half* __restrict__ Al,
         const float* __restrict__ Af,
         const __half* __restrict__ Bh, const __half* __restrict__ Bl,
         const float* __restrict__ bias, const float* __restrict__ res,
         float* __restrict__ Cf, __half* __restrict__ Ch, __half* __restrict__ Cl,
         int K, int N, ll sA, ll sB, ll sC)
{
    extern __shared__ char smc[];
    const uint32_t sbase = smem_u32(smc);
    const int tid = threadIdx.x, lane = tid & 31, wid = tid >> 5;
    const int warp_m = wid & 1, warp_n = wid >> 1;
    const ll m0 = (ll)blockIdx.y * 128;
    const ll n0 = (ll)blockIdx.x * 128;
    const ll zb = blockIdx.z;

    const __half* A1 = Ah + zb * sA;  const __half* A2 = Al + zb * sA;
    const __half* B1 = Bh + zb * sB;  const __half* B2 = Bl + zb * sB;

    const int NC = K >> 5;
    if (ASRC) {
        float4 r[4];
        ldg_A_f32(r, Af, m0,  0, K, tid); sts_A_split(smc,       r, tid);
        ldg_A_f32(r, Af, m0, 32, K, tid); sts_A_split(smc + STG, r, tid);
    } else {
        fill_A_hf(sbase,       A1, A2, m0,  0, K, tid);
        fill_A_hf(sbase + STG, A1, A2, m0, 32, K, tid);
    }
    fill_B<TERMS>(sbase,       B1, B2, n0,  0, K, tid);
    asm volatile("cp.async.commit_group;" ::: "memory");
    fill_B<TERMS>(sbase + STG, B1, B2, n0, 32, K, tid);
    asm volatile("cp.async.commit_group;" ::: "memory");

    float acc[4][4][4];
    #pragma unroll
    for (int i = 0; i < 4; i++)
        #pragma unroll
        for (int j = 0; j < 4; j++)
            #pragma unroll
            for (int q = 0; q < 4; q++) acc[i][j][q] = 0.0f;

    const int row_a = warp_m*64 + (lane & 15);
    const uint32_t a_row = (uint32_t)(row_a * 64);
    const int swa = ((lane & 15) >> 1) & 3;
    const int cha = lane >> 4;
    const int row_b = warp_n*32 + ((lane >> 4) << 3) + (lane & 7);
    const uint32_t b_row = (uint32_t)(row_b * 64);
    const int swb = (row_b >> 1) & 3;
    const int chb = (lane >> 3) & 1;

    for (int c = 0; c < NC; c++) {
        asm volatile("cp.async.wait_group 1;" ::: "memory");
        __syncthreads();
        const uint32_t sb = sbase + (uint32_t)(c % 3) * STG;

        float4 r[4];
        const bool pf = (c + 2 < NC);
        if (ASRC) {
            if (pf) ldg_A_f32(r, Af, m0, (c + 2) * 32, K, tid);
        } else {
            if (pf) fill_A_hf(sbase + (uint32_t)((c + 2) % 3) * STG, A1, A2,
                              m0, (c + 2) * 32, K, tid);
        }
        if (pf) fill_B<TERMS>(sbase + (uint32_t)((c + 2) % 3) * STG, B1, B2, n0,
                              (c + 2) * 32, K, tid);
        asm volatile("cp.async.commit_group;" ::: "memory");

        #pragma unroll
        for (int ks = 0; ks < 2; ks++) {
            const uint32_t ca = (uint32_t)(((ks*2 + cha) ^ swa) << 4);
            const uint32_t cb = (uint32_t)(((ks*2 + chb) ^ swb) << 4);
            uint32_t afh[4][4], afl[4][4], bq[2][4];
            #pragma unroll
            for (int mt = 0; mt < 4; mt++) {
                ldsm4(afh[mt], sb + a_row + mt*1024u + ca);
                ldsm4(afl[mt], sb + 8192u + a_row + mt*1024u + ca);
            }
            #pragma unroll
            for (int h = 0; h < 2; h++)
                ldsm4(bq[h], sb + 16384u + b_row + h*1024u + cb);      // B hi
            // term 1: Ah*Bh
            #pragma unroll
            for (int mt = 0; mt < 4; mt++)
                #pragma unroll
                for (int nt = 0; nt < 4; nt++)
                    mma16816(acc[mt][nt], afh[mt], &bq[nt >> 1][(nt & 1) * 2]);
            // term 2: Al*Bh
            #pragma unroll
            for (int mt = 0; mt < 4; mt++)
                #pragma unroll
                for (int nt = 0; nt < 4; nt++)
                    mma16816(acc[mt][nt], afl[mt], &bq[nt >> 1][(nt & 1) * 2]);
            if (TERMS == 3) {
                // B lo over B hi
                #pragma unroll
                for (int h = 0; h < 2; h++)
                    ldsm4(bq[h], sb + 24576u + b_row + h*1024u + cb);
                // term 3: Ah*Bl
                #pragma unroll
                for (int mt = 0; mt < 4; mt++)
                    #pragma unroll
                    for (int nt = 0; nt < 4; nt++)
                        mma16816(acc[mt][nt], afh[mt], &bq[nt >> 1][(nt & 1) * 2]);
            }
        }
        if (ASRC && pf)
            sts_A_split(smc + ((c + 2) % 3) * STG, r, tid);
    }

    // ---------------- epilogue ----------------------------------------------------
    const int r0 = lane >> 2, c0 = (lane & 3) * 2;
    if (EPI != 4) {
        float*  Cbf = Cf + zb * sC;
        __half* Cbh = Ch + zb * sC;
        __half* Cbl = Cl + zb * sC;
        const float* Rb = res + zb * sC;
        #pragma unroll
        for (int mt = 0; mt < 4; mt++)
            #pragma unroll
            for (int nt = 0; nt < 4; nt++) {
                const int n = warp_n*32 + nt*8 + c0;
                float2 bv = make_float2(0.f, 0.f);
                if (EPI >= 1) bv = *(const float2*)&bias[n0 + n];
                #pragma unroll
                for (int hh = 0; hh < 2; hh++) {
                    const int m = warp_m*64 + mt*16 + r0 + hh*8;
                    float v0 = acc[mt][nt][hh*2], v1 = acc[mt][nt][hh*2+1];
                    if (EPI >= 1) { v0 += bv.x; v1 += bv.y; }
                    if (EPI >= 2) { v0 = gelu_f(v0); v1 = gelu_f(v1); }
                    const ll idx = (m0 + m) * (ll)N + n0 + n;
                    if (EPI == 3) {
                        float2 rv = *(const float2*)&Rb[idx];
                        v0 += rv.x; v1 += rv.y;
                    }
                    if (OUT == 0) {
                        *(float2*)&Cbf[idx] = make_float2(v0, v1);
                    } else {
                        __half2 h, l; split2(v0, v1, h, l);
                        *(__half2*)&Cbh[idx] = h;
                        *(__half2*)&Cbl[idx] = l;
                    }
                }
            }
    } else {
        // bias+gelu, transposed split store: bodyT[b][n][t]
        __syncthreads();
        float* st = (float*)smc;                    // 128 rows x 128 cols, stride 132
        #pragma unroll
        for (int mt = 0; mt < 4; mt++)
            #pragma unroll
            for (int nt = 0; nt < 4; nt++) {
                const int n = warp_n*32 + nt*8 + c0;
                const float2 bv = *(const float2*)&bias[n0 + n];
                #pragma unroll
                for (int hh = 0; hh < 2; hh++) {
                    const int m = warp_m*64 + mt*16 + r0 + hh*8;
                    st[m*132 + n]     = gelu_f(acc[mt][nt][hh*2]   + bv.x);
                    st[m*132 + n + 1] = gelu_f(acc[mt][nt][hh*2+1] + bv.y);
                }
            }
        __syncthreads();
        const int b  = (int)(m0 >> 11);
        const int t0 = (int)(m0 & 2047);
        for (int e = tid; e < 128 * 64; e += NTHREADS) {
            const int n  = e >> 6;
            const int tp = (e & 63) * 2;
            const float v0 = st[tp*132 + n], v1 = st[(tp+1)*132 + n];
            __half2 h, l; split2(v0, v1, h, l);
            const ll idx = ((ll)b * DD + n0 + n) * TT + t0 + tp;
            *(__half2*)&Ch[idx] = h;
            *(__half2*)&Cl[idx] = l;
        }
    }
}

// ---------------- weight prep (transpose + split) --------------------------------
__device__ __forceinline__ void wtile(const float* src, __half* dh, __half* dl,
                                      int R, int Cc, int bx, int by)
{
    __shared__ float t[32][33];
    int x = bx * 32 + threadIdx.x;
    int y = by * 32 + threadIdx.y;
    #pragma unroll
    for (int j = 0; j < 32; j += 8) t[threadIdx.y + j][threadIdx.x] = src[(ll)(y + j) * Cc + x];
    __syncthreads();
    x = by * 32 + threadIdx.x;
    y = bx * 32 + threadIdx.y;
    #pragma unroll
    for (int j = 0; j < 32; j += 8) {
        float v = t[threadIdx.x][threadIdx.y + j];
        __half h = __float2half_rn(v);
        ll idx = (ll)(y + j) * R + x;
        dh[idx] = h;
        dl[idx] = __float2half_rn(v - __half2float(h));
    }
}
__global__ void __launch_bounds__(256)
wprep1(const float* __restrict__ s0, const float* __restrict__ s1)
{
    const int b = blockIdx.x;
    const int w = b >> 8, tt = b & 255;
    wtile(w ? s1 : s0, w ? g_WrTh : g_WlTh, w ? g_WrTl : g_WlTl,
          DD, DD, tt & 15, tt >> 4);
}
__global__ void __launch_bounds__(256)
wprep2(const float* __restrict__ s2, const float* __restrict__ s3,
       const float* __restrict__ s4, const float* __restrict__ s5,
       const float* __restrict__ s6)
{
    const int b = blockIdx.x;
    if (b < 768) {
        const int w = b >> 8, tt = b & 255;
        const float* src = w == 0 ? s2 : (w == 1 ? s3 : s4);
        __half* dh = w == 0 ? g_WbTh : (w == 1 ? g_WoTh : g_W1Th);
        __half* dl = w == 0 ? g_WbTl : (w == 1 ? g_WoTl : g_W1Tl);
        wtile(src, dh, dl, DD, DD, tt & 15, tt >> 4);
    } else if (b < 1536) {
        const int tt = b - 768;
        wtile(s5, g_W2Th, g_W2Tl, DD, DMID, tt % 48, tt / 48);
    } else {
        const int tt = b - 1536;
        wtile(s6, g_W3Th, g_W3Tl, DMID, DD, tt % 16, tt / 16);
    }
}

// ---------------- softmax rows of 2048, split-fp16 in/out ------------------------
__global__ void __launch_bounds__(256)
softmax2048s(__half* __restrict__ Sh, __half* __restrict__ Sl)
{
    __shared__ float sh[8];
    const ll base = (ll)blockIdx.x * TT;
    const int tid = threadIdx.x, lane = tid & 31, warp = tid >> 5;
    float x[8];
    {
        uint4 hv = *(const uint4*)(Sh + base + tid * 8);
        uint4 lv = *(const uint4*)(Sl + base + tid * 8);
        const uint32_t hr[4] = {hv.x, hv.y, hv.z, hv.w};
        const uint32_t lr[4] = {lv.x, lv.y, lv.z, lv.w};
        #pragma unroll
        for (int i = 0; i < 4; i++) {
            float2 h2 = __half22float2(*(const __half2*)&hr[i]);
            float2 l2 = __half22float2(*(const __half2*)&lr[i]);
            x[i*2]   = h2.x + l2.x;
            x[i*2+1] = h2.y + l2.y;
        }
    }
    float m = x[0];
    #pragma unroll
    for (int i = 1; i < 8; i++) m = fmaxf(m, x[i]);
    #pragma unroll
    for (int o = 16; o > 0; o >>= 1) m = fmaxf(m, __shfl_xor_sync(0xffffffffu, m, o));
    if (lane == 0) sh[warp] = m;
    __syncthreads();
    if (tid == 0) { float mm = sh[0]; for (int w = 1; w < 8; w++) mm = fmaxf(mm, sh[w]); sh[0] = mm; }
    __syncthreads();
    const float rmax = sh[0];
    __syncthreads();
    float e[8], s = 0.0f;
    #pragma unroll
    for (int i = 0; i < 8; i++) { e[i] = __expf(x[i] - rmax); s += e[i]; }
    #pragma unroll
    for (int o = 16; o > 0; o >>= 1) s += __shfl_xor_sync(0xffffffffu, s, o);
    if (lane == 0) sh[warp] = s;
    __syncthreads();
    if (tid == 0) { float ss = 0; for (int w = 0; w < 8; w++) ss += sh[w]; sh[0] = ss; }
    __syncthreads();
    const float inv = 1.0f / sh[0];
    #pragma unroll
    for (int i = 0; i < 4; i++) {
        __half2 h, l;
        split2(e[i*2] * inv, e[i*2+1] * inv, h, l);
        *(__half2*)&Sh[base + tid*8 + i*2] = h;
        *(__half2*)&Sl[base + tid*8 + i*2] = l;
    }
}

// ---------------- layernorm rows of 512 -> fp32 + split --------------------------
__global__ void __launch_bounds__(128)
layernorm512s(const float* __restrict__ X, float* __restrict__ Y,
              __half* __restrict__ Yh, __half* __restrict__ Yl,
              const float* __restrict__ g, const float* __restrict__ b)
{
    __shared__ float shs[4], shq[4];
    const ll base = (ll)blockIdx.x * DD;
    const float* x = X + base;
    const int tid = threadIdx.x, lane = tid & 31, warp = tid >> 5;
    float4 v = *(const float4*)(x + tid * 4);
    float s = v.x + v.y + v.z + v.w;
    float q = v.x*v.x + v.y*v.y + v.z*v.z + v.w*v.w;
    #pragma unroll
    for (int o = 16; o > 0; o >>= 1) {
        s += __shfl_xor_sync(0xffffffffu, s, o);
        q += __shfl_xor_sync(0xffffffffu, q, o);
    }
    if (lane == 0) { shs[warp] = s; shq[warp] = q; }
    __syncthreads();
    if (tid == 0) { shs[0] = shs[0]+shs[1]+shs[2]+shs[3]; shq[0] = shq[0]+shq[1]+shq[2]+shq[3]; }
    __syncthreads();
    const float mu  = shs[0] * (1.0f / DD);
    const float var = shq[0] * (1.0f / DD) - mu * mu;
    const float r = rsqrtf(var + 1e-5f);
    float4 gg = *(const float4*)(g + tid * 4);
    float4 bb = *(const float4*)(b + tid * 4);
    float4 o;
    o.x = (v.x - mu) * r * gg.x + bb.x;
    o.y = (v.y - mu) * r * gg.y + bb.y;
    o.z = (v.z - mu) * r * gg.z + bb.z;
    o.w = (v.w - mu) * r * gg.w + bb.w;
    *(float4*)(Y + base + tid * 4) = o;
    __half2 h0, l0, h1, l1;
    split2(o.x, o.y, h0, l0);
    split2(o.z, o.w, h1, l1);
    *(__half2*)&Yh[base + tid*4]     = h0;
    *(__half2*)&Yh[base + tid*4 + 2] = h1;
    *(__half2*)&Yl[base + tid*4]     = l0;
    *(__half2*)&Yl[base + tid*4 + 2] = l1;
}

// ---------------- launch ----------------------------------------------------------
extern "C" void kernel_launch(void* const* d_in, const int* in_sizes, int n_in,
                              void* d_out, int out_size)
{
    const float* left  = (const float*)d_in[0];
    const float* right = (const float*)d_in[1];
    const float* body  = (const float*)d_in[2];
    const float* Wl = (const float*)d_in[3];  const float* bl = (const float*)d_in[4];
    const float* Wr = (const float*)d_in[5];  const float* br = (const float*)d_in[6];
    const float* Wb = (const float*)d_in[7];  const float* bbv = (const float*)d_in[8];
    const float* Wo = (const float*)d_in[9];  const float* bo = (const float*)d_in[10];
    const float* ln_g = (const float*)d_in[11]; const float* ln_b = (const float*)d_in[12];
    const float* W1 = (const float*)d_in[13]; const float* b1 = (const float*)d_in[14];
    const float* lg2 = (const float*)d_in[15]; const float* lb2 = (const float*)d_in[16];
    const float* W2 = (const float*)d_in[17]; const float* b2 = (const float*)d_in[18];
    const float* W3 = (const float*)d_in[19]; const float* b3 = (const float*)d_in[20];
    float* out = (float*)d_out;

    float *t2, *ln1;
    __half *Sh, *Sl, *loh, *lol, *roh, *rol, *bth, *btl;
    __half *t1h, *t1l, *l1h, *l1l, *l2h, *l2l, *mh, *ml;
    __half *WlTh,*WlTl,*WrTh,*WrTl,*WbTh,*WbTl,*WoTh,*WoTl,*W1Th,*W1Tl,*W2Th,*W2Tl,*W3Th,*W3Tl;
    cudaGetSymbolAddress((void**)&Sh,  g_Sh);  cudaGetSymbolAddress((void**)&Sl,  g_Sl);
    cudaGetSymbolAddress((void**)&loh, g_loh); cudaGetSymbolAddress((void**)&lol, g_lol);
    cudaGetSymbolAddress((void**)&roh, g_roh); cudaGetSymbolAddress((void**)&rol, g_rol);
    cudaGetSymbolAddress((void**)&bth, g_bth); cudaGetSymbolAddress((void**)&btl, g_btl);
    cudaGetSymbolAddress((void**)&t1h, g_t1h); cudaGetSymbolAddress((void**)&t1l, g_t1l);
    cudaGetSymbolAddress((void**)&t2,  g_t2);  cudaGetSymbolAddress((void**)&ln1, g_ln1);
    cudaGetSymbolAddress((void**)&l1h, g_l1h); cudaGetSymbolAddress((void**)&l1l, g_l1l);
    cudaGetSymbolAddress((void**)&l2h, g_l2h); cudaGetSymbolAddress((void**)&l2l, g_l2l);
    cudaGetSymbolAddress((void**)&mh,  g_mh);  cudaGetSymbolAddress((void**)&ml,  g_ml);
    cudaGetSymbolAddress((void**)&WlTh,g_WlTh);cudaGetSymbolAddress((void**)&WlTl,g_WlTl);
    cudaGetSymbolAddress((void**)&WrTh,g_WrTh);cudaGetSymbolAddress((void**)&WrTl,g_WrTl);
    cudaGetSymbolAddress((void**)&WbTh,g_WbTh);cudaGetSymbolAddress((void**)&WbTl,g_WbTl);
    cudaGetSymbolAddress((void**)&WoTh,g_WoTh);cudaGetSymbolAddress((void**)&WoTl,g_WoTl);
    cudaGetSymbolAddress((void**)&W1Th,g_W1Th);cudaGetSymbolAddress((void**)&W1Tl,g_W1Tl);
    cudaGetSymbolAddress((void**)&W2Th,g_W2Th);cudaGetSymbolAddress((void**)&W2Tl,g_W2Tl);
    cudaGetSymbolAddress((void**)&W3Th,g_W3Th);cudaGetSymbolAddress((void**)&W3Tl,g_W3Tl);

    cudaFuncSetAttribute(gemm_mma<2,1,1,2>, cudaFuncAttributeMaxDynamicSharedMemorySize, SMEM_BYTES);
    cudaFuncSetAttribute(gemm_mma<4,1,1,2>, cudaFuncAttributeMaxDynamicSharedMemorySize, SMEM_BYTES);
    cudaFuncSetAttribute(gemm_mma<0,1,0,3>, cudaFuncAttributeMaxDynamicSharedMemorySize, SMEM_BYTES);
    cudaFuncSetAttribute(gemm_mma<1,0,0,2>, cudaFuncAttributeMaxDynamicSharedMemorySize, SMEM_BYTES);
    cudaFuncSetAttribute(gemm_mma<3,0,0,2>, cudaFuncAttributeMaxDynamicSharedMemorySize, SMEM_BYTES);
    cudaFuncSetAttribute(gemm_mma<2,1,0,2>, cudaFuncAttributeMaxDynamicSharedMemorySize, SMEM_BYTES);

    const ll sTD = (ll)TT * DD;
    const ll sTT = (ll)TT * TT;
    dim3 tb(32, 8);

    // idx 0: Wl, Wr prep only
    wprep1<<<512, tb>>>(Wl, Wr);
    // idx 1-2: left/right projections (A = fp32 embeds, split in-kernel; 2-term)
    gemm_mma<2,1,1,2><<<dim3(4,128,1), NTHREADS, SMEM_BYTES>>>(nullptr, nullptr, left,
        WlTh, WlTl, bl, nullptr, nullptr, loh, lol, DD, DD, 0, 0, 0);
    gemm_mma<2,1,1,2><<<dim3(4,128,1), NTHREADS, SMEM_BYTES>>>(nullptr, nullptr, right,
        WrTh, WrTl, br, nullptr, nullptr, roh, rol, DD, DD, 0, 0, 0);
    // idx 3: attention scores (3-term)  <-- ncu profiles this launch
    gemm_mma<0,1,0,3><<<dim3(16,16,BB), NTHREADS, SMEM_BYTES>>>(roh, rol, nullptr,
        loh, lol, nullptr, nullptr, nullptr, Sh, Sl, DD, TT, sTD, sTD, sTT);
    // idx 4-5: remaining weight prep + body projection (2-term, transposed out)
    wprep2<<<2304, tb>>>(Wb, Wo, W1, W2, W3);
    gemm_mma<4,1,1,2><<<dim3(4,128,1), NTHREADS, SMEM_BYTES>>>(nullptr, nullptr, body,
        WbTh, WbTl, bbv, nullptr, nullptr, bth, btl, DD, DD, 0, 0, 0);
    // softmax + fuse (3-term)
    softmax2048s<<<BT, 256>>>(Sh, Sl);
    gemm_mma<0,1,0,3><<<dim3(4,16,BB), NTHREADS, SMEM_BYTES>>>(Sh, Sl, nullptr,
        bth, btl, nullptr, nullptr, nullptr, t1h, t1l, TT, DD, sTT, sTD, sTD);
    // output projection + LN (2-term)
    gemm_mma<1,0,0,2><<<dim3(4,128,1), NTHREADS, SMEM_BYTES>>>(t1h, t1l, nullptr,
        WoTh, WoTl, bo, nullptr, t2, nullptr, nullptr, DD, DD, 0, 0, 0);
    layernorm512s<<<BT, 128>>>(t2, ln1, l1h, l1l, ln_g, ln_b);
    // inverted residual (2-term)
    gemm_mma<3,0,0,2><<<dim3(4,128,1), NTHREADS, SMEM_BYTES>>>(l1h, l1l, nullptr,
        W1Th, W1Tl, b1, ln1, t2, nullptr, nullptr, DD, DD, 0, 0, 0);
    layernorm512s<<<BT, 128>>>(t2, ln1, l2h, l2l, lg2, lb2);
    gemm_mma<2,1,0,2><<<dim3(12,128,1), NTHREADS, SMEM_BYTES>>>(l2h, l2l, nullptr,
        W2Th, W2Tl, b2, nullptr, nullptr, mh, ml, DD, DMID, 0, 0, 0);
    gemm_mma<1,0,0,2><<<dim3(4,128,1), NTHREADS, SMEM_BYTES>>>(mh, ml, nullptr,
        W3Th, W3Tl, b3, nullptr, out, nullptr, nullptr, DMID, DD, 0, 0, 0);
}

// round 13
// speedup vs baseline: 3.6221x; 1.0723x over previous
#include <cuda_runtime.h>
#include <cuda_fp16.h>
#include <cstdint>
#include <math.h>

#define BB   8
#define TT   2048
#define DD   512
#define BT   (BB*TT)
#define DMID (3*DD)
typedef long long ll;

// ---------------- scratch -------------------------------------------------------
__device__ __align__(16) __half g_Sh[(ll)BB*TT*TT];
__device__ __align__(16) __half g_Sl[(ll)BB*TT*TT];
__device__ __align__(16) __half g_loh[BT*DD], g_lol[BT*DD];
__device__ __align__(16) __half g_roh[BT*DD], g_rol[BT*DD];
__device__ __align__(16) __half g_bth[BT*DD], g_btl[BT*DD];
__device__ __align__(16) __half g_t1h[BT*DD], g_t1l[BT*DD];
__device__ __align__(16) float g_t2 [BT*DD];
__device__ __align__(16) float g_ln1[BT*DD];
__device__ __align__(16) __half g_l1h[BT*DD], g_l1l[BT*DD];
__device__ __align__(16) __half g_l2h[BT*DD], g_l2l[BT*DD];
__device__ __align__(16) __half g_mh[BT*DMID], g_ml[BT*DMID];
__device__ __align__(16) __half g_WlTh[DD*DD],  g_WlTl[DD*DD];
__device__ __align__(16) __half g_WrTh[DD*DD],  g_WrTl[DD*DD];
__device__ __align__(16) __half g_WbTh[DD*DD],  g_WbTl[DD*DD];
__device__ __align__(16) __half g_WoTh[DD*DD],  g_WoTl[DD*DD];
__device__ __align__(16) __half g_W1Th[DD*DD],  g_W1Tl[DD*DD];
__device__ __align__(16) __half g_W2Th[DMID*DD],g_W2Tl[DMID*DD];
__device__ __align__(16) __half g_W3Th[DD*DMID],g_W3Tl[DD*DMID];

// ---------------- helpers -------------------------------------------------------
__device__ __forceinline__ float gelu_f(float x) {
    return 0.5f * x * (1.0f + erff(x * 0.7071067811865476f));
}
__device__ __forceinline__ uint32_t smem_u32(const void* p) {
    uint32_t a;
    asm("{ .reg .u64 t; cvta.to.shared.u64 t, %1; cvt.u32.u64 %0, t; }" : "=r"(a) : "l"(p));
    return a;
}
__device__ __forceinline__ void cpa16(uint32_t dst, const void* src) {
    asm volatile("cp.async.cg.shared.global [%0], [%1], 16;" :: "r"(dst), "l"(src));
}
__device__ __forceinline__ void ldsm4(uint32_t* r, uint32_t a) {
    asm volatile("ldmatrix.sync.aligned.m8n8.x4.shared.b16 {%0,%1,%2,%3}, [%4];"
                 : "=r"(r[0]), "=r"(r[1]), "=r"(r[2]), "=r"(r[3]) : "r"(a));
}
__device__ __forceinline__ void mma16816(float* d, const uint32_t* a, const uint32_t* b) {
    asm volatile("mma.sync.aligned.m16n8k16.row.col.f32.f16.f16.f32 "
                 "{%0,%1,%2,%3}, {%4,%5,%6,%7}, {%8,%9}, {%0,%1,%2,%3};"
                 : "+f"(d[0]), "+f"(d[1]), "+f"(d[2]), "+f"(d[3])
                 : "r"(a[0]), "r"(a[1]), "r"(a[2]), "r"(a[3]), "r"(b[0]), "r"(b[1]));
}
__device__ __forceinline__ void split2(float v0, float v1, __half2& h, __half2& l) {
    h = __floats2half2_rn(v0, v1);
    float2 f = __half22float2(h);
    l = __floats2half2_rn(v0 - f.x, v1 - f.y);
}
__device__ __forceinline__ uint32_t swz_off(int row, int ch) {
    return (uint32_t)(row * 64 + ((ch ^ ((row >> 1) & 3)) << 4));
}

#define SMEM_BYTES 98304
#define NTHREADS 256

// --- fills ------------------------------------------------------------------------
template<int TERMS>
__device__ __forceinline__ void fill_B(uint32_t sb,
    const __half* B1, const __half* B2, ll n0, int k0, int K, int tid)
{
    #pragma unroll
    for (int j = 0; j < 2; j++) {
        const int id = j*256 + tid;
        const int row = id >> 2, ch = id & 3;
        const uint32_t so = swz_off(row, ch);
        const ll bo = (n0 + row) * (ll)K + k0 + ch * 8;
        cpa16(sb + 16384u + so, B1 + bo);
        if (TERMS == 3) cpa16(sb + 24576u + so, B2 + bo);
    }
}
__device__ __forceinline__ void fill_A_hf(uint32_t sb,
    const __half* A1, const __half* A2, ll m0, int k0, int K, int tid)
{
    #pragma unroll
    for (int j = 0; j < 2; j++) {
        const int id = j*256 + tid;
        const int row = id >> 2, ch = id & 3;
        const uint32_t so = swz_off(row, ch);
        const ll ao = (m0 + row) * (ll)K + k0 + ch * 8;
        cpa16(sb + so, A1 + ao);
        cpa16(sb + 8192u + so, A2 + ao);
    }
}
__device__ __forceinline__ void ldg_A_f32(float4* r, const float* Af,
                                          ll m0, int k0, int K, int tid)
{
    #pragma unroll
    for (int j = 0; j < 2; j++) {
        const int id = j*256 + tid;
        const int row = id >> 2, ch = id & 3;
        const float* s = Af + (m0 + row) * (ll)K + k0 + ch * 8;
        r[j*2]   = *(const float4*)s;
        r[j*2+1] = *(const float4*)(s + 4);
    }
}
__device__ __forceinline__ void sts_A_split(char* sp, const float4* r, int tid)
{
    #pragma unroll
    for (int j = 0; j < 2; j++) {
        const int id = j*256 + tid;
        const int row = id >> 2, ch = id & 3;
        const uint32_t so = swz_off(row, ch);
        __half2 h0,l0,h1,l1,h2,l2,h3,l3;
        split2(r[j*2].x,   r[j*2].y,   h0, l0);
        split2(r[j*2].z,   r[j*2].w,   h1, l1);
        split2(r[j*2+1].x, r[j*2+1].y, h2, l2);
        split2(r[j*2+1].z, r[j*2+1].w, h3, l3);
        *(uint4*)(sp + so) = make_uint4(*(uint32_t*)&h0, *(uint32_t*)&h1,
                                        *(uint32_t*)&h2, *(uint32_t*)&h3);
        *(uint4*)(sp + 8192 + so) = make_uint4(*(uint32_t*)&l0, *(uint32_t*)&l1,
                                               *(uint32_t*)&l2, *(uint32_t*)&l3);
    }
}

// ---------------- shared GEMM mainloop: 128x128 tile, split-fp16 -----------------
// 8 warps 2(m) x 4(n), warp tile 64x32; interleaved fills; NST stages
template<int ASRC, int TERMS>
__device__ __forceinline__ void gemm_core(float (&acc)[4][4][4],
    const __half* A1, const __half* A2, const float* Af,
    const __half* B1, const __half* B2,
    ll m0, ll n0, int K, char* smc, int tid, int lane, int warp_m, int warp_n)
{
    const uint32_t sbase = smem_u32(smc);
    constexpr uint32_t STGT = (TERMS == 3) ? 32768u : 24576u;
    constexpr int NST = (TERMS == 3) ? 3 : 4;
    constexpr int PFD = NST - 1;
    const int NC = K >> 5;

    // prologue: fill PFD stages
    for (int s = 0; s < PFD; s++) {
        if (ASRC) {
            float4 r[4];
            ldg_A_f32(r, Af, m0, s*32, K, tid);
            sts_A_split(smc + s*STGT, r, tid);
        } else {
            fill_A_hf(sbase + (uint32_t)s*STGT, A1, A2, m0, s*32, K, tid);
        }
        fill_B<TERMS>(sbase + (uint32_t)s*STGT, B1, B2, n0, s*32, K, tid);
        asm volatile("cp.async.commit_group;" ::: "memory");
    }

    const int row_a = warp_m*64 + (lane & 15);
    const uint32_t a_row = (uint32_t)(row_a * 64);
    const int swa = ((lane & 15) >> 1) & 3;
    const int cha = lane >> 4;
    const int row_b = warp_n*32 + ((lane >> 4) << 3) + (lane & 7);
    const uint32_t b_row = (uint32_t)(row_b * 64);
    const int swb = (row_b >> 1) & 3;
    const int chb = (lane >> 3) & 1;

    for (int c = 0; c < NC; c++) {
        asm volatile("cp.async.wait_group %0;" :: "n"(NST - 2) : "memory");
        __syncthreads();
        const uint32_t sb = sbase + (uint32_t)(c % NST) * STGT;
        const uint32_t spfu = sbase + (uint32_t)((c + PFD) % NST) * STGT;
        char* spf = smc + ((c + PFD) % NST) * STGT;
        const bool pf = (c + PFD < NC);
        const int kpf = (c + PFD) * 32;
        float4 r[4];

        uint32_t afh[4][4], afl[4][4], bq[2][4];
        // ===== ks = 0: interleave fills between terms =====
        {
            const uint32_t ca = (uint32_t)((cha ^ swa) << 4);
            const uint32_t cb = (uint32_t)((chb ^ swb) << 4);
            #pragma unroll
            for (int mt = 0; mt < 4; mt++) ldsm4(afh[mt], sb + a_row + mt*1024u + ca);
            #pragma unroll
            for (int h = 0; h < 2; h++) ldsm4(bq[h], sb + 16384u + b_row + h*1024u + cb);
            #pragma unroll
            for (int mt = 0; mt < 4; mt++)
                #pragma unroll
                for (int nt = 0; nt < 4; nt++)
                    mma16816(acc[mt][nt], afh[mt], &bq[nt >> 1][(nt & 1) * 2]);
            // A prefetch for stage c+PFD
            if (pf) {
                if (ASRC) ldg_A_f32(r, Af, m0, kpf, K, tid);
                else      fill_A_hf(spfu, A1, A2, m0, kpf, K, tid);
            }
            #pragma unroll
            for (int mt = 0; mt < 4; mt++) ldsm4(afl[mt], sb + 8192u + a_row + mt*1024u + ca);
            #pragma unroll
            for (int mt = 0; mt < 4; mt++)
                #pragma unroll
                for (int nt = 0; nt < 4; nt++)
                    mma16816(acc[mt][nt], afl[mt], &bq[nt >> 1][(nt & 1) * 2]);
            // B prefetch for stage c+PFD
            if (pf) fill_B<TERMS>(spfu, B1, B2, n0, kpf, K, tid);
            if (TERMS == 3) {
                #pragma unroll
                for (int h = 0; h < 2; h++)
                    ldsm4(bq[h], sb + 24576u + b_row + h*1024u + cb);
                #pragma unroll
                for (int mt = 0; mt < 4; mt++)
                    #pragma unroll
                    for (int nt = 0; nt < 4; nt++)
                        mma16816(acc[mt][nt], afh[mt], &bq[nt >> 1][(nt & 1) * 2]);
            }
        }
        asm volatile("cp.async.commit_group;" ::: "memory");
        // ===== ks = 1: pure compute =====
        {
            const uint32_t ca = (uint32_t)(((2 + cha) ^ swa) << 4);
            const uint32_t cb = (uint32_t)(((2 + chb) ^ swb) << 4);
            #pragma unroll
            for (int mt = 0; mt < 4; mt++) ldsm4(afh[mt], sb + a_row + mt*1024u + ca);
            #pragma unroll
            for (int h = 0; h < 2; h++) ldsm4(bq[h], sb + 16384u + b_row + h*1024u + cb);
            #pragma unroll
            for (int mt = 0; mt < 4; mt++)
                #pragma unroll
                for (int nt = 0; nt < 4; nt++)
                    mma16816(acc[mt][nt], afh[mt], &bq[nt >> 1][(nt & 1) * 2]);
            #pragma unroll
            for (int mt = 0; mt < 4; mt++) ldsm4(afl[mt], sb + 8192u + a_row + mt*1024u + ca);
            #pragma unroll
            for (int mt = 0; mt < 4; mt++)
                #pragma unroll
                for (int nt = 0; nt < 4; nt++)
                    mma16816(acc[mt][nt], afl[mt], &bq[nt >> 1][(nt & 1) * 2]);
            if (TERMS == 3) {
                #pragma unroll
                for (int h = 0; h < 2; h++)
                    ldsm4(bq[h], sb + 24576u + b_row + h*1024u + cb);
                #pragma unroll
                for (int mt = 0; mt < 4; mt++)
                    #pragma unroll
                    for (int nt = 0; nt < 4; nt++)
                        mma16816(acc[mt][nt], afh[mt], &bq[nt >> 1][(nt & 1) * 2]);
            }
        }
        if (ASRC && pf) sts_A_split(spf, r, tid);
    }
}

// ---------------- generic GEMM kernel ---------------------------------------------
// EPI: 0 none, 1 +bias, 2 gelu(+bias), 3 gelu(+bias)+res
// OUT: 0 fp32, 1 split-fp16 ; ASRC: 0 pre-split fp16, 1 fp32 (split in-kernel)
template<int EPI, int OUT, int ASRC, int TERMS>
__global__ void __launch_bounds__(NTHREADS, 2)
gemm_mma(const __half* __restrict__ Ah, const __half* __restrict__ Al,
         const float* __restrict__ Af,
         const __half* __restrict__ Bh, const __half* __restrict__ Bl,
         const float* __restrict__ bias, const float* __restrict__ res,
         float* __restrict__ Cf, __half* __restrict__ Ch, __half* __restrict__ Cl,
         int K, int N, ll sA, ll sB, ll sC)
{
    extern __shared__ char smc[];
    const int tid = threadIdx.x, lane = tid & 31, wid = tid >> 5;
    const int warp_m = wid & 1, warp_n = wid >> 1;
    const ll m0 = (ll)blockIdx.y * 128;
    const ll n0 = (ll)blockIdx.x * 128;
    const ll zb = blockIdx.z;

    float acc[4][4][4];
    #pragma unroll
    for (int i = 0; i < 4; i++)
        #pragma unroll
        for (int j = 0; j < 4; j++)
            #pragma unroll
            for (int q = 0; q < 4; q++) acc[i][j][q] = 0.0f;

    gemm_core<ASRC, TERMS>(acc, Ah + zb * sA, Al + zb * sA, Af,
                           Bh + zb * sB, Bl + zb * sB,
                           m0, n0, K, smc, tid, lane, warp_m, warp_n);

    const int r0 = lane >> 2, c0 = (lane & 3) * 2;
    float*  Cbf = Cf + zb * sC;
    __half* Cbh = Ch + zb * sC;
    __half* Cbl = Cl + zb * sC;
    const float* Rb = res + zb * sC;
    #pragma unroll
    for (int mt = 0; mt < 4; mt++)
        #pragma unroll
        for (int nt = 0; nt < 4; nt++) {
            const int n = warp_n*32 + nt*8 + c0;
            float2 bv = make_float2(0.f, 0.f);
            if (EPI >= 1) bv = *(const float2*)&bias[n0 + n];
            #pragma unroll
            for (int hh = 0; hh < 2; hh++) {
                const int m = warp_m*64 + mt*16 + r0 + hh*8;
                float v0 = acc[mt][nt][hh*2], v1 = acc[mt][nt][hh*2+1];
                if (EPI >= 1) { v0 += bv.x; v1 += bv.y; }
                if (EPI >= 2) { v0 = gelu_f(v0); v1 = gelu_f(v1); }
                const ll idx = (m0 + m) * (ll)N + n0 + n;
                if (EPI == 3) {
                    float2 rv = *(const float2*)&Rb[idx];
                    v0 += rv.x; v1 += rv.y;
                }
                if (OUT == 0) {
                    *(float2*)&Cbf[idx] = make_float2(v0, v1);
                } else {
                    __half2 h, l; split2(v0, v1, h, l);
                    *(__half2*)&Cbh[idx] = h;
                    *(__half2*)&Cbl[idx] = l;
                }
            }
        }
}

// ---------------- merged projections kernel (z = 0:left 1:right 2:body) -----------
struct P3 { const float* A; const __half* Wh; const __half* Wl;
            const float* bias; __half* Ch; __half* Cl; };

__global__ void __launch_bounds__(NTHREADS, 2)
proj3(P3 p0, P3 p1, P3 p2)
{
    extern __shared__ char smc[];
    const int tid = threadIdx.x, lane = tid & 31, wid = tid >> 5;
    const int warp_m = wid & 1, warp_n = wid >> 1;
    const int z = blockIdx.z;
    const P3 p = (z == 0) ? p0 : (z == 1) ? p1 : p2;
    const ll m0 = (ll)blockIdx.y * 128;
    const ll n0 = (ll)blockIdx.x * 128;

    float acc[4][4][4];
    #pragma unroll
    for (int i = 0; i < 4; i++)
        #pragma unroll
        for (int j = 0; j < 4; j++)
            #pragma unroll
            for (int q = 0; q < 4; q++) acc[i][j][q] = 0.0f;

    gemm_core<1, 2>(acc, nullptr, nullptr, p.A, p.Wh, p.Wl,
                    m0, n0, DD, smc, tid, lane, warp_m, warp_n);

    const int r0 = lane >> 2, c0 = (lane & 3) * 2;
    if (z < 2) {
        #pragma unroll
        for (int mt = 0; mt < 4; mt++)
            #pragma unroll
            for (int nt = 0; nt < 4; nt++) {
                const int n = warp_n*32 + nt*8 + c0;
                const float2 bv = *(const float2*)&p.bias[n0 + n];
                #pragma unroll
                for (int hh = 0; hh < 2; hh++) {
                    const int m = warp_m*64 + mt*16 + r0 + hh*8;
                    float v0 = gelu_f(acc[mt][nt][hh*2]   + bv.x);
                    float v1 = gelu_f(acc[mt][nt][hh*2+1] + bv.y);
                    const ll idx = (m0 + m) * (ll)DD + n0 + n;
                    __half2 h, l; split2(v0, v1, h, l);
                    *(__half2*)&p.Ch[idx] = h;
                    *(__half2*)&p.Cl[idx] = l;
                }
            }
    } else {
        // transposed split store: bodyT[b][n][t]
        __syncthreads();
        float* st = (float*)smc;                    // 128 x 128, stride 132
        #pragma unroll
        for (int mt = 0; mt < 4; mt++)
            #pragma unroll
            for (int nt = 0; nt < 4; nt++) {
                const int n = warp_n*32 + nt*8 + c0;
                const float2 bv = *(const float2*)&p.bias[n0 + n];
                #pragma unroll
                for (int hh = 0; hh < 2; hh++) {
                    const int m = warp_m*64 + mt*16 + r0 + hh*8;
                    st[m*132 + n]     = gelu_f(acc[mt][nt][hh*2]   + bv.x);
                    st[m*132 + n + 1] = gelu_f(acc[mt][nt][hh*2+1] + bv.y);
                }
            }
        __syncthreads();
        const int b  = (int)(m0 >> 11);
        const int t0 = (int)(m0 & 2047);
        for (int e = tid; e < 128 * 64; e += NTHREADS) {
            const int n  = e >> 6;
            const int tp = (e & 63) * 2;
            const float v0 = st[tp*132 + n], v1 = st[(tp+1)*132 + n];
            __half2 h, l; split2(v0, v1, h, l);
            const ll idx = ((ll)b * DD + n0 + n) * TT + t0 + tp;
            *(__half2*)&p.Ch[idx] = h;
            *(__half2*)&p.Cl[idx] = l;
        }
    }
}

// ---------------- weight prep (transpose + split) --------------------------------
__device__ __forceinline__ void wtile(const float* src, __half* dh, __half* dl,
                                      int R, int Cc, int bx, int by)
{
    __shared__ float t[32][33];
    int x = bx * 32 + threadIdx.x;
    int y = by * 32 + threadIdx.y;
    #pragma unroll
    for (int j = 0; j < 32; j += 8) t[threadIdx.y + j][threadIdx.x] = src[(ll)(y + j) * Cc + x];
    __syncthreads();
    x = by * 32 + threadIdx.x;
    y = bx * 32 + threadIdx.y;
    #pragma unroll
    for (int j = 0; j < 32; j += 8) {
        float v = t[threadIdx.x][threadIdx.y + j];
        __half h = __float2half_rn(v);
        ll idx = (ll)(y + j) * R + x;
        dh[idx] = h;
        dl[idx] = __float2half_rn(v - __half2float(h));
    }
}
__global__ void __launch_bounds__(256)
wprep1(const float* __restrict__ s0, const float* __restrict__ s1,
       const float* __restrict__ s2)
{
    const int b = blockIdx.x;
    const int w = b >> 8, tt = b & 255;
    const float* src = w == 0 ? s0 : (w == 1 ? s1 : s2);
    __half* dh = w == 0 ? g_WlTh : (w == 1 ? g_WrTh : g_WbTh);
    __half* dl = w == 0 ? g_WlTl : (w == 1 ? g_WrTl : g_WbTl);
    wtile(src, dh, dl, DD, DD, tt & 15, tt >> 4);
}
__global__ void __launch_bounds__(256)
wprep2(const float* __restrict__ s3, const float* __restrict__ s4,
       const float* __restrict__ s5, const float* __restrict__ s6)
{
    const int b = blockIdx.x;
    if (b < 512) {
        const int w = b >> 8, tt = b & 255;
        wtile(w ? s4 : s3, w ? g_W1Th : g_WoTh, w ? g_W1Tl : g_WoTl,
              DD, DD, tt & 15, tt >> 4);
    } else if (b < 1280) {
        const int tt = b - 512;
        wtile(s5, g_W2Th, g_W2Tl, DD, DMID, tt % 48, tt / 48);
    } else {
        const int tt = b - 1280;
        wtile(s6, g_W3Th, g_W3Tl, DMID, DD, tt % 16, tt / 16);
    }
}

// ---------------- softmax rows of 2048, split-fp16 in/out ------------------------
__global__ void __launch_bounds__(256)
softmax2048s(__half* __restrict__ Sh, __half* __restrict__ Sl)
{
    __shared__ float sh[8];
    const ll base = (ll)blockIdx.x * TT;
    const int tid = threadIdx.x, lane = tid & 31, warp = tid >> 5;
    float x[8];
    {
        uint4 hv = *(const uint4*)(Sh + base + tid * 8);
        uint4 lv = *(const uint4*)(Sl + base + tid * 8);
        const uint32_t hr[4] = {hv.x, hv.y, hv.z, hv.w};
        const uint32_t lr[4] = {lv.x, lv.y, lv.z, lv.w};
        #pragma unroll
        for (int i = 0; i < 4; i++) {
            float2 h2 = __half22float2(*(const __half2*)&hr[i]);
            float2 l2 = __half22float2(*(const __half2*)&lr[i]);
            x[i*2]   = h2.x + l2.x;
            x[i*2+1] = h2.y + l2.y;
        }
    }
    float m = x[0];
    #pragma unroll
    for (int i = 1; i < 8; i++) m = fmaxf(m, x[i]);
    #pragma unroll
    for (int o = 16; o > 0; o >>= 1) m = fmaxf(m, __shfl_xor_sync(0xffffffffu, m, o));
    if (lane == 0) sh[warp] = m;
    __syncthreads();
    if (tid == 0) { float mm = sh[0]; for (int w = 1; w < 8; w++) mm = fmaxf(mm, sh[w]); sh[0] = mm; }
    __syncthreads();
    const float rmax = sh[0];
    __syncthreads();
    float e[8], s = 0.0f;
    #pragma unroll
    for (int i = 0; i < 8; i++) { e[i] = __expf(x[i] - rmax); s += e[i]; }
    #pragma unroll
    for (int o = 16; o > 0; o >>= 1) s += __shfl_xor_sync(0xffffffffu, s, o);
    if (lane == 0) sh[warp] = s;
    __syncthreads();
    if (tid == 0) { float ss = 0; for (int w = 0; w < 8; w++) ss += sh[w]; sh[0] = ss; }
    __syncthreads();
    const float inv = 1.0f / sh[0];
    #pragma unroll
    for (int i = 0; i < 4; i++) {
        __half2 h, l;
        split2(e[i*2] * inv, e[i*2+1] * inv, h, l);
        *(__half2*)&Sh[base + tid*8 + i*2] = h;
        *(__half2*)&Sl[base + tid*8 + i*2] = l;
    }
}

// ---------------- layernorm rows of 512 -> fp32 + split --------------------------
__global__ void __launch_bounds__(128)
layernorm512s(const float* __restrict__ X, float* __restrict__ Y,
              __half* __restrict__ Yh, __half* __restrict__ Yl,
              const float* __restrict__ g, const float* __restrict__ b)
{
    __shared__ float shs[4], shq[4];
    const ll base = (ll)blockIdx.x * DD;
    const float* x = X + base;
    const int tid = threadIdx.x, lane = tid & 31, warp = tid >> 5;
    float4 v = *(const float4*)(x + tid * 4);
    float s = v.x + v.y + v.z + v.w;
    float q = v.x*v.x + v.y*v.y + v.z*v.z + v.w*v.w;
    #pragma unroll
    for (int o = 16; o > 0; o >>= 1) {
        s += __shfl_xor_sync(0xffffffffu, s, o);
        q += __shfl_xor_sync(0xffffffffu, q, o);
    }
    if (lane == 0) { shs[warp] = s; shq[warp] = q; }
    __syncthreads();
    if (tid == 0) { shs[0] = shs[0]+shs[1]+shs[2]+shs[3]; shq[0] = shq[0]+shq[1]+shq[2]+shq[3]; }
    __syncthreads();
    const float mu  = shs[0] * (1.0f / DD);
    const float var = shq[0] * (1.0f / DD) - mu * mu;
    const float r = rsqrtf(var + 1e-5f);
    float4 gg = *(const float4*)(g + tid * 4);
    float4 bb = *(const float4*)(b + tid * 4);
    float4 o;
    o.x = (v.x - mu) * r * gg.x + bb.x;
    o.y = (v.y - mu) * r * gg.y + bb.y;
    o.z = (v.z - mu) * r * gg.z + bb.z;
    o.w = (v.w - mu) * r * gg.w + bb.w;
    *(float4*)(Y + base + tid * 4) = o;
    __half2 h0, l0, h1, l1;
    split2(o.x, o.y, h0, l0);
    split2(o.z, o.w, h1, l1);
    *(__half2*)&Yh[base + tid*4]     = h0;
    *(__half2*)&Yh[base + tid*4 + 2] = h1;
    *(__half2*)&Yl[base + tid*4]     = l0;
    *(__half2*)&Yl[base + tid*4 + 2] = l1;
}

// ---------------- launch ----------------------------------------------------------
extern "C" void kernel_launch(void* const* d_in, const int* in_sizes, int n_in,
                              void* d_out, int out_size)
{
    const float* left  = (const float*)d_in[0];
    const float* right = (const float*)d_in[1];
    const float* body  = (const float*)d_in[2];
    const float* Wl = (const float*)d_in[3];  const float* bl = (const float*)d_in[4];
    const float* Wr = (const float*)d_in[5];  const float* br = (const float*)d_in[6];
    const float* Wb = (const float*)d_in[7];  const float* bbv = (const float*)d_in[8];
    const float* Wo = (const float*)d_in[9];  const float* bo = (const float*)d_in[10];
    const float* ln_g = (const float*)d_in[11]; const float* ln_b = (const float*)d_in[12];
    const float* W1 = (const float*)d_in[13]; const float* b1 = (const float*)d_in[14];
    const float* lg2 = (const float*)d_in[15]; const float* lb2 = (const float*)d_in[16];
    const float* W2 = (const float*)d_in[17]; const float* b2 = (const float*)d_in[18];
    const float* W3 = (const float*)d_in[19]; const float* b3 = (const float*)d_in[20];
    float* out = (float*)d_out;

    float *t2, *ln1;
    __half *Sh, *Sl, *loh, *lol, *roh, *rol, *bth, *btl;
    __half *t1h, *t1l, *l1h, *l1l, *l2h, *l2l, *mh, *ml;
    __half *WlTh,*WlTl,*WrTh,*WrTl,*WbTh,*WbTl,*WoTh,*WoTl,*W1Th,*W1Tl,*W2Th,*W2Tl,*W3Th,*W3Tl;
    cudaGetSymbolAddress((void**)&Sh,  g_Sh);  cudaGetSymbolAddress((void**)&Sl,  g_Sl);
    cudaGetSymbolAddress((void**)&loh, g_loh); cudaGetSymbolAddress((void**)&lol, g_lol);
    cudaGetSymbolAddress((void**)&roh, g_roh); cudaGetSymbolAddress((void**)&rol, g_rol);
    cudaGetSymbolAddress((void**)&bth, g_bth); cudaGetSymbolAddress((void**)&btl, g_btl);
    cudaGetSymbolAddress((void**)&t1h, g_t1h); cudaGetSymbolAddress((void**)&t1l, g_t1l);
    cudaGetSymbolAddress((void**)&t2,  g_t2);  cudaGetSymbolAddress((void**)&ln1, g_ln1);
    cudaGetSymbolAddress((void**)&l1h, g_l1h); cudaGetSymbolAddress((void**)&l1l, g_l1l);
    cudaGetSymbolAddress((void**)&l2h, g_l2h); cudaGetSymbolAddress((void**)&l2l, g_l2l);
    cudaGetSymbolAddress((void**)&mh,  g_mh);  cudaGetSymbolAddress((void**)&ml,  g_ml);
    cudaGetSymbolAddress((void**)&WlTh,g_WlTh);cudaGetSymbolAddress((void**)&WlTl,g_WlTl);
    cudaGetSymbolAddress((void**)&WrTh,g_WrTh);cudaGetSymbolAddress((void**)&WrTl,g_WrTl);
    cudaGetSymbolAddress((void**)&WbTh,g_WbTh);cudaGetSymbolAddress((void**)&WbTl,g_WbTl);
    cudaGetSymbolAddress((void**)&WoTh,g_WoTh);cudaGetSymbolAddress((void**)&WoTl,g_WoTl);
    cudaGetSymbolAddress((void**)&W1Th,g_W1Th);cudaGetSymbolAddress((void**)&W1Tl,g_W1Tl);
    cudaGetSymbolAddress((void**)&W2Th,g_W2Th);cudaGetSymbolAddress((void**)&W2Tl,g_W2Tl);
    cudaGetSymbolAddress((void**)&W3Th,g_W3Th);cudaGetSymbolAddress((void**)&W3Tl,g_W3Tl);

    cudaFuncSetAttribute(proj3,          cudaFuncAttributeMaxDynamicSharedMemorySize, SMEM_BYTES);
    cudaFuncSetAttribute(gemm_mma<0,1,0,3>, cudaFuncAttributeMaxDynamicSharedMemorySize, SMEM_BYTES);
    cudaFuncSetAttribute(gemm_mma<1,0,0,2>, cudaFuncAttributeMaxDynamicSharedMemorySize, SMEM_BYTES);
    cudaFuncSetAttribute(gemm_mma<3,0,0,2>, cudaFuncAttributeMaxDynamicSharedMemorySize, SMEM_BYTES);
    cudaFuncSetAttribute(gemm_mma<2,1,0,2>, cudaFuncAttributeMaxDynamicSharedMemorySize, SMEM_BYTES);

    const ll sTD = (ll)TT * DD;
    const ll sTT = (ll)TT * TT;
    dim3 tb(32, 8);

    P3 p0 = {left,  WlTh, WlTl, bl,  loh, lol};
    P3 p1 = {right, WrTh, WrTl, br,  roh, rol};
    P3 p2 = {body,  WbTh, WbTl, bbv, bth, btl};

    // idx 0: Wl/Wr/Wb prep
    wprep1<<<768, tb>>>(Wl, Wr, Wb);
    // idx 1: merged projections (z = 0,1,2)
    proj3<<<dim3(4, 128, 3), NTHREADS, SMEM_BYTES>>>(p0, p1, p2);
    // idx 2: remaining weight prep
    wprep2<<<2048, tb>>>(Wo, W1, W2, W3);
    // idx 3: attention scores (3-term)  <-- ncu profiles this launch
    gemm_mma<0,1,0,3><<<dim3(16,16,BB), NTHREADS, SMEM_BYTES>>>(roh, rol, nullptr,
        loh, lol, nullptr, nullptr, nullptr, Sh, Sl, DD, TT, sTD, sTD, sTT);
    // softmax + fuse (3-term)
    softmax2048s<<<BT, 256>>>(Sh, Sl);
    gemm_mma<0,1,0,3><<<dim3(4,16,BB), NTHREADS, SMEM_BYTES>>>(Sh, Sl, nullptr,
        bth, btl, nullptr, nullptr, nullptr, t1h, t1l, TT, DD, sTT, sTD, sTD);
    // output projection + LN (2-term)
    gemm_mma<1,0,0,2><<<dim3(4,128,1), NTHREADS, SMEM_BYTES>>>(t1h, t1l, nullptr,
        WoTh, WoTl, bo, nullptr, t2, nullptr, nullptr, DD, DD, 0, 0, 0);
    layernorm512s<<<BT, 128>>>(t2, ln1, l1h, l1l, ln_g, ln_b);
    // inverted residual (2-term)
    gemm_mma<3,0,0,2><<<dim3(4,128,1), NTHREADS, SMEM_BYTES>>>(l1h, l1l, nullptr,
        W1Th, W1Tl, b1, ln1, t2, nullptr, nullptr, DD, DD, 0, 0, 0);
    layernorm512s<<<BT, 128>>>(t2, ln1, l2h, l2l, lg2, lb2);
    gemm_mma<2,1,0,2><<<dim3(12,128,1), NTHREADS, SMEM_BYTES>>>(l2h, l2l, nullptr,
        W2Th, W2Tl, b2, nullptr, nullptr, mh, ml, DD, DMID, 0, 0, 0);
    gemm_mma<1,0,0,2><<<dim3(4,128,1), NTHREADS, SMEM_BYTES>>>(mh, ml, nullptr,
        W3Th, W3Tl, b3, nullptr, out, nullptr, nullptr, DMID, DD, 0, 0, 0);
}

// round 14
// speedup vs baseline: 3.6290x; 1.0019x over previous
#include <cuda_runtime.h>
#include <cuda_fp16.h>
#include <cstdint>
#include <math.h>

#define BB   8
#define TT   2048
#define DD   512
#define BT   (BB*TT)
#define DMID (3*DD)
typedef long long ll;

// ---------------- scratch -------------------------------------------------------
__device__ __align__(16) __half g_Sh[(ll)BB*TT*TT];
__device__ __align__(16) __half g_Sl[(ll)BB*TT*TT];
__device__ __align__(16) __half g_loh[BT*DD], g_lol[BT*DD];
__device__ __align__(16) __half g_roh[BT*DD], g_rol[BT*DD];
__device__ __align__(16) __half g_bth[BT*DD], g_btl[BT*DD];
__device__ __align__(16) __half g_t1h[BT*DD], g_t1l[BT*DD];
__device__ __align__(16) float g_t2 [BT*DD];
__device__ __align__(16) float g_ln1[BT*DD];
__device__ __align__(16) __half g_l1h[BT*DD], g_l1l[BT*DD];
__device__ __align__(16) __half g_l2h[BT*DD], g_l2l[BT*DD];
__device__ __align__(16) __half g_mh[BT*DMID], g_ml[BT*DMID];
__device__ __align__(16) __half g_WlTh[DD*DD],  g_WlTl[DD*DD];
__device__ __align__(16) __half g_WrTh[DD*DD],  g_WrTl[DD*DD];
__device__ __align__(16) __half g_WbTh[DD*DD],  g_WbTl[DD*DD];
__device__ __align__(16) __half g_WoTh[DD*DD],  g_WoTl[DD*DD];
__device__ __align__(16) __half g_W1Th[DD*DD],  g_W1Tl[DD*DD];
__device__ __align__(16) __half g_W2Th[DMID*DD],g_W2Tl[DMID*DD];
__device__ __align__(16) __half g_W3Th[DD*DMID],g_W3Tl[DD*DMID];

// ---------------- helpers -------------------------------------------------------
__device__ __forceinline__ float gelu_f(float x) {
    return 0.5f * x * (1.0f + erff(x * 0.7071067811865476f));
}
__device__ __forceinline__ uint32_t smem_u32(const void* p) {
    uint32_t a;
    asm("{ .reg .u64 t; cvta.to.shared.u64 t, %1; cvt.u32.u64 %0, t; }" : "=r"(a) : "l"(p));
    return a;
}
__device__ __forceinline__ void cpa16(uint32_t dst, const void* src) {
    asm volatile("cp.async.cg.shared.global [%0], [%1], 16;" :: "r"(dst), "l"(src));
}
__device__ __forceinline__ void ldsm4(uint32_t* r, uint32_t a) {
    asm volatile("ldmatrix.sync.aligned.m8n8.x4.shared.b16 {%0,%1,%2,%3}, [%4];"
                 : "=r"(r[0]), "=r"(r[1]), "=r"(r[2]), "=r"(r[3]) : "r"(a));
}
__device__ __forceinline__ void mma16816(float* d, const uint32_t* a, const uint32_t* b) {
    asm volatile("mma.sync.aligned.m16n8k16.row.col.f32.f16.f16.f32 "
                 "{%0,%1,%2,%3}, {%4,%5,%6,%7}, {%8,%9}, {%0,%1,%2,%3};"
                 : "+f"(d[0]), "+f"(d[1]), "+f"(d[2]), "+f"(d[3])
                 : "r"(a[0]), "r"(a[1]), "r"(a[2]), "r"(a[3]), "r"(b[0]), "r"(b[1]));
}
__device__ __forceinline__ void split2(float v0, float v1, __half2& h, __half2& l) {
    h = __floats2half2_rn(v0, v1);
    float2 f = __half22float2(h);
    l = __floats2half2_rn(v0 - f.x, v1 - f.y);
}
__device__ __forceinline__ uint32_t swz_off(int row, int ch) {
    return (uint32_t)(row * 64 + ((ch ^ ((row >> 1) & 3)) << 4));
}

#define SMEM_BYTES 98304
#define NTHREADS 256

// --- fills ------------------------------------------------------------------------
template<int TERMS>
__device__ __forceinline__ void fill_B(uint32_t sb,
    const __half* B1, const __half* B2, ll n0, int k0, int K, int tid)
{
    #pragma unroll
    for (int j = 0; j < 2; j++) {
        const int id = j*256 + tid;
        const int row = id >> 2, ch = id & 3;
        const uint32_t so = swz_off(row, ch);
        const ll bo = (n0 + row) * (ll)K + k0 + ch * 8;
        cpa16(sb + 16384u + so, B1 + bo);
        if (TERMS == 3) cpa16(sb + 24576u + so, B2 + bo);
    }
}
__device__ __forceinline__ void fill_A_hf(uint32_t sb,
    const __half* A1, const __half* A2, ll m0, int k0, int K, int tid)
{
    #pragma unroll
    for (int j = 0; j < 2; j++) {
        const int id = j*256 + tid;
        const int row = id >> 2, ch = id & 3;
        const uint32_t so = swz_off(row, ch);
        const ll ao = (m0 + row) * (ll)K + k0 + ch * 8;
        cpa16(sb + so, A1 + ao);
        cpa16(sb + 8192u + so, A2 + ao);
    }
}
__device__ __forceinline__ void ldg_A_f32(float4* r, const float* Af,
                                          ll m0, int k0, int K, int tid)
{
    #pragma unroll
    for (int j = 0; j < 2; j++) {
        const int id = j*256 + tid;
        const int row = id >> 2, ch = id & 3;
        const float* s = Af + (m0 + row) * (ll)K + k0 + ch * 8;
        r[j*2]   = *(const float4*)s;
        r[j*2+1] = *(const float4*)(s + 4);
    }
}
__device__ __forceinline__ void sts_A_split(char* sp, const float4* r, int tid)
{
    #pragma unroll
    for (int j = 0; j < 2; j++) {
        const int id = j*256 + tid;
        const int row = id >> 2, ch = id & 3;
        const uint32_t so = swz_off(row, ch);
        __half2 h0,l0,h1,l1,h2,l2,h3,l3;
        split2(r[j*2].x,   r[j*2].y,   h0, l0);
        split2(r[j*2].z,   r[j*2].w,   h1, l1);
        split2(r[j*2+1].x, r[j*2+1].y, h2, l2);
        split2(r[j*2+1].z, r[j*2+1].w, h3, l3);
        *(uint4*)(sp + so) = make_uint4(*(uint32_t*)&h0, *(uint32_t*)&h1,
                                        *(uint32_t*)&h2, *(uint32_t*)&h3);
        *(uint4*)(sp + 8192 + so) = make_uint4(*(uint32_t*)&l0, *(uint32_t*)&l1,
                                               *(uint32_t*)&l2, *(uint32_t*)&l3);
    }
}

// ---------------- shared GEMM mainloop: 128x128 tile, split-fp16 -----------------
// 8 warps 2(m) x 4(n), warp tile 64x32; interleaved fills; NST stages
// 3-term path uses a second B-fragment buffer so B-lo latency hides under term-2.
template<int ASRC, int TERMS>
__device__ __forceinline__ void gemm_core(float (&acc)[4][4][4],
    const __half* A1, const __half* A2, const float* Af,
    const __half* B1, const __half* B2,
    ll m0, ll n0, int K, char* smc, int tid, int lane, int warp_m, int warp_n)
{
    const uint32_t sbase = smem_u32(smc);
    constexpr uint32_t STGT = (TERMS == 3) ? 32768u : 24576u;
    constexpr int NST = (TERMS == 3) ? 3 : 4;
    constexpr int PFD = NST - 1;
    const int NC = K >> 5;

    for (int s = 0; s < PFD; s++) {
        if (ASRC) {
            float4 r[4];
            ldg_A_f32(r, Af, m0, s*32, K, tid);
            sts_A_split(smc + s*STGT, r, tid);
        } else {
            fill_A_hf(sbase + (uint32_t)s*STGT, A1, A2, m0, s*32, K, tid);
        }
        fill_B<TERMS>(sbase + (uint32_t)s*STGT, B1, B2, n0, s*32, K, tid);
        asm volatile("cp.async.commit_group;" ::: "memory");
    }

    const int row_a = warp_m*64 + (lane & 15);
    const uint32_t a_row = (uint32_t)(row_a * 64);
    const int swa = ((lane & 15) >> 1) & 3;
    const int cha = lane >> 4;
    const int row_b = warp_n*32 + ((lane >> 4) << 3) + (lane & 7);
    const uint32_t b_row = (uint32_t)(row_b * 64);
    const int swb = (row_b >> 1) & 3;
    const int chb = (lane >> 3) & 1;

    for (int c = 0; c < NC; c++) {
        asm volatile("cp.async.wait_group %0;" :: "n"(NST - 2) : "memory");
        __syncthreads();
        const uint32_t sb = sbase + (uint32_t)(c % NST) * STGT;
        const uint32_t spfu = sbase + (uint32_t)((c + PFD) % NST) * STGT;
        char* spf = smc + ((c + PFD) % NST) * STGT;
        const bool pf = (c + PFD < NC);
        const int kpf = (c + PFD) * 32;
        float4 r[4];

        #pragma unroll
        for (int ks = 0; ks < 2; ks++) {
            const uint32_t ca = (uint32_t)(((ks*2 + cha) ^ swa) << 4);
            const uint32_t cb = (uint32_t)(((ks*2 + chb) ^ swb) << 4);
            uint32_t afh[4][4], afl[4][4], bq[2][4], bq2[2][4];
            #pragma unroll
            for (int mt = 0; mt < 4; mt++) ldsm4(afh[mt], sb + a_row + mt*1024u + ca);
            #pragma unroll
            for (int h = 0; h < 2; h++) ldsm4(bq[h], sb + 16384u + b_row + h*1024u + cb);
            // term 1: Ah*Bh
            #pragma unroll
            for (int mt = 0; mt < 4; mt++)
                #pragma unroll
                for (int nt = 0; nt < 4; nt++)
                    mma16816(acc[mt][nt], afh[mt], &bq[nt >> 1][(nt & 1) * 2]);
            // A prefetch (only in ks=0 slot)
            if (ks == 0 && pf) {
                if (ASRC) ldg_A_f32(r, Af, m0, kpf, K, tid);
                else      fill_A_hf(spfu, A1, A2, m0, kpf, K, tid);
            }
            #pragma unroll
            for (int mt = 0; mt < 4; mt++) ldsm4(afl[mt], sb + 8192u + a_row + mt*1024u + ca);
            if (TERMS == 3) {
                // hoist B-lo loads so they hide under term-2 MMAs
                #pragma unroll
                for (int h = 0; h < 2; h++)
                    ldsm4(bq2[h], sb + 24576u + b_row + h*1024u + cb);
            }
            // term 2: Al*Bh
            #pragma unroll
            for (int mt = 0; mt < 4; mt++)
                #pragma unroll
                for (int nt = 0; nt < 4; nt++)
                    mma16816(acc[mt][nt], afl[mt], &bq[nt >> 1][(nt & 1) * 2]);
            // B prefetch (only in ks=0 slot)
            if (ks == 0 && pf) fill_B<TERMS>(spfu, B1, B2, n0, kpf, K, tid);
            if (TERMS == 3) {
                // term 3: Ah*Bl
                #pragma unroll
                for (int mt = 0; mt < 4; mt++)
                    #pragma unroll
                    for (int nt = 0; nt < 4; nt++)
                        mma16816(acc[mt][nt], afh[mt], &bq2[nt >> 1][(nt & 1) * 2]);
            }
            if (ks == 0) asm volatile("cp.async.commit_group;" ::: "memory");
        }
        if (ASRC && pf) sts_A_split(spf, r, tid);
    }
}

// ---------------- generic GEMM kernel ---------------------------------------------
template<int EPI, int OUT, int ASRC, int TERMS>
__global__ void __launch_bounds__(NTHREADS, 2)
gemm_mma(const __half* __restrict__ Ah, const __half* __restrict__ Al,
         const float* __restrict__ Af,
         const __half* __restrict__ Bh, const __half* __restrict__ Bl,
         const float* __restrict__ bias, const float* __restrict__ res,
         float* __restrict__ Cf, __half* __restrict__ Ch, __half* __restrict__ Cl,
         int K, int N, ll sA, ll sB, ll sC)
{
    extern __shared__ char smc[];
    const int tid = threadIdx.x, lane = tid & 31, wid = tid >> 5;
    const int warp_m = wid & 1, warp_n = wid >> 1;
    const ll m0 = (ll)blockIdx.y * 128;
    const ll n0 = (ll)blockIdx.x * 128;
    const ll zb = blockIdx.z;

    float acc[4][4][4];
    #pragma unroll
    for (int i = 0; i < 4; i++)
        #pragma unroll
        for (int j = 0; j < 4; j++)
            #pragma unroll
            for (int q = 0; q < 4; q++) acc[i][j][q] = 0.0f;

    gemm_core<ASRC, TERMS>(acc, Ah + zb * sA, Al + zb * sA, Af,
                           Bh + zb * sB, Bl + zb * sB,
                           m0, n0, K, smc, tid, lane, warp_m, warp_n);

    const int r0 = lane >> 2, c0 = (lane & 3) * 2;
    float*  Cbf = Cf + zb * sC;
    __half* Cbh = Ch + zb * sC;
    __half* Cbl = Cl + zb * sC;
    const float* Rb = res + zb * sC;
    #pragma unroll
    for (int mt = 0; mt < 4; mt++)
        #pragma unroll
        for (int nt = 0; nt < 4; nt++) {
            const int n = warp_n*32 + nt*8 + c0;
            float2 bv = make_float2(0.f, 0.f);
            if (EPI >= 1) bv = *(const float2*)&bias[n0 + n];
            #pragma unroll
            for (int hh = 0; hh < 2; hh++) {
                const int m = warp_m*64 + mt*16 + r0 + hh*8;
                float v0 = acc[mt][nt][hh*2], v1 = acc[mt][nt][hh*2+1];
                if (EPI >= 1) { v0 += bv.x; v1 += bv.y; }
                if (EPI >= 2) { v0 = gelu_f(v0); v1 = gelu_f(v1); }
                const ll idx = (m0 + m) * (ll)N + n0 + n;
                if (EPI == 3) {
                    float2 rv = *(const float2*)&Rb[idx];
                    v0 += rv.x; v1 += rv.y;
                }
                if (OUT == 0) {
                    *(float2*)&Cbf[idx] = make_float2(v0, v1);
                } else {
                    __half2 h, l; split2(v0, v1, h, l);
                    *(__half2*)&Cbh[idx] = h;
                    *(__half2*)&Cbl[idx] = l;
                }
            }
        }
}

// ---------------- merged projections kernel (z = 0:left 1:right 2:body) -----------
struct P3 { const float* A; const __half* Wh; const __half* Wl;
            const float* bias; __half* Ch; __half* Cl; };

__global__ void __launch_bounds__(NTHREADS, 2)
proj3(P3 p0, P3 p1, P3 p2)
{
    extern __shared__ char smc[];
    const int tid = threadIdx.x, lane = tid & 31, wid = tid >> 5;
    const int warp_m = wid & 1, warp_n = wid >> 1;
    const int z = blockIdx.z;
    const P3 p = (z == 0) ? p0 : (z == 1) ? p1 : p2;
    const ll m0 = (ll)blockIdx.y * 128;
    const ll n0 = (ll)blockIdx.x * 128;

    float acc[4][4][4];
    #pragma unroll
    for (int i = 0; i < 4; i++)
        #pragma unroll
        for (int j = 0; j < 4; j++)
            #pragma unroll
            for (int q = 0; q < 4; q++) acc[i][j][q] = 0.0f;

    gemm_core<1, 2>(acc, nullptr, nullptr, p.A, p.Wh, p.Wl,
                    m0, n0, DD, smc, tid, lane, warp_m, warp_n);

    const int r0 = lane >> 2, c0 = (lane & 3) * 2;
    if (z < 2) {
        #pragma unroll
        for (int mt = 0; mt < 4; mt++)
            #pragma unroll
            for (int nt = 0; nt < 4; nt++) {
                const int n = warp_n*32 + nt*8 + c0;
                const float2 bv = *(const float2*)&p.bias[n0 + n];
                #pragma unroll
                for (int hh = 0; hh < 2; hh++) {
                    const int m = warp_m*64 + mt*16 + r0 + hh*8;
                    float v0 = gelu_f(acc[mt][nt][hh*2]   + bv.x);
                    float v1 = gelu_f(acc[mt][nt][hh*2+1] + bv.y);
                    const ll idx = (m0 + m) * (ll)DD + n0 + n;
                    __half2 h, l; split2(v0, v1, h, l);
                    *(__half2*)&p.Ch[idx] = h;
                    *(__half2*)&p.Cl[idx] = l;
                }
            }
    } else {
        __syncthreads();
        float* st = (float*)smc;                    // 128 x 128, stride 132
        #pragma unroll
        for (int mt = 0; mt < 4; mt++)
            #pragma unroll
            for (int nt = 0; nt < 4; nt++) {
                const int n = warp_n*32 + nt*8 + c0;
                const float2 bv = *(const float2*)&p.bias[n0 + n];
                #pragma unroll
                for (int hh = 0; hh < 2; hh++) {
                    const int m = warp_m*64 + mt*16 + r0 + hh*8;
                    st[m*132 + n]     = gelu_f(acc[mt][nt][hh*2]   + bv.x);
                    st[m*132 + n + 1] = gelu_f(acc[mt][nt][hh*2+1] + bv.y);
                }
            }
        __syncthreads();
        const int b  = (int)(m0 >> 11);
        const int t0 = (int)(m0 & 2047);
        for (int e = tid; e < 128 * 64; e += NTHREADS) {
            const int n  = e >> 6;
            const int tp = (e & 63) * 2;
            const float v0 = st[tp*132 + n], v1 = st[(tp+1)*132 + n];
            __half2 h, l; split2(v0, v1, h, l);
            const ll idx = ((ll)b * DD + n0 + n) * TT + t0 + tp;
            *(__half2*)&p.Ch[idx] = h;
            *(__half2*)&p.Cl[idx] = l;
        }
    }
}

// ---------------- weight prep (transpose + split) --------------------------------
__device__ __forceinline__ void wtile(const float* src, __half* dh, __half* dl,
                                      int R, int Cc, int bx, int by)
{
    __shared__ float t[32][33];
    int x = bx * 32 + threadIdx.x;
    int y = by * 32 + threadIdx.y;
    #pragma unroll
    for (int j = 0; j < 32; j += 8) t[threadIdx.y + j][threadIdx.x] = src[(ll)(y + j) * Cc + x];
    __syncthreads();
    x = by * 32 + threadIdx.x;
    y = bx * 32 + threadIdx.y;
    #pragma unroll
    for (int j = 0; j < 32; j += 8) {
        float v = t[threadIdx.x][threadIdx.y + j];
        __half h = __float2half_rn(v);
        ll idx = (ll)(y + j) * R + x;
        dh[idx] = h;
        dl[idx] = __float2half_rn(v - __half2float(h));
    }
}
__global__ void __launch_bounds__(256)
wprep1(const float* __restrict__ s0, const float* __restrict__ s1,
       const float* __restrict__ s2)
{
    const int b = blockIdx.x;
    const int w = b >> 8, tt = b & 255;
    const float* src = w == 0 ? s0 : (w == 1 ? s1 : s2);
    __half* dh = w == 0 ? g_WlTh : (w == 1 ? g_WrTh : g_WbTh);
    __half* dl = w == 0 ? g_WlTl : (w == 1 ? g_WrTl : g_WbTl);
    wtile(src, dh, dl, DD, DD, tt & 15, tt >> 4);
}
__global__ void __launch_bounds__(256)
wprep2(const float* __restrict__ s3, const float* __restrict__ s4,
       const float* __restrict__ s5, const float* __restrict__ s6)
{
    const int b = blockIdx.x;
    if (b < 512) {
        const int w = b >> 8, tt = b & 255;
        wtile(w ? s4 : s3, w ? g_W1Th : g_WoTh, w ? g_W1Tl : g_WoTl,
              DD, DD, tt & 15, tt >> 4);
    } else if (b < 1280) {
        const int tt = b - 512;
        wtile(s5, g_W2Th, g_W2Tl, DD, DMID, tt % 48, tt / 48);
    } else {
        const int tt = b - 1280;
        wtile(s6, g_W3Th, g_W3Tl, DMID, DD, tt % 16, tt / 16);
    }
}

// ---------------- softmax rows of 2048, split-fp16 in/out ------------------------
__global__ void __launch_bounds__(256)
softmax2048s(__half* __restrict__ Sh, __half* __restrict__ Sl)
{
    __shared__ float sh[8];
    const ll base = (ll)blockIdx.x * TT;
    const int tid = threadIdx.x, lane = tid & 31, warp = tid >> 5;
    float x[8];
    {
        uint4 hv = *(const uint4*)(Sh + base + tid * 8);
        uint4 lv = *(const uint4*)(Sl + base + tid * 8);
        const uint32_t hr[4] = {hv.x, hv.y, hv.z, hv.w};
        const uint32_t lr[4] = {lv.x, lv.y, lv.z, lv.w};
        #pragma unroll
        for (int i = 0; i < 4; i++) {
            float2 h2 = __half22float2(*(const __half2*)&hr[i]);
            float2 l2 = __half22float2(*(const __half2*)&lr[i]);
            x[i*2]   = h2.x + l2.x;
            x[i*2+1] = h2.y + l2.y;
        }
    }
    float m = x[0];
    #pragma unroll
    for (int i = 1; i < 8; i++) m = fmaxf(m, x[i]);
    #pragma unroll
    for (int o = 16; o > 0; o >>= 1) m = fmaxf(m, __shfl_xor_sync(0xffffffffu, m, o));
    if (lane == 0) sh[warp] = m;
    __syncthreads();
    if (tid == 0) { float mm = sh[0]; for (int w = 1; w < 8; w++) mm = fmaxf(mm, sh[w]); sh[0] = mm; }
    __syncthreads();
    const float rmax = sh[0];
    __syncthreads();
    float e[8], s = 0.0f;
    #pragma unroll
    for (int i = 0; i < 8; i++) { e[i] = __expf(x[i] - rmax); s += e[i]; }
    #pragma unroll
    for (int o = 16; o > 0; o >>= 1) s += __shfl_xor_sync(0xffffffffu, s, o);
    if (lane == 0) sh[warp] = s;
    __syncthreads();
    if (tid == 0) { float ss = 0; for (int w = 0; w < 8; w++) ss += sh[w]; sh[0] = ss; }
    __syncthreads();
    const float inv = 1.0f / sh[0];
    #pragma unroll
    for (int i = 0; i < 4; i++) {
        __half2 h, l;
        split2(e[i*2] * inv, e[i*2+1] * inv, h, l);
        *(__half2*)&Sh[base + tid*8 + i*2] = h;
        *(__half2*)&Sl[base + tid*8 + i*2] = l;
    }
}

// ---------------- layernorm rows of 512 -> fp32 + split --------------------------
__global__ void __launch_bounds__(128)
layernorm512s(const float* __restrict__ X, float* __restrict__ Y,
              __half* __restrict__ Yh, __half* __restrict__ Yl,
              const float* __restrict__ g, const float* __restrict__ b)
{
    __shared__ float shs[4], shq[4];
    const ll base = (ll)blockIdx.x * DD;
    const float* x = X + base;
    const int tid = threadIdx.x, lane = tid & 31, warp = tid >> 5;
    float4 v = *(const float4*)(x + tid * 4);
    float s = v.x + v.y + v.z + v.w;
    float q = v.x*v.x + v.y*v.y + v.z*v.z + v.w*v.w;
    #pragma unroll
    for (int o = 16; o > 0; o >>= 1) {
        s += __shfl_xor_sync(0xffffffffu, s, o);
        q += __shfl_xor_sync(0xffffffffu, q, o);
    }
    if (lane == 0) { shs[warp] = s; shq[warp] = q; }
    __syncthreads();
    if (tid == 0) { shs[0] = shs[0]+shs[1]+shs[2]+shs[3]; shq[0] = shq[0]+shq[1]+shq[2]+shq[3]; }
    __syncthreads();
    const float mu  = shs[0] * (1.0f / DD);
    const float var = shq[0] * (1.0f / DD) - mu * mu;
    const float r = rsqrtf(var + 1e-5f);
    float4 gg = *(const float4*)(g + tid * 4);
    float4 bb = *(const float4*)(b + tid * 4);
    float4 o;
    o.x = (v.x - mu) * r * gg.x + bb.x;
    o.y = (v.y - mu) * r * gg.y + bb.y;
    o.z = (v.z - mu) * r * gg.z + bb.z;
    o.w = (v.w - mu) * r * gg.w + bb.w;
    *(float4*)(Y + base + tid * 4) = o;
    __half2 h0, l0, h1, l1;
    split2(o.x, o.y, h0, l0);
    split2(o.z, o.w, h1, l1);
    *(__half2*)&Yh[base + tid*4]     = h0;
    *(__half2*)&Yh[base + tid*4 + 2] = h1;
    *(__half2*)&Yl[base + tid*4]     = l0;
    *(__half2*)&Yl[base + tid*4 + 2] = l1;
}

// ---------------- launch ----------------------------------------------------------
extern "C" void kernel_launch(void* const* d_in, const int* in_sizes, int n_in,
                              void* d_out, int out_size)
{
    const float* left  = (const float*)d_in[0];
    const float* right = (const float*)d_in[1];
    const float* body  = (const float*)d_in[2];
    const float* Wl = (const float*)d_in[3];  const float* bl = (const float*)d_in[4];
    const float* Wr = (const float*)d_in[5];  const float* br = (const float*)d_in[6];
    const float* Wb = (const float*)d_in[7];  const float* bbv = (const float*)d_in[8];
    const float* Wo = (const float*)d_in[9];  const float* bo = (const float*)d_in[10];
    const float* ln_g = (const float*)d_in[11]; const float* ln_b = (const float*)d_in[12];
    const float* W1 = (const float*)d_in[13]; const float* b1 = (const float*)d_in[14];
    const float* lg2 = (const float*)d_in[15]; const float* lb2 = (const float*)d_in[16];
    const float* W2 = (const float*)d_in[17]; const float* b2 = (const float*)d_in[18];
    const float* W3 = (const float*)d_in[19]; const float* b3 = (const float*)d_in[20];
    float* out = (float*)d_out;

    float *t2, *ln1;
    __half *Sh, *Sl, *loh, *lol, *roh, *rol, *bth, *btl;
    __half *t1h, *t1l, *l1h, *l1l, *l2h, *l2l, *mh, *ml;
    __half *WlTh,*WlTl,*WrTh,*WrTl,*WbTh,*WbTl,*WoTh,*WoTl,*W1Th,*W1Tl,*W2Th,*W2Tl,*W3Th,*W3Tl;
    cudaGetSymbolAddress((void**)&Sh,  g_Sh);  cudaGetSymbolAddress((void**)&Sl,  g_Sl);
    cudaGetSymbolAddress((void**)&loh, g_loh); cudaGetSymbolAddress((void**)&lol, g_lol);
    cudaGetSymbolAddress((void**)&roh, g_roh); cudaGetSymbolAddress((void**)&rol, g_rol);
    cudaGetSymbolAddress((void**)&bth, g_bth); cudaGetSymbolAddress((void**)&btl, g_btl);
    cudaGetSymbolAddress((void**)&t1h, g_t1h); cudaGetSymbolAddress((void**)&t1l, g_t1l);
    cudaGetSymbolAddress((void**)&t2,  g_t2);  cudaGetSymbolAddress((void**)&ln1, g_ln1);
    cudaGetSymbolAddress((void**)&l1h, g_l1h); cudaGetSymbolAddress((void**)&l1l, g_l1l);
    cudaGetSymbolAddress((void**)&l2h, g_l2h); cudaGetSymbolAddress((void**)&l2l, g_l2l);
    cudaGetSymbolAddress((void**)&mh,  g_mh);  cudaGetSymbolAddress((void**)&ml,  g_ml);
    cudaGetSymbolAddress((void**)&WlTh,g_WlTh);cudaGetSymbolAddress((void**)&WlTl,g_WlTl);
    cudaGetSymbolAddress((void**)&WrTh,g_WrTh);cudaGetSymbolAddress((void**)&WrTl,g_WrTl);
    cudaGetSymbolAddress((void**)&WbTh,g_WbTh);cudaGetSymbolAddress((void**)&WbTl,g_WbTl);
    cudaGetSymbolAddress((void**)&WoTh,g_WoTh);cudaGetSymbolAddress((void**)&WoTl,g_WoTl);
    cudaGetSymbolAddress((void**)&W1Th,g_W1Th);cudaGetSymbolAddress((void**)&W1Tl,g_W1Tl);
    cudaGetSymbolAddress((void**)&W2Th,g_W2Th);cudaGetSymbolAddress((void**)&W2Tl,g_W2Tl);
    cudaGetSymbolAddress((void**)&W3Th,g_W3Th);cudaGetSymbolAddress((void**)&W3Tl,g_W3Tl);

    cudaFuncSetAttribute(proj3,             cudaFuncAttributeMaxDynamicSharedMemorySize, SMEM_BYTES);
    cudaFuncSetAttribute(gemm_mma<0,1,0,3>, cudaFuncAttributeMaxDynamicSharedMemorySize, SMEM_BYTES);
    cudaFuncSetAttribute(gemm_mma<1,0,0,2>, cudaFuncAttributeMaxDynamicSharedMemorySize, SMEM_BYTES);
    cudaFuncSetAttribute(gemm_mma<3,0,0,2>, cudaFuncAttributeMaxDynamicSharedMemorySize, SMEM_BYTES);
    cudaFuncSetAttribute(gemm_mma<2,1,0,2>, cudaFuncAttributeMaxDynamicSharedMemorySize, SMEM_BYTES);

    const ll sTD = (ll)TT * DD;
    const ll sTT = (ll)TT * TT;
    dim3 tb(32, 8);

    P3 p0 = {left,  WlTh, WlTl, bl,  loh, lol};
    P3 p1 = {right, WrTh, WrTl, br,  roh, rol};
    P3 p2 = {body,  WbTh, WbTl, bbv, bth, btl};

    // idx 0: Wl/Wr/Wb prep
    wprep1<<<768, tb>>>(Wl, Wr, Wb);
    // idx 1: merged projections (z = 0,1,2)
    proj3<<<dim3(4, 128, 3), NTHREADS, SMEM_BYTES>>>(p0, p1, p2);
    // idx 2: remaining weight prep
    wprep2<<<2048, tb>>>(Wo, W1, W2, W3);
    // idx 3: attention scores (3-term)  <-- ncu profiles this launch
    gemm_mma<0,1,0,3><<<dim3(16,16,BB), NTHREADS, SMEM_BYTES>>>(roh, rol, nullptr,
        loh, lol, nullptr, nullptr, nullptr, Sh, Sl, DD, TT, sTD, sTD, sTT);
    // softmax + fuse (3-term)
    softmax2048s<<<BT, 256>>>(Sh, Sl);
    gemm_mma<0,1,0,3><<<dim3(4,16,BB), NTHREADS, SMEM_BYTES>>>(Sh, Sl, nullptr,
        bth, btl, nullptr, nullptr, nullptr, t1h, t1l, TT, DD, sTT, sTD, sTD);
    // output projection + LN (2-term)
    gemm_mma<1,0,0,2><<<dim3(4,128,1), NTHREADS, SMEM_BYTES>>>(t1h, t1l, nullptr,
        WoTh, WoTl, bo, nullptr, t2, nullptr, nullptr, DD, DD, 0, 0, 0);
    layernorm512s<<<BT, 128>>>(t2, ln1, l1h, l1l, ln_g, ln_b);
    // inverted residual (2-term)
    gemm_mma<3,0,0,2><<<dim3(4,128,1), NTHREADS, SMEM_BYTES>>>(l1h, l1l, nullptr,
        W1Th, W1Tl, b1, ln1, t2, nullptr, nullptr, DD, DD, 0, 0, 0);
    layernorm512s<<<BT, 128>>>(t2, ln1, l2h, l2l, lg2, lb2);
    gemm_mma<2,1,0,2><<<dim3(12,128,1), NTHREADS, SMEM_BYTES>>>(l2h, l2l, nullptr,
        W2Th, W2Tl, b2, nullptr, nullptr, mh, ml, DD, DMID, 0, 0, 0);
    gemm_mma<1,0,0,2><<<dim3(4,128,1), NTHREADS, SMEM_BYTES>>>(mh, ml, nullptr,
        W3Th, W3Tl, b3, nullptr, out, nullptr, nullptr, DMID, DD, 0, 0, 0);
}

// round 17
// speedup vs baseline: 3.6303x; 1.0003x over previous
#include <cuda_runtime.h>
#include <cuda_fp16.h>
#include <cstdint>
#include <math.h>

#define BB   8
#define TT   2048
#define DD   512
#define BT   (BB*TT)
#define DMID (3*DD)
typedef long long ll;

// ---------------- scratch -------------------------------------------------------
__device__ __align__(16) __half g_Sh[(ll)BB*TT*TT];
__device__ __align__(16) __half g_Sl[(ll)BB*TT*TT];
__device__ __align__(16) __half g_loh[BT*DD], g_lol[BT*DD];
__device__ __align__(16) __half g_roh[BT*DD], g_rol[BT*DD];
__device__ __align__(16) __half g_bth[BT*DD], g_btl[BT*DD];
__device__ __align__(16) __half g_t1h[BT*DD], g_t1l[BT*DD];
__device__ __align__(16) float g_t2 [BT*DD];
__device__ __align__(16) float g_ln1[BT*DD];
__device__ __align__(16) __half g_l1h[BT*DD], g_l1l[BT*DD];
__device__ __align__(16) __half g_l2h[BT*DD], g_l2l[BT*DD];
__device__ __align__(16) __half g_mh[BT*DMID], g_ml[BT*DMID];
__device__ __align__(16) __half g_WlTh[DD*DD],  g_WlTl[DD*DD];
__device__ __align__(16) __half g_WrTh[DD*DD],  g_WrTl[DD*DD];
__device__ __align__(16) __half g_WbTh[DD*DD],  g_WbTl[DD*DD];
__device__ __align__(16) __half g_WoTh[DD*DD],  g_WoTl[DD*DD];
__device__ __align__(16) __half g_W1Th[DD*DD],  g_W1Tl[DD*DD];
__device__ __align__(16) __half g_W2Th[DMID*DD],g_W2Tl[DMID*DD];
__device__ __align__(16) __half g_W3Th[DD*DMID],g_W3Tl[DD*DMID];

// ---------------- helpers -------------------------------------------------------
__device__ __forceinline__ float gelu_f(float x) {
    return 0.5f * x * (1.0f + erff(x * 0.7071067811865476f));
}
__device__ __forceinline__ uint32_t smem_u32(const void* p) {
    uint32_t a;
    asm("{ .reg .u64 t; cvta.to.shared.u64 t, %1; cvt.u32.u64 %0, t; }" : "=r"(a) : "l"(p));
    return a;
}
__device__ __forceinline__ void cpa16(uint32_t dst, const void* src) {
    asm volatile("cp.async.cg.shared.global [%0], [%1], 16;" :: "r"(dst), "l"(src));
}
__device__ __forceinline__ void ldsm4(uint32_t* r, uint32_t a) {
    asm volatile("ldmatrix.sync.aligned.m8n8.x4.shared.b16 {%0,%1,%2,%3}, [%4];"
                 : "=r"(r[0]), "=r"(r[1]), "=r"(r[2]), "=r"(r[3]) : "r"(a));
}
__device__ __forceinline__ void mma16816(float* d, const uint32_t* a, const uint32_t* b) {
    asm volatile("mma.sync.aligned.m16n8k16.row.col.f32.f16.f16.f32 "
                 "{%0,%1,%2,%3}, {%4,%5,%6,%7}, {%8,%9}, {%0,%1,%2,%3};"
                 : "+f"(d[0]), "+f"(d[1]), "+f"(d[2]), "+f"(d[3])
                 : "r"(a[0]), "r"(a[1]), "r"(a[2]), "r"(a[3]), "r"(b[0]), "r"(b[1]));
}
__device__ __forceinline__ void split2(float v0, float v1, __half2& h, __half2& l) {
    h = __floats2half2_rn(v0, v1);
    float2 f = __half22float2(h);
    l = __floats2half2_rn(v0 - f.x, v1 - f.y);
}
__device__ __forceinline__ uint32_t swz_off(int row, int ch) {
    return (uint32_t)(row * 64 + ((ch ^ ((row >> 1) & 3)) << 4));
}

#define SMEM_BYTES 98304
#define NTHREADS 256

// --- fills (stage layout: A-hi 0 | A-lo 8192 | B-hi 16384 | [B-lo 24576]) ---------
template<int TERMS>
__device__ __forceinline__ void fill_B(uint32_t sb,
    const __half* B1, const __half* B2, ll n0, int k0, int K, int tid)
{
    #pragma unroll
    for (int j = 0; j < 2; j++) {
        const int id = j*256 + tid;
        const int row = id >> 2, ch = id & 3;
        const uint32_t so = swz_off(row, ch);
        const ll bo = (n0 + row) * (ll)K + k0 + ch * 8;
        cpa16(sb + 16384u + so, B1 + bo);
        if (TERMS == 3) cpa16(sb + 24576u + so, B2 + bo);
    }
}
__device__ __forceinline__ void fill_A_hf(uint32_t sb,
    const __half* A1, const __half* A2, ll m0, int k0, int K, int tid)
{
    #pragma unroll
    for (int j = 0; j < 2; j++) {
        const int id = j*256 + tid;
        const int row = id >> 2, ch = id & 3;
        const uint32_t so = swz_off(row, ch);
        const ll ao = (m0 + row) * (ll)K + k0 + ch * 8;
        cpa16(sb + so, A1 + ao);
        cpa16(sb + 8192u + so, A2 + ao);
    }
}
__device__ __forceinline__ void ldg_A_f32(float4* r, const float* Af,
                                          ll m0, int k0, int K, int tid)
{
    #pragma unroll
    for (int j = 0; j < 2; j++) {
        const int id = j*256 + tid;
        const int row = id >> 2, ch = id & 3;
        const float* s = Af + (m0 + row) * (ll)K + k0 + ch * 8;
        r[j*2]   = *(const float4*)s;
        r[j*2+1] = *(const float4*)(s + 4);
    }
}
__device__ __forceinline__ void sts_A_split(char* sp, const float4* r, int tid)
{
    #pragma unroll
    for (int j = 0; j < 2; j++) {
        const int id = j*256 + tid;
        const int row = id >> 2, ch = id & 3;
        const uint32_t so = swz_off(row, ch);
        __half2 h0,l0,h1,l1,h2,l2,h3,l3;
        split2(r[j*2].x,   r[j*2].y,   h0, l0);
        split2(r[j*2].z,   r[j*2].w,   h1, l1);
        split2(r[j*2+1].x, r[j*2+1].y, h2, l2);
        split2(r[j*2+1].z, r[j*2+1].w, h3, l3);
        *(uint4*)(sp + so) = make_uint4(*(uint32_t*)&h0, *(uint32_t*)&h1,
                                        *(uint32_t*)&h2, *(uint32_t*)&h3);
        *(uint4*)(sp + 8192 + so) = make_uint4(*(uint32_t*)&l0, *(uint32_t*)&l1,
                                               *(uint32_t*)&l2, *(uint32_t*)&l3);
    }
}

// ---------------- R14 shared GEMM mainloop: 128x128 tile, split-fp16 --------------
template<int ASRC, int TERMS>
__device__ __forceinline__ void gemm_core(float (&acc)[4][4][4],
    const __half* A1, const __half* A2, const float* Af,
    const __half* B1, const __half* B2,
    ll m0, ll n0, int K, char* smc, int tid, int lane, int warp_m, int warp_n)
{
    const uint32_t sbase = smem_u32(smc);
    constexpr uint32_t STGT = (TERMS == 3) ? 32768u : 24576u;
    constexpr int NST = (TERMS == 3) ? 3 : 4;
    constexpr int PFD = NST - 1;
    const int NC = K >> 5;

    for (int s = 0; s < PFD; s++) {
        if (ASRC) {
            float4 r[4];
            ldg_A_f32(r, Af, m0, s*32, K, tid);
            sts_A_split(smc + s*STGT, r, tid);
        } else {
            fill_A_hf(sbase + (uint32_t)s*STGT, A1, A2, m0, s*32, K, tid);
        }
        fill_B<TERMS>(sbase + (uint32_t)s*STGT, B1, B2, n0, s*32, K, tid);
        asm volatile("cp.async.commit_group;" ::: "memory");
    }

    const int row_a = warp_m*64 + (lane & 15);
    const uint32_t a_row = (uint32_t)(row_a * 64);
    const int swa = ((lane & 15) >> 1) & 3;
    const int cha = lane >> 4;
    const int row_b = warp_n*32 + ((lane >> 4) << 3) + (lane & 7);
    const uint32_t b_row = (uint32_t)(row_b * 64);
    const int swb = (row_b >> 1) & 3;
    const int chb = (lane >> 3) & 1;

    for (int c = 0; c < NC; c++) {
        asm volatile("cp.async.wait_group %0;" :: "n"(NST - 2) : "memory");
        __syncthreads();
        const uint32_t sb = sbase + (uint32_t)(c % NST) * STGT;
        const uint32_t spfu = sbase + (uint32_t)((c + PFD) % NST) * STGT;
        char* spf = smc + ((c + PFD) % NST) * STGT;
        const bool pf = (c + PFD < NC);
        const int kpf = (c + PFD) * 32;
        float4 r[4];

        #pragma unroll
        for (int ks = 0; ks < 2; ks++) {
            const uint32_t ca = (uint32_t)(((ks*2 + cha) ^ swa) << 4);
            const uint32_t cb = (uint32_t)(((ks*2 + chb) ^ swb) << 4);
            uint32_t afh[4][4], afl[4][4], bq[2][4], bq2[2][4];
            #pragma unroll
            for (int mt = 0; mt < 4; mt++) ldsm4(afh[mt], sb + a_row + mt*1024u + ca);
            #pragma unroll
            for (int h = 0; h < 2; h++) ldsm4(bq[h], sb + 16384u + b_row + h*1024u + cb);
            #pragma unroll
            for (int mt = 0; mt < 4; mt++)
                #pragma unroll
                for (int nt = 0; nt < 4; nt++)
                    mma16816(acc[mt][nt], afh[mt], &bq[nt >> 1][(nt & 1) * 2]);
            if (ks == 0 && pf) {
                if (ASRC) ldg_A_f32(r, Af, m0, kpf, K, tid);
                else      fill_A_hf(spfu, A1, A2, m0, kpf, K, tid);
            }
            #pragma unroll
            for (int mt = 0; mt < 4; mt++) ldsm4(afl[mt], sb + 8192u + a_row + mt*1024u + ca);
            if (TERMS == 3) {
                #pragma unroll
                for (int h = 0; h < 2; h++)
                    ldsm4(bq2[h], sb + 24576u + b_row + h*1024u + cb);
            }
            #pragma unroll
            for (int mt = 0; mt < 4; mt++)
                #pragma unroll
                for (int nt = 0; nt < 4; nt++)
                    mma16816(acc[mt][nt], afl[mt], &bq[nt >> 1][(nt & 1) * 2]);
            if (ks == 0 && pf) fill_B<TERMS>(spfu, B1, B2, n0, kpf, K, tid);
            if (TERMS == 3) {
                #pragma unroll
                for (int mt = 0; mt < 4; mt++)
                    #pragma unroll
                    for (int nt = 0; nt < 4; nt++)
                        mma16816(acc[mt][nt], afh[mt], &bq2[nt >> 1][(nt & 1) * 2]);
            }
            if (ks == 0) asm volatile("cp.async.commit_group;" ::: "memory");
        }
        if (ASRC && pf) sts_A_split(spf, r, tid);
    }
}

// ---------------- generic GEMM kernel ---------------------------------------------
template<int EPI, int OUT, int ASRC, int TERMS>
__global__ void __launch_bounds__(NTHREADS, 2)
gemm_mma(const __half* __restrict__ Ah, const __half* __restrict__ Al,
         const float* __restrict__ Af,
         const __half* __restrict__ Bh, const __half* __restrict__ Bl,
         const float* __restrict__ bias, const float* __restrict__ res,
         float* __restrict__ Cf, __half* __restrict__ Ch, __half* __restrict__ Cl,
         int K, int N, ll sA, ll sB, ll sC)
{
    extern __shared__ char smc[];
    const int tid = threadIdx.x, lane = tid & 31, wid = tid >> 5;
    const int warp_m = wid & 1, warp_n = wid >> 1;
    const ll m0 = (ll)blockIdx.y * 128;
    const ll n0 = (ll)blockIdx.x * 128;
    const ll zb = blockIdx.z;

    float acc[4][4][4];
    #pragma unroll
    for (int i = 0; i < 4; i++)
        #pragma unroll
        for (int j = 0; j < 4; j++)
            #pragma unroll
            for (int q = 0; q < 4; q++) acc[i][j][q] = 0.0f;

    gemm_core<ASRC, TERMS>(acc, Ah + zb * sA, Al + zb * sA, Af,
                           Bh + zb * sB, Bl + zb * sB,
                           m0, n0, K, smc, tid, lane, warp_m, warp_n);

    const int r0 = lane >> 2, c0 = (lane & 3) * 2;
    float*  Cbf = Cf + zb * sC;
    __half* Cbh = Ch + zb * sC;
    __half* Cbl = Cl + zb * sC;
    const float* Rb = res + zb * sC;
    #pragma unroll
    for (int mt = 0; mt < 4; mt++)
        #pragma unroll
        for (int nt = 0; nt < 4; nt++) {
            const int n = warp_n*32 + nt*8 + c0;
            float2 bv = make_float2(0.f, 0.f);
            if (EPI >= 1) bv = *(const float2*)&bias[n0 + n];
            #pragma unroll
            for (int hh = 0; hh < 2; hh++) {
                const int m = warp_m*64 + mt*16 + r0 + hh*8;
                float v0 = acc[mt][nt][hh*2], v1 = acc[mt][nt][hh*2+1];
                if (EPI >= 1) { v0 += bv.x; v1 += bv.y; }
                if (EPI >= 2) { v0 = gelu_f(v0); v1 = gelu_f(v1); }
                const ll idx = (m0 + m) * (ll)N + n0 + n;
                if (EPI == 3) {
                    float2 rv = *(const float2*)&Rb[idx];
                    v0 += rv.x; v1 += rv.y;
                }
                if (OUT == 0) {
                    *(float2*)&Cbf[idx] = make_float2(v0, v1);
                } else {
                    __half2 h, l; split2(v0, v1, h, l);
                    *(__half2*)&Cbh[idx] = h;
                    *(__half2*)&Cbl[idx] = l;
                }
            }
        }
}

// ---------------- merged projections kernel (z = 0:left 1:right 2:body) -----------
struct P3 { const float* A; const __half* Wh; const __half* Wl;
            const float* bias; __half* Ch; __half* Cl; };

__global__ void __launch_bounds__(NTHREADS, 2)
proj3(P3 p0, P3 p1, P3 p2)
{
    extern __shared__ char smc[];
    const int tid = threadIdx.x, lane = tid & 31, wid = tid >> 5;
    const int warp_m = wid & 1, warp_n = wid >> 1;
    const int z = blockIdx.z;
    const P3 p = (z == 0) ? p0 : (z == 1) ? p1 : p2;
    const ll m0 = (ll)blockIdx.y * 128;
    const ll n0 = (ll)blockIdx.x * 128;

    float acc[4][4][4];
    #pragma unroll
    for (int i = 0; i < 4; i++)
        #pragma unroll
        for (int j = 0; j < 4; j++)
            #pragma unroll
            for (int q = 0; q < 4; q++) acc[i][j][q] = 0.0f;

    gemm_core<1, 2>(acc, nullptr, nullptr, p.A, p.Wh, p.Wl,
                    m0, n0, DD, smc, tid, lane, warp_m, warp_n);

    const int r0 = lane >> 2, c0 = (lane & 3) * 2;
    if (z < 2) {
        #pragma unroll
        for (int mt = 0; mt < 4; mt++)
            #pragma unroll
            for (int nt = 0; nt < 4; nt++) {
                const int n = warp_n*32 + nt*8 + c0;
                const float2 bv = *(const float2*)&p.bias[n0 + n];
                #pragma unroll
                for (int hh = 0; hh < 2; hh++) {
                    const int m = warp_m*64 + mt*16 + r0 + hh*8;
                    float v0 = gelu_f(acc[mt][nt][hh*2]   + bv.x);
                    float v1 = gelu_f(acc[mt][nt][hh*2+1] + bv.y);
                    const ll idx = (m0 + m) * (ll)DD + n0 + n;
                    __half2 h, l; split2(v0, v1, h, l);
                    *(__half2*)&p.Ch[idx] = h;
                    *(__half2*)&p.Cl[idx] = l;
                }
            }
    } else {
        __syncthreads();
        float* st = (float*)smc;                    // 128 x 128, stride 132
        #pragma unroll
        for (int mt = 0; mt < 4; mt++)
            #pragma unroll
            for (int nt = 0; nt < 4; nt++) {
                const int n = warp_n*32 + nt*8 + c0;
                const float2 bv = *(const float2*)&p.bias[n0 + n];
                #pragma unroll
                for (int hh = 0; hh < 2; hh++) {
                    const int m = warp_m*64 + mt*16 + r0 + hh*8;
                    st[m*132 + n]     = gelu_f(acc[mt][nt][hh*2]   + bv.x);
                    st[m*132 + n + 1] = gelu_f(acc[mt][nt][hh*2+1] + bv.y);
                }
            }
        __syncthreads();
        const int b  = (int)(m0 >> 11);
        const int t0 = (int)(m0 & 2047);
        for (int e = tid; e < 128 * 64; e += NTHREADS) {
            const int n  = e >> 6;
            const int tp = (e & 63) * 2;
            const float v0 = st[tp*132 + n], v1 = st[(tp+1)*132 + n];
            __half2 h, l; split2(v0, v1, h, l);
            const ll idx = ((ll)b * DD + n0 + n) * TT + t0 + tp;
            *(__half2*)&p.Ch[idx] = h;
            *(__half2*)&p.Cl[idx] = l;
        }
    }
}

// ---------------- weight prep: ALL transposes+splits in one launch ---------------
__device__ __forceinline__ void wtile(const float* src, __half* dh, __half* dl,
                                      int R, int Cc, int bx, int by)
{
    __shared__ float t[32][33];
    int x = bx * 32 + threadIdx.x;
    int y = by * 32 + threadIdx.y;
    #pragma unroll
    for (int j = 0; j < 32; j += 8) t[threadIdx.y + j][threadIdx.x] = src[(ll)(y + j) * Cc + x];
    __syncthreads();
    x = by * 32 + threadIdx.x;
    y = bx * 32 + threadIdx.y;
    #pragma unroll
    for (int j = 0; j < 32; j += 8) {
        float v = t[threadIdx.x][threadIdx.y + j];
        __half h = __float2half_rn(v);
        ll idx = (ll)(y + j) * R + x;
        dh[idx] = h;
        dl[idx] = __float2half_rn(v - __half2float(h));
    }
}
__global__ void __launch_bounds__(256)
wprep(const float* __restrict__ s0, const float* __restrict__ s1,
      const float* __restrict__ s2, const float* __restrict__ s3,
      const float* __restrict__ s4, const float* __restrict__ s5,
      const float* __restrict__ s6)
{
    const int b = blockIdx.x;
    if (b < 1280) {
        const int w = b >> 8, tt = b & 255;
        const float* src; __half *dh, *dl;
        switch (w) {
            case 0:  src = s0; dh = g_WlTh; dl = g_WlTl; break;
            case 1:  src = s1; dh = g_WrTh; dl = g_WrTl; break;
            case 2:  src = s2; dh = g_WbTh; dl = g_WbTl; break;
            case 3:  src = s3; dh = g_WoTh; dl = g_WoTl; break;
            default: src = s4; dh = g_W1Th; dl = g_W1Tl; break;
        }
        wtile(src, dh, dl, DD, DD, tt & 15, tt >> 4);
    } else if (b < 2048) {
        const int tt = b - 1280;
        wtile(s5, g_W2Th, g_W2Tl, DD, DMID, tt % 48, tt / 48);
    } else {
        const int tt = b - 2048;
        wtile(s6, g_W3Th, g_W3Tl, DMID, DD, tt % 16, tt / 16);
    }
}

// ---------------- softmax rows of 2048, split-fp16 in/out ------------------------
__global__ void __launch_bounds__(256)
softmax2048s(__half* __restrict__ Sh, __half* __restrict__ Sl)
{
    __shared__ float sh[8];
    const ll base = (ll)blockIdx.x * TT;
    const int tid = threadIdx.x, lane = tid & 31, warp = tid >> 5;
    float x[8];
    {
        uint4 hv = *(const uint4*)(Sh + base + tid * 8);
        uint4 lv = *(const uint4*)(Sl + base + tid * 8);
        const uint32_t hr[4] = {hv.x, hv.y, hv.z, hv.w};
        const uint32_t lr[4] = {lv.x, lv.y, lv.z, lv.w};
        #pragma unroll
        for (int i = 0; i < 4; i++) {
            float2 h2 = __half22float2(*(const __half2*)&hr[i]);
            float2 l2 = __half22float2(*(const __half2*)&lr[i]);
            x[i*2]   = h2.x + l2.x;
            x[i*2+1] = h2.y + l2.y;
        }
    }
    float m = x[0];
    #pragma unroll
    for (int i = 1; i < 8; i++) m = fmaxf(m, x[i]);
    #pragma unroll
    for (int o = 16; o > 0; o >>= 1) m = fmaxf(m, __shfl_xor_sync(0xffffffffu, m, o));
    if (lane == 0) sh[warp] = m;
    __syncthreads();
    if (tid == 0) { float mm = sh[0]; for (int w = 1; w < 8; w++) mm = fmaxf(mm, sh[w]); sh[0] = mm; }
    __syncthreads();
    const float rmax = sh[0];
    __syncthreads();
    float e[8], s = 0.0f;
    #pragma unroll
    for (int i = 0; i < 8; i++) { e[i] = __expf(x[i] - rmax); s += e[i]; }
    #pragma unroll
    for (int o = 16; o > 0; o >>= 1) s += __shfl_xor_sync(0xffffffffu, s, o);
    if (lane == 0) sh[warp] = s;
    __syncthreads();
    if (tid == 0) { float ss = 0; for (int w = 0; w < 8; w++) ss += sh[w]; sh[0] = ss; }
    __syncthreads();
    const float inv = 1.0f / sh[0];
    #pragma unroll
    for (int i = 0; i < 4; i++) {
        __half2 h, l;
        split2(e[i*2] * inv, e[i*2+1] * inv, h, l);
        *(__half2*)&Sh[base + tid*8 + i*2] = h;
        *(__half2*)&Sl[base + tid*8 + i*2] = l;
    }
}

// ---------------- layernorm rows of 512 -> fp32 + split --------------------------
__global__ void __launch_bounds__(128)
layernorm512s(const float* __restrict__ X, float* __restrict__ Y,
              __half* __restrict__ Yh, __half* __restrict__ Yl,
              const float* __restrict__ g, const float* __restrict__ b)
{
    __shared__ float shs[4], shq[4];
    const ll base = (ll)blockIdx.x * DD;
    const float* x = X + base;
    const int tid = threadIdx.x, lane = tid & 31, warp = tid >> 5;
    float4 v = *(const float4*)(x + tid * 4);
    float s = v.x + v.y + v.z + v.w;
    float q = v.x*v.x + v.y*v.y + v.z*v.z + v.w*v.w;
    #pragma unroll
    for (int o = 16; o > 0; o >>= 1) {
        s += __shfl_xor_sync(0xffffffffu, s, o);
        q += __shfl_xor_sync(0xffffffffu, q, o);
    }
    if (lane == 0) { shs[warp] = s; shq[warp] = q; }
    __syncthreads();
    if (tid == 0) { shs[0] = shs[0]+shs[1]+shs[2]+shs[3]; shq[0] = shq[0]+shq[1]+shq[2]+shq[3]; }
    __syncthreads();
    const float mu  = shs[0] * (1.0f / DD);
    const float var = shq[0] * (1.0f / DD) - mu * mu;
    const float r = rsqrtf(var + 1e-5f);
    float4 gg = *(const float4*)(g + tid * 4);
    float4 bb = *(const float4*)(b + tid * 4);
    float4 o;
    o.x = (v.x - mu) * r * gg.x + bb.x;
    o.y = (v.y - mu) * r * gg.y + bb.y;
    o.z = (v.z - mu) * r * gg.z + bb.z;
    o.w = (v.w - mu) * r * gg.w + bb.w;
    *(float4*)(Y + base + tid * 4) = o;
    __half2 h0, l0, h1, l1;
    split2(o.x, o.y, h0, l0);
    split2(o.z, o.w, h1, l1);
    *(__half2*)&Yh[base + tid*4]     = h0;
    *(__half2*)&Yh[base + tid*4 + 2] = h1;
    *(__half2*)&Yl[base + tid*4]     = l0;
    *(__half2*)&Yl[base + tid*4 + 2] = l1;
}

// ---------------- launch ----------------------------------------------------------
extern "C" void kernel_launch(void* const* d_in, const int* in_sizes, int n_in,
                              void* d_out, int out_size)
{
    const float* left  = (const float*)d_in[0];
    const float* right = (const float*)d_in[1];
    const float* body  = (const float*)d_in[2];
    const float* Wl = (const float*)d_in[3];  const float* bl = (const float*)d_in[4];
    const float* Wr = (const float*)d_in[5];  const float* br = (const float*)d_in[6];
    const float* Wb = (const float*)d_in[7];  const float* bbv = (const float*)d_in[8];
    const float* Wo = (const float*)d_in[9];  const float* bo = (const float*)d_in[10];
    const float* ln_g = (const float*)d_in[11]; const float* ln_b = (const float*)d_in[12];
    const float* W1 = (const float*)d_in[13]; const float* b1 = (const float*)d_in[14];
    const float* lg2 = (const float*)d_in[15]; const float* lb2 = (const float*)d_in[16];
    const float* W2 = (const float*)d_in[17]; const float* b2 = (const float*)d_in[18];
    const float* W3 = (const float*)d_in[19]; const float* b3 = (const float*)d_in[20];
    float* out = (float*)d_out;

    float *t2, *ln1;
    __half *Sh, *Sl, *loh, *lol, *roh, *rol, *bth, *btl;
    __half *t1h, *t1l, *l1h, *l1l, *l2h, *l2l, *mh, *ml;
    __half *WlTh,*WlTl,*WrTh,*WrTl,*WbTh,*WbTl,*WoTh,*WoTl,*W1Th,*W1Tl,*W2Th,*W2Tl,*W3Th,*W3Tl;
    cudaGetSymbolAddress((void**)&Sh,  g_Sh);  cudaGetSymbolAddress((void**)&Sl,  g_Sl);
    cudaGetSymbolAddress((void**)&loh, g_loh); cudaGetSymbolAddress((void**)&lol, g_lol);
    cudaGetSymbolAddress((void**)&roh, g_roh); cudaGetSymbolAddress((void**)&rol, g_rol);
    cudaGetSymbolAddress((void**)&bth, g_bth); cudaGetSymbolAddress((void**)&btl, g_btl);
    cudaGetSymbolAddress((void**)&t1h, g_t1h); cudaGetSymbolAddress((void**)&t1l, g_t1l);
    cudaGetSymbolAddress((void**)&t2,  g_t2);  cudaGetSymbolAddress((void**)&ln1, g_ln1);
    cudaGetSymbolAddress((void**)&l1h, g_l1h); cudaGetSymbolAddress((void**)&l1l, g_l1l);
    cudaGetSymbolAddress((void**)&l2h, g_l2h); cudaGetSymbolAddress((void**)&l2l, g_l2l);
    cudaGetSymbolAddress((void**)&mh,  g_mh);  cudaGetSymbolAddress((void**)&ml,  g_ml);
    cudaGetSymbolAddress((void**)&WlTh,g_WlTh);cudaGetSymbolAddress((void**)&WlTl,g_WlTl);
    cudaGetSymbolAddress((void**)&WrTh,g_WrTh);cudaGetSymbolAddress((void**)&WrTl,g_WrTl);
    cudaGetSymbolAddress((void**)&WbTh,g_WbTh);cudaGetSymbolAddress((void**)&WbTl,g_WbTl);
    cudaGetSymbolAddress((void**)&WoTh,g_WoTh);cudaGetSymbolAddress((void**)&WoTl,g_WoTl);
    cudaGetSymbolAddress((void**)&W1Th,g_W1Th);cudaGetSymbolAddress((void**)&W1Tl,g_W1Tl);
    cudaGetSymbolAddress((void**)&W2Th,g_W2Th);cudaGetSymbolAddress((void**)&W2Tl,g_W2Tl);
    cudaGetSymbolAddress((void**)&W3Th,g_W3Th);cudaGetSymbolAddress((void**)&W3Tl,g_W3Tl);

    cudaFuncSetAttribute(proj3,             cudaFuncAttributeMaxDynamicSharedMemorySize, SMEM_BYTES);
    cudaFuncSetAttribute(gemm_mma<0,1,0,3>, cudaFuncAttributeMaxDynamicSharedMemorySize, SMEM_BYTES);
    cudaFuncSetAttribute(gemm_mma<1,0,0,2>, cudaFuncAttributeMaxDynamicSharedMemorySize, SMEM_BYTES);
    cudaFuncSetAttribute(gemm_mma<3,0,0,2>, cudaFuncAttributeMaxDynamicSharedMemorySize, SMEM_BYTES);
    cudaFuncSetAttribute(gemm_mma<2,1,0,2>, cudaFuncAttributeMaxDynamicSharedMemorySize, SMEM_BYTES);

    const ll sTD = (ll)TT * DD;
    const ll sTT = (ll)TT * TT;
    dim3 tb(32, 8);

    P3 p0 = {left,  WlTh, WlTl, bl,  loh, lol};
    P3 p1 = {right, WrTh, WrTl, br,  roh, rol};
    P3 p2 = {body,  WbTh, WbTl, bbv, bth, btl};

    // idx 0: ALL weight prep in one launch
    wprep<<<2816, tb>>>(Wl, Wr, Wb, Wo, W1, W2, W3);
    // idx 1: merged projections
    proj3<<<dim3(4, 128, 3), NTHREADS, SMEM_BYTES>>>(p0, p1, p2);
    // idx 2: attention scores (3-term)
    gemm_mma<0,1,0,3><<<dim3(16,16,BB), NTHREADS, SMEM_BYTES>>>(roh, rol, nullptr,
        loh, lol, nullptr, nullptr, nullptr, Sh, Sl, DD, TT, sTD, sTD, sTT);
    // idx 3: softmax  <-- ncu profiles this launch
    softmax2048s<<<BT, 256>>>(Sh, Sl);
    // fuse (3-term)
    gemm_mma<0,1,0,3><<<dim3(4,16,BB), NTHREADS, SMEM_BYTES>>>(Sh, Sl, nullptr,
        bth, btl, nullptr, nullptr, nullptr, t1h, t1l, TT, DD, sTT, sTD, sTD);
    // output projection + LN (2-term)
    gemm_mma<1,0,0,2><<<dim3(4,128,1), NTHREADS, SMEM_BYTES>>>(t1h, t1l, nullptr,
        WoTh, WoTl, bo, nullptr, t2, nullptr, nullptr, DD, DD, 0, 0, 0);
    layernorm512s<<<BT, 128>>>(t2, ln1, l1h, l1l, ln_g, ln_b);
    // inverted residual (2-term)
    gemm_mma<3,0,0,2><<<dim3(4,128,1), NTHREADS, SMEM_BYTES>>>(l1h, l1l, nullptr,
        W1Th, W1Tl, b1, ln1, t2, nullptr, nullptr, DD, DD, 0, 0, 0);
    layernorm512s<<<BT, 128>>>(t2, ln1, l2h, l2l, lg2, lb2);
    gemm_mma<2,1,0,2><<<dim3(12,128,1), NTHREADS, SMEM_BYTES>>>(l2h, l2l, nullptr,
        W2Th, W2Tl, b2, nullptr, nullptr, mh, ml, DD, DMID, 0, 0, 0);
    gemm_mma<1,0,0,2><<<dim3(4,128,1), NTHREADS, SMEM_BYTES>>>(mh, ml, nullptr,
        W3Th, W3Tl, b3, nullptr, out, nullptr, nullptr, DMID, DD, 0, 0, 0);
}